// round 9
// baseline (speedup 1.0000x reference)
#include <cuda_runtime.h>
#include <cuda_bf16.h>
#include <math.h>
#include <stdint.h>

// Problem constants
#define BB   4
#define TT   2048
#define CC   1024
#define NH   16
#define DH   64
#define ROWS (BB * TT)        // 8192
#define FF   (4 * CC)         // 4096

// ---------------- scratch (no allocs allowed) ----------------
__device__ float g_h [ROWS * CC];
__device__ float g_q [ROWS * CC];
__device__ float g_k [ROWS * CC];
__device__ float g_v [ROWS * CC];
__device__ float g_y [ROWS * CC];
__device__ float g_x1[ROWS * CC];
__device__ float g_m [ROWS * FF];
// rna-rounded weight copies
__device__ float g_wqkv[CC * 3 * CC];   // [K=1024][N=3072] (Wq|Wk|Wv)
__device__ float g_bqkv[3 * CC];
__device__ float g_wo  [CC * CC];
__device__ float g_w1  [CC * FF];
__device__ float g_w2  [FF * CC];

// ---------------- common helpers ----------------
__device__ __forceinline__ float gelu_exact(float x) {
    return 0.5f * x * (1.0f + erff(x * 0.70710678118654752f));
}

__device__ __forceinline__ float cvt_tf32(float x) {
    uint32_t r;
    asm("cvt.rna.tf32.f32 %0, %1;" : "=r"(r) : "f"(x));
    return __uint_as_float(r);
}

__device__ __forceinline__ void mma_tf32(float& d0, float& d1, float& d2, float& d3,
                                         uint32_t a0, uint32_t a1, uint32_t a2, uint32_t a3,
                                         uint32_t b0, uint32_t b1) {
    asm volatile(
        "mma.sync.aligned.m16n8k8.row.col.f32.tf32.tf32.f32 "
        "{%0,%1,%2,%3}, {%4,%5,%6,%7}, {%8,%9}, {%0,%1,%2,%3};"
        : "+f"(d0), "+f"(d1), "+f"(d2), "+f"(d3)
        : "r"(a0), "r"(a1), "r"(a2), "r"(a3), "r"(b0), "r"(b1));
}

#define CP_ASYNC16(dst, src) \
    asm volatile("cp.async.cg.shared.global [%0], [%1], 16;\n" :: "r"(dst), "l"(src))
#define CP_COMMIT() asm volatile("cp.async.commit_group;\n" ::: "memory")

// ---------------- weight prep: rna-rounded copy ----------------
__global__ void round_copy(const float* __restrict__ src, float* __restrict__ dst,
                           int n) {
    int i = (blockIdx.x * blockDim.x + threadIdx.x) * 4;
    if (i < n) {
        float4 v = *(const float4*)(src + i);
        v.x = cvt_tf32(v.x); v.y = cvt_tf32(v.y);
        v.z = cvt_tf32(v.z); v.w = cvt_tf32(v.w);
        *(float4*)(dst + i) = v;
    }
}

__global__ void round_copy_cat(const float* __restrict__ src, float* __restrict__ dst,
                               int K, int coloff) {
    int k = blockIdx.y;
    int n = (blockIdx.x * blockDim.x + threadIdx.x) * 4;
    float4 v = *(const float4*)(src + (size_t)k * CC + n);
    v.x = cvt_tf32(v.x); v.y = cvt_tf32(v.y);
    v.z = cvt_tf32(v.z); v.w = cvt_tf32(v.w);
    *(float4*)(dst + (size_t)k * (3 * CC) + coloff + n) = v;
}

__global__ void cat_bias(const float* __restrict__ b0, const float* __restrict__ b1,
                         const float* __restrict__ b2, float* __restrict__ dst) {
    int i = blockIdx.x * blockDim.x + threadIdx.x;
    dst[i]          = b0[i];
    dst[i + CC]     = b1[i];
    dst[i + 2 * CC] = b2[i];
}

// ---------------- LayerNorm: one block per row (rna-rounded out) --------------
__global__ void ln_kernel(const float* __restrict__ X,
                          const float* __restrict__ gam,
                          const float* __restrict__ bet,
                          float* __restrict__ out) {
    int row = blockIdx.x;
    int tid = threadIdx.x;
    const float4* x4 = (const float4*)(X + (size_t)row * CC);
    float4 v = x4[tid];
    float s  = v.x + v.y + v.z + v.w;
    float ss = v.x*v.x + v.y*v.y + v.z*v.z + v.w*v.w;
    #pragma unroll
    for (int off = 16; off > 0; off >>= 1) {
        s  += __shfl_down_sync(0xffffffffu, s,  off);
        ss += __shfl_down_sync(0xffffffffu, ss, off);
    }
    __shared__ float smS[8], smQ[8];
    __shared__ float sh_mu, sh_rstd;
    int lane = tid & 31, w = tid >> 5;
    if (lane == 0) { smS[w] = s; smQ[w] = ss; }
    __syncthreads();
    if (tid == 0) {
        float ts = 0.f, tq = 0.f;
        #pragma unroll
        for (int i = 0; i < 8; i++) { ts += smS[i]; tq += smQ[i]; }
        float mu  = ts * (1.0f / CC);
        float var = tq * (1.0f / CC) - mu * mu;
        sh_mu = mu;
        sh_rstd = rsqrtf(var + 1e-5f);
    }
    __syncthreads();
    float mu = sh_mu, rstd = sh_rstd;
    float4 gv = ((const float4*)gam)[tid];
    float4 bv = ((const float4*)bet)[tid];
    float4 o;
    o.x = cvt_tf32((v.x - mu) * rstd * gv.x + bv.x);
    o.y = cvt_tf32((v.y - mu) * rstd * gv.y + bv.y);
    o.z = cvt_tf32((v.z - mu) * rstd * gv.z + bv.z);
    o.w = cvt_tf32((v.w - mu) * rstd * gv.w + bv.w);
    ((float4*)(out + (size_t)row * CC))[tid] = o;
}

// ---------------- TF32 HMMA GEMM: 32-k stages, 3-stage cp.async ----------------
// C = A[M,K] @ W[K,N] + bias (+res) (+gelu+round); output split for QKV fusion.
// Tile 128x128x32-per-stage, 256 threads, 8 warps (2x4), warp tile 64x32.
#define AST 36     // A row stride (128 rows x 32 k, pad 4): frag bank = 4m+t, conflict-free
#define WST 132    // W row stride (32 rows x 128 n)
#define GST 3
#define STG_FLOATS (128 * AST + 32 * WST)   // 4608 + 4224 = 8832
#define GEMM_SMEM  (GST * STG_FLOATS * 4)   // 105984 bytes

template <int EPI>
__global__ __launch_bounds__(256, 2)
void gemm_tc(const float* __restrict__ A, const float* __restrict__ W,
             const float* __restrict__ bias, const float* __restrict__ res,
             float* __restrict__ C0, float* __restrict__ C1, float* __restrict__ C2,
             int M, int N, int K, int outN) {
    extern __shared__ __align__(16) float dsm[];

    int tid  = threadIdx.x;
    int lane = tid & 31;
    int wid  = tid >> 5;
    int warp_m = wid >> 2;
    int warp_n = wid & 3;
    int g = lane >> 2, t = lane & 3;
    int bm = blockIdx.y * 128;
    int bn = blockIdx.x * 128;

    int bi = bn / outN;
    float* C = (bi == 0) ? C0 : ((bi == 1) ? C1 : C2);
    int cn = bn - bi * outN;

    // A staging: thread -> row am (0..127), 64B chunk at col ac (0 or 16)
    int am = tid >> 1;
    int ac = (tid & 1) * 16;
    // W staging: thread -> row wk (0..31), 64B chunk at col wn (0..112 step 16)
    int wk = tid >> 3;
    int wn = (tid & 7) * 16;

    const float* Apb = A + (size_t)(bm + am) * K + ac;
    const float* Wpb = W + (size_t)wk * N + bn + wn;

    uint32_t sA[GST], sW[GST];
    #pragma unroll
    for (int s = 0; s < GST; s++) {
        float* base = dsm + s * STG_FLOATS;
        sA[s] = (uint32_t)__cvta_generic_to_shared(base + am * AST + ac);
        sW[s] = (uint32_t)__cvta_generic_to_shared(base + 128 * AST + wk * WST + wn);
    }

    float acc[4][4][4];
    #pragma unroll
    for (int i = 0; i < 4; i++)
        #pragma unroll
        for (int j = 0; j < 4; j++)
            #pragma unroll
            for (int r = 0; r < 4; r++) acc[i][j][r] = 0.f;

    int NT = K >> 5;   // K/32

    // prologue: stages 0, 1
    #pragma unroll
    for (int s = 0; s < GST - 1; s++) {
        int k0 = s << 5;
        #pragma unroll
        for (int j = 0; j < 4; j++) {
            CP_ASYNC16(sA[s] + j * 16, Apb + k0 + j * 4);
            CP_ASYNC16(sW[s] + j * 16, Wpb + (size_t)k0 * N + j * 4);
        }
        CP_COMMIT();
    }

    for (int kt = 0; kt < NT; kt++) {
        int st = kt % GST;
        asm volatile("cp.async.wait_group 1;" ::: "memory");
        __syncthreads();

        if (kt + GST - 1 < NT) {
            int ns = (kt + GST - 1) % GST;
            int k0 = (kt + GST - 1) << 5;
            #pragma unroll
            for (int j = 0; j < 4; j++) {
                CP_ASYNC16(sA[ns] + j * 16, Apb + k0 + j * 4);
                CP_ASYNC16(sW[ns] + j * 16, Wpb + (size_t)k0 * N + j * 4);
            }
        }
        CP_COMMIT();

        float* base = dsm + st * STG_FLOATS;
        float (*As)[AST] = (float(*)[AST])base;
        float (*Ws)[WST] = (float(*)[WST])(base + 128 * AST);

        #pragma unroll
        for (int kc = 0; kc < 4; kc++) {
            int kr = kc * 8 + t;
            uint32_t af[4][4];
            uint32_t bf[4][2];
            #pragma unroll
            for (int mtl = 0; mtl < 4; mtl++) {
                int m = warp_m * 64 + mtl * 16 + g;
                af[mtl][0] = __float_as_uint(As[m    ][kr    ]);
                af[mtl][1] = __float_as_uint(As[m + 8][kr    ]);
                af[mtl][2] = __float_as_uint(As[m    ][kr + 4]);
                af[mtl][3] = __float_as_uint(As[m + 8][kr + 4]);
            }
            #pragma unroll
            for (int ntl = 0; ntl < 4; ntl++) {
                int n = warp_n * 32 + ntl * 8 + g;
                bf[ntl][0] = __float_as_uint(Ws[kr    ][n]);
                bf[ntl][1] = __float_as_uint(Ws[kr + 4][n]);
            }
            #pragma unroll
            for (int mtl = 0; mtl < 4; mtl++)
                #pragma unroll
                for (int ntl = 0; ntl < 4; ntl++)
                    mma_tf32(acc[mtl][ntl][0], acc[mtl][ntl][1],
                             acc[mtl][ntl][2], acc[mtl][ntl][3],
                             af[mtl][0], af[mtl][1], af[mtl][2], af[mtl][3],
                             bf[ntl][0], bf[ntl][1]);
        }
    }

    // ---- epilogue ----
    #pragma unroll
    for (int mt = 0; mt < 4; mt++) {
        int r0 = bm + warp_m * 64 + mt * 16 + g;
        #pragma unroll
        for (int nt = 0; nt < 4; nt++) {
            int gcol = bn + warp_n * 32 + nt * 8 + t * 2;
            int col  = cn + warp_n * 32 + nt * 8 + t * 2;
            float b0 = bias[gcol], b1 = bias[gcol + 1];
            #pragma unroll
            for (int h = 0; h < 2; h++) {
                int row = r0 + h * 8;
                float v0 = acc[mt][nt][h * 2 + 0] + b0;
                float v1 = acc[mt][nt][h * 2 + 1] + b1;
                if (EPI == 1) {
                    const float* rp = res + (size_t)row * outN + col;
                    v0 += rp[0]; v1 += rp[1];
                }
                if (EPI == 2) {
                    v0 = cvt_tf32(gelu_exact(v0));
                    v1 = cvt_tf32(gelu_exact(v1));
                }
                *(float2*)(C + (size_t)row * outN + col) = make_float2(v0, v1);
            }
        }
    }
}

// ---------------- Tensor-core flash attention (causal, tf32) ----------------
#define KS_STR 68
#define VS_STR 72

__global__ __launch_bounds__(128)
void attn_tc_kernel(const float* __restrict__ Q,
                    const float* __restrict__ K,
                    const float* __restrict__ V,
                    float* __restrict__ Y) {
    __shared__ float KPs[64][KS_STR];
    __shared__ float Vs [64][VS_STR];

    int qt = blockIdx.x, h = blockIdx.y, b = blockIdx.z;
    int tid = threadIdx.x;
    int lane = tid & 31, w = tid >> 5;
    int g = lane >> 2, t = lane & 3;
    int qbase = qt * 64;
    const int hoff = h * DH;

    int lrow = tid >> 1;
    int ld0  = (tid & 1) * 32;

    {
        const float* qp = Q + (size_t)(b * TT + qbase + lrow) * CC + hoff + ld0;
        #pragma unroll
        for (int i = 0; i < 8; i++) {
            float4 v4 = ((const float4*)qp)[i];
            KPs[lrow][ld0 + 4*i + 0] = cvt_tf32(v4.x * 0.125f);
            KPs[lrow][ld0 + 4*i + 1] = cvt_tf32(v4.y * 0.125f);
            KPs[lrow][ld0 + 4*i + 2] = cvt_tf32(v4.z * 0.125f);
            KPs[lrow][ld0 + 4*i + 3] = cvt_tf32(v4.w * 0.125f);
        }
    }
    __syncthreads();
    uint32_t qf[8][4];
    {
        int rA = 16 * w + g;
        #pragma unroll
        for (int kc = 0; kc < 8; kc++) {
            qf[kc][0] = __float_as_uint(KPs[rA    ][kc*8 + t    ]);
            qf[kc][1] = __float_as_uint(KPs[rA + 8][kc*8 + t    ]);
            qf[kc][2] = __float_as_uint(KPs[rA    ][kc*8 + t + 4]);
            qf[kc][3] = __float_as_uint(KPs[rA + 8][kc*8 + t + 4]);
        }
    }
    __syncthreads();

    float o[8][4];
    #pragma unroll
    for (int nt = 0; nt < 8; nt++)
        #pragma unroll
        for (int j = 0; j < 4; j++) o[nt][j] = 0.f;
    float mA = -1e30f, mB = -1e30f, lA = 0.f, lB = 0.f;

    float4 kr[8], vr[8];
    {
        const float4* kp = (const float4*)(K + (size_t)(b * TT + lrow) * CC + hoff + ld0);
        const float4* vp = (const float4*)(V + (size_t)(b * TT + lrow) * CC + hoff + ld0);
        #pragma unroll
        for (int i = 0; i < 8; i++) { kr[i] = kp[i]; vr[i] = vp[i]; }
    }

    for (int kt = 0; kt <= qt; kt++) {
        #pragma unroll
        for (int i = 0; i < 8; i++) {
            float4 kv = kr[i];
            KPs[lrow][ld0 + 4*i + 0] = cvt_tf32(kv.x);
            KPs[lrow][ld0 + 4*i + 1] = cvt_tf32(kv.y);
            KPs[lrow][ld0 + 4*i + 2] = cvt_tf32(kv.z);
            KPs[lrow][ld0 + 4*i + 3] = cvt_tf32(kv.w);
            float4 vv = vr[i];
            Vs[lrow][ld0 + 4*i + 0] = cvt_tf32(vv.x);
            Vs[lrow][ld0 + 4*i + 1] = cvt_tf32(vv.y);
            Vs[lrow][ld0 + 4*i + 2] = cvt_tf32(vv.z);
            Vs[lrow][ld0 + 4*i + 3] = cvt_tf32(vv.w);
        }
        __syncthreads();

        if (kt < qt) {
            const float4* kp = (const float4*)(K + (size_t)(b * TT + (kt+1) * 64 + lrow) * CC + hoff + ld0);
            const float4* vp = (const float4*)(V + (size_t)(b * TT + (kt+1) * 64 + lrow) * CC + hoff + ld0);
            #pragma unroll
            for (int i = 0; i < 8; i++) { kr[i] = kp[i]; vr[i] = vp[i]; }
        }

        float s[8][4];
        #pragma unroll
        for (int nt = 0; nt < 8; nt++)
            #pragma unroll
            for (int j = 0; j < 4; j++) s[nt][j] = 0.f;
        #pragma unroll
        for (int kc = 0; kc < 8; kc++) {
            #pragma unroll
            for (int nt = 0; nt < 8; nt++) {
                uint32_t b0 = __float_as_uint(KPs[nt*8 + g][kc*8 + t    ]);
                uint32_t b1 = __float_as_uint(KPs[nt*8 + g][kc*8 + t + 4]);
                mma_tf32(s[nt][0], s[nt][1], s[nt][2], s[nt][3],
                         qf[kc][0], qf[kc][1], qf[kc][2], qf[kc][3], b0, b1);
            }
        }

        int rA = 16 * w + g;
        int rB = rA + 8;

        if (kt == qt) {
            #pragma unroll
            for (int nt = 0; nt < 8; nt++) {
                int c0 = nt * 8 + 2 * t;
                if (c0     > rA) s[nt][0] = -1e30f;
                if (c0 + 1 > rA) s[nt][1] = -1e30f;
                if (c0     > rB) s[nt][2] = -1e30f;
                if (c0 + 1 > rB) s[nt][3] = -1e30f;
            }
        }

        float mxA = -1e30f, mxB = -1e30f;
        #pragma unroll
        for (int nt = 0; nt < 8; nt++) {
            mxA = fmaxf(mxA, fmaxf(s[nt][0], s[nt][1]));
            mxB = fmaxf(mxB, fmaxf(s[nt][2], s[nt][3]));
        }
        mxA = fmaxf(mxA, __shfl_xor_sync(0xffffffffu, mxA, 1));
        mxA = fmaxf(mxA, __shfl_xor_sync(0xffffffffu, mxA, 2));
        mxB = fmaxf(mxB, __shfl_xor_sync(0xffffffffu, mxB, 1));
        mxB = fmaxf(mxB, __shfl_xor_sync(0xffffffffu, mxB, 2));
        float mnA = fmaxf(mA, mxA);
        float mnB = fmaxf(mB, mxB);
        float corrA = __expf(mA - mnA);
        float corrB = __expf(mB - mnB);

        float sumA = 0.f, sumB = 0.f;
        #pragma unroll
        for (int nt = 0; nt < 8; nt++) {
            s[nt][0] = __expf(s[nt][0] - mnA); sumA += s[nt][0];
            s[nt][1] = __expf(s[nt][1] - mnA); sumA += s[nt][1];
            s[nt][2] = __expf(s[nt][2] - mnB); sumB += s[nt][2];
            s[nt][3] = __expf(s[nt][3] - mnB); sumB += s[nt][3];
        }
        sumA += __shfl_xor_sync(0xffffffffu, sumA, 1);
        sumA += __shfl_xor_sync(0xffffffffu, sumA, 2);
        sumB += __shfl_xor_sync(0xffffffffu, sumB, 1);
        sumB += __shfl_xor_sync(0xffffffffu, sumB, 2);
        lA = lA * corrA + sumA;
        lB = lB * corrB + sumB;
        mA = mnA; mB = mnB;

        #pragma unroll
        for (int nt = 0; nt < 8; nt++) {
            o[nt][0] *= corrA; o[nt][1] *= corrA;
            o[nt][2] *= corrB; o[nt][3] *= corrB;
        }

        __syncthreads();
        #pragma unroll
        for (int nt = 0; nt < 8; nt++) {
            int c0 = nt * 8 + 2 * t;
            KPs[rA][c0    ] = cvt_tf32(s[nt][0]);
            KPs[rA][c0 + 1] = cvt_tf32(s[nt][1]);
            KPs[rB][c0    ] = cvt_tf32(s[nt][2]);
            KPs[rB][c0 + 1] = cvt_tf32(s[nt][3]);
        }
        __syncwarp();

        #pragma unroll
        for (int kc = 0; kc < 8; kc++) {
            uint32_t a0 = __float_as_uint(KPs[rA][kc*8 + t    ]);
            uint32_t a1 = __float_as_uint(KPs[rB][kc*8 + t    ]);
            uint32_t a2 = __float_as_uint(KPs[rA][kc*8 + t + 4]);
            uint32_t a3 = __float_as_uint(KPs[rB][kc*8 + t + 4]);
            #pragma unroll
            for (int nt = 0; nt < 8; nt++) {
                uint32_t b0 = __float_as_uint(Vs[kc*8 + t    ][nt*8 + g]);
                uint32_t b1 = __float_as_uint(Vs[kc*8 + t + 4][nt*8 + g]);
                mma_tf32(o[nt][0], o[nt][1], o[nt][2], o[nt][3],
                         a0, a1, a2, a3, b0, b1);
            }
        }
        __syncthreads();
    }

    float invA = 1.0f / lA, invB = 1.0f / lB;
    int rowA = qbase + 16 * w + g;
    float* yA = Y + (size_t)(b * TT + rowA) * CC + hoff;
    float* yB = Y + (size_t)(b * TT + rowA + 8) * CC + hoff;
    #pragma unroll
    for (int nt = 0; nt < 8; nt++) {
        int c0 = nt * 8 + 2 * t;
        *(float2*)(yA + c0) = make_float2(cvt_tf32(o[nt][0] * invA), cvt_tf32(o[nt][1] * invA));
        *(float2*)(yB + c0) = make_float2(cvt_tf32(o[nt][2] * invB), cvt_tf32(o[nt][3] * invB));
    }
}

// ---------------- launcher ----------------
extern "C" void kernel_launch(void* const* d_in, const int* in_sizes, int n_in,
                              void* d_out, int out_size) {
    const float* x     = (const float*)d_in[0];
    const float* ln1_g = (const float*)d_in[1];
    const float* ln1_b = (const float*)d_in[2];
    const float* Wq    = (const float*)d_in[3];
    const float* bq    = (const float*)d_in[4];
    const float* Wk    = (const float*)d_in[5];
    const float* bk    = (const float*)d_in[6];
    const float* Wv    = (const float*)d_in[7];
    const float* bv    = (const float*)d_in[8];
    const float* Wo    = (const float*)d_in[9];
    const float* bo    = (const float*)d_in[10];
    const float* ln2_g = (const float*)d_in[11];
    const float* ln2_b = (const float*)d_in[12];
    const float* W1    = (const float*)d_in[13];
    const float* b1    = (const float*)d_in[14];
    const float* W2    = (const float*)d_in[15];
    const float* b2    = (const float*)d_in[16];
    float* out = (float*)d_out;

    float *h, *q, *k, *v, *y, *x1, *m;
    float *wqkv, *bqkv, *wo, *w1, *w2;
    cudaGetSymbolAddress((void**)&h,    g_h);
    cudaGetSymbolAddress((void**)&q,    g_q);
    cudaGetSymbolAddress((void**)&k,    g_k);
    cudaGetSymbolAddress((void**)&v,    g_v);
    cudaGetSymbolAddress((void**)&y,    g_y);
    cudaGetSymbolAddress((void**)&x1,   g_x1);
    cudaGetSymbolAddress((void**)&m,    g_m);
    cudaGetSymbolAddress((void**)&wqkv, g_wqkv);
    cudaGetSymbolAddress((void**)&bqkv, g_bqkv);
    cudaGetSymbolAddress((void**)&wo,   g_wo);
    cudaGetSymbolAddress((void**)&w1,   g_w1);
    cudaGetSymbolAddress((void**)&w2,   g_w2);

    cudaFuncSetAttribute(gemm_tc<0>, cudaFuncAttributeMaxDynamicSharedMemorySize, GEMM_SMEM);
    cudaFuncSetAttribute(gemm_tc<1>, cudaFuncAttributeMaxDynamicSharedMemorySize, GEMM_SMEM);
    cudaFuncSetAttribute(gemm_tc<2>, cudaFuncAttributeMaxDynamicSharedMemorySize, GEMM_SMEM);

    // 0) weight prep (rna rounding; QKV concat)
    round_copy_cat<<<dim3(CC/(256*4), CC), 256>>>(Wq, wqkv, CC, 0);
    round_copy_cat<<<dim3(CC/(256*4), CC), 256>>>(Wk, wqkv, CC, CC);
    round_copy_cat<<<dim3(CC/(256*4), CC), 256>>>(Wv, wqkv, CC, 2*CC);
    cat_bias<<<CC/256, 256>>>(bq, bk, bv, bqkv);
    round_copy<<<(CC*CC)/(256*4), 256>>>(Wo, wo, CC*CC);
    round_copy<<<(CC*FF)/(256*4), 256>>>(W1, w1, CC*FF);
    round_copy<<<(FF*CC)/(256*4), 256>>>(W2, w2, FF*CC);

    dim3 gQKV(3*CC / 128, ROWS / 128);
    dim3 gC(CC / 128, ROWS / 128);
    dim3 gF(FF / 128, ROWS / 128);

    ln_kernel<<<ROWS, 256>>>(x, ln1_g, ln1_b, h);
    gemm_tc<0><<<gQKV, 256, GEMM_SMEM>>>(h, wqkv, bqkv, nullptr, q, k, v,
                                         ROWS, 3*CC, CC, CC);
    attn_tc_kernel<<<dim3(TT / 64, NH, BB), 128>>>(q, k, v, y);
    gemm_tc<1><<<gC, 256, GEMM_SMEM>>>(y, wo, bo, x, x1, x1, x1,
                                       ROWS, CC, CC, CC);
    ln_kernel<<<ROWS, 256>>>(x1, ln2_g, ln2_b, h);
    gemm_tc<2><<<gF, 256, GEMM_SMEM>>>(h, w1, b1, nullptr, m, m, m,
                                       ROWS, FF, CC, FF);
    gemm_tc<1><<<gC, 256, GEMM_SMEM>>>(m, w2, b2, x1, out, out, out,
                                       ROWS, CC, FF, CC);
}

// round 10
// speedup vs baseline: 1.2537x; 1.2537x over previous
#include <cuda_runtime.h>
#include <cuda_bf16.h>
#include <math.h>
#include <stdint.h>

// Problem constants
#define BB   4
#define TT   2048
#define CC   1024
#define NH   16
#define DH   64
#define ROWS (BB * TT)        // 8192
#define FF   (4 * CC)         // 4096

// ---------------- scratch (no allocs allowed) ----------------
__device__ float g_h [ROWS * CC];
__device__ float g_q [ROWS * CC];
__device__ float g_k [ROWS * CC];
__device__ float g_v [ROWS * CC];
__device__ float g_y [ROWS * CC];
__device__ float g_x1[ROWS * CC];
__device__ float g_m [ROWS * FF];
// rna-rounded weight copies
__device__ float g_wqkv[CC * 3 * CC];   // [K=1024][N=3072] (Wq|Wk|Wv)
__device__ float g_bqkv[3 * CC];
__device__ float g_wo  [CC * CC];
__device__ float g_w1  [CC * FF];
__device__ float g_w2  [FF * CC];

// ---------------- common helpers ----------------
__device__ __forceinline__ float gelu_exact(float x) {
    return 0.5f * x * (1.0f + erff(x * 0.70710678118654752f));
}

__device__ __forceinline__ float cvt_tf32(float x) {
    uint32_t r;
    asm("cvt.rna.tf32.f32 %0, %1;" : "=r"(r) : "f"(x));
    return __uint_as_float(r);
}

__device__ __forceinline__ void mma_tf32(float& d0, float& d1, float& d2, float& d3,
                                         uint32_t a0, uint32_t a1, uint32_t a2, uint32_t a3,
                                         uint32_t b0, uint32_t b1) {
    asm volatile(
        "mma.sync.aligned.m16n8k8.row.col.f32.tf32.tf32.f32 "
        "{%0,%1,%2,%3}, {%4,%5,%6,%7}, {%8,%9}, {%0,%1,%2,%3};"
        : "+f"(d0), "+f"(d1), "+f"(d2), "+f"(d3)
        : "r"(a0), "r"(a1), "r"(a2), "r"(a3), "r"(b0), "r"(b1));
}

#define CP_ASYNC16(dst, src) \
    asm volatile("cp.async.cg.shared.global [%0], [%1], 16;\n" :: "r"(dst), "l"(src))
#define CP_COMMIT() asm volatile("cp.async.commit_group;\n" ::: "memory")

// ---------------- weight prep: rna-rounded copy ----------------
__global__ void round_copy(const float* __restrict__ src, float* __restrict__ dst,
                           int n) {
    int i = (blockIdx.x * blockDim.x + threadIdx.x) * 4;
    if (i < n) {
        float4 v = *(const float4*)(src + i);
        v.x = cvt_tf32(v.x); v.y = cvt_tf32(v.y);
        v.z = cvt_tf32(v.z); v.w = cvt_tf32(v.w);
        *(float4*)(dst + i) = v;
    }
}

__global__ void round_copy_cat(const float* __restrict__ src, float* __restrict__ dst,
                               int K, int coloff) {
    int k = blockIdx.y;
    int n = (blockIdx.x * blockDim.x + threadIdx.x) * 4;
    float4 v = *(const float4*)(src + (size_t)k * CC + n);
    v.x = cvt_tf32(v.x); v.y = cvt_tf32(v.y);
    v.z = cvt_tf32(v.z); v.w = cvt_tf32(v.w);
    *(float4*)(dst + (size_t)k * (3 * CC) + coloff + n) = v;
}

__global__ void cat_bias(const float* __restrict__ b0, const float* __restrict__ b1,
                         const float* __restrict__ b2, float* __restrict__ dst) {
    int i = blockIdx.x * blockDim.x + threadIdx.x;
    dst[i]          = b0[i];
    dst[i + CC]     = b1[i];
    dst[i + 2 * CC] = b2[i];
}

// ---------------- LayerNorm: one block per row (rna-rounded out) --------------
__global__ void ln_kernel(const float* __restrict__ X,
                          const float* __restrict__ gam,
                          const float* __restrict__ bet,
                          float* __restrict__ out) {
    int row = blockIdx.x;
    int tid = threadIdx.x;
    const float4* x4 = (const float4*)(X + (size_t)row * CC);
    float4 v = x4[tid];
    float s  = v.x + v.y + v.z + v.w;
    float ss = v.x*v.x + v.y*v.y + v.z*v.z + v.w*v.w;
    #pragma unroll
    for (int off = 16; off > 0; off >>= 1) {
        s  += __shfl_down_sync(0xffffffffu, s,  off);
        ss += __shfl_down_sync(0xffffffffu, ss, off);
    }
    __shared__ float smS[8], smQ[8];
    __shared__ float sh_mu, sh_rstd;
    int lane = tid & 31, w = tid >> 5;
    if (lane == 0) { smS[w] = s; smQ[w] = ss; }
    __syncthreads();
    if (tid == 0) {
        float ts = 0.f, tq = 0.f;
        #pragma unroll
        for (int i = 0; i < 8; i++) { ts += smS[i]; tq += smQ[i]; }
        float mu  = ts * (1.0f / CC);
        float var = tq * (1.0f / CC) - mu * mu;
        sh_mu = mu;
        sh_rstd = rsqrtf(var + 1e-5f);
    }
    __syncthreads();
    float mu = sh_mu, rstd = sh_rstd;
    float4 gv = ((const float4*)gam)[tid];
    float4 bv = ((const float4*)bet)[tid];
    float4 o;
    o.x = cvt_tf32((v.x - mu) * rstd * gv.x + bv.x);
    o.y = cvt_tf32((v.y - mu) * rstd * gv.y + bv.y);
    o.z = cvt_tf32((v.z - mu) * rstd * gv.z + bv.z);
    o.w = cvt_tf32((v.w - mu) * rstd * gv.w + bv.w);
    ((float4*)(out + (size_t)row * CC))[tid] = o;
}

// ---------------- TF32 HMMA GEMM: 16-k stages, 5-stage ring, 2 stages/barrier --
// C = A[M,K] @ W[K,N] + bias (+res) (+gelu+round); output split for QKV fusion.
#define AST 20
#define WST 132
#define GST 5
#define STG_FLOATS (128 * AST + 16 * WST)   // 4672 floats = 18688 B
#define STG_BYTES  (STG_FLOATS * 4)
#define GEMM_SMEM  (GST * STG_BYTES)        // 93440 B

template <int EPI>
__global__ __launch_bounds__(256, 2)
void gemm_tc(const float* __restrict__ A, const float* __restrict__ W,
             const float* __restrict__ bias, const float* __restrict__ res,
             float* __restrict__ C0, float* __restrict__ C1, float* __restrict__ C2,
             int M, int N, int K, int outN) {
    extern __shared__ __align__(16) float dsm[];

    int tid  = threadIdx.x;
    int lane = tid & 31;
    int wid  = tid >> 5;
    int warp_m = wid >> 2;
    int warp_n = wid & 3;
    int g = lane >> 2, t = lane & 3;
    int bm = blockIdx.y * 128;
    int bn = blockIdx.x * 128;

    int bi = bn / outN;
    float* C = (bi == 0) ? C0 : ((bi == 1) ? C1 : C2);
    int cn = bn - bi * outN;

    // staging map (identical to R8)
    int am  = tid >> 2;             // 0..63: rows am, am+64
    int akq = (tid & 3) * 4;        // 0,4,8,12
    int wk  = tid >> 5;             // 0..7: rows wk, wk+8
    int wn4 = (tid & 31) * 4;

    const float* Apb = A + (size_t)(bm + am) * K + akq;
    const float* Wpb = W + (size_t)wk * N + bn + wn4;

    // base smem addresses for stage 0 (stage s = base + s*STG_BYTES)
    uint32_t bA0 = (uint32_t)__cvta_generic_to_shared(dsm + am * AST + akq);
    uint32_t bA1 = (uint32_t)__cvta_generic_to_shared(dsm + (am + 64) * AST + akq);
    uint32_t bW0 = (uint32_t)__cvta_generic_to_shared(dsm + 128 * AST + wk * WST + wn4);
    uint32_t bW1 = (uint32_t)__cvta_generic_to_shared(dsm + 128 * AST + (wk + 8) * WST + wn4);

    float acc[4][4][4];
    #pragma unroll
    for (int i = 0; i < 4; i++)
        #pragma unroll
        for (int j = 0; j < 4; j++)
            #pragma unroll
            for (int r = 0; r < 4; r++) acc[i][j][r] = 0.f;

    int NT = K >> 4;   // K/16 (even)

    // prologue: issue stages 0,1,2 (3 commit groups)
    #pragma unroll
    for (int s = 0; s < 3; s++) {
        uint32_t so = (uint32_t)s * STG_BYTES;
        int k0 = s << 4;
        CP_ASYNC16(bA0 + so, Apb + k0);
        CP_ASYNC16(bA1 + so, Apb + (size_t)64 * K + k0);
        CP_ASYNC16(bW0 + so, Wpb + (size_t)k0 * N);
        CP_ASYNC16(bW1 + so, Wpb + (size_t)(k0 + 8) * N);
        CP_COMMIT();
    }

    for (int kt = 0; kt < NT; kt += 2) {
        asm volatile("cp.async.wait_group 1;" ::: "memory");
        __syncthreads();

        // issue stages kt+3 and kt+4 (buffers (kt+3)%5 and (kt-1)%5 — both dead)
        #pragma unroll
        for (int d = 3; d <= 4; d++) {
            int ks = kt + d;
            if (ks < NT) {
                uint32_t so = (uint32_t)(ks % GST) * STG_BYTES;
                int k0 = ks << 4;
                CP_ASYNC16(bA0 + so, Apb + k0);
                CP_ASYNC16(bA1 + so, Apb + (size_t)64 * K + k0);
                CP_ASYNC16(bW0 + so, Wpb + (size_t)k0 * N);
                CP_ASYNC16(bW1 + so, Wpb + (size_t)(k0 + 8) * N);
            }
            CP_COMMIT();
        }

        // compute stages kt and kt+1 back-to-back (one barrier covers both)
        #pragma unroll
        for (int d = 0; d < 2; d++) {
            int st = (kt + d) % GST;
            float* base = dsm + st * STG_FLOATS;
            float (*As)[AST] = (float(*)[AST])base;
            float (*Ws)[WST] = (float(*)[WST])(base + 128 * AST);

            #pragma unroll
            for (int kc = 0; kc < 2; kc++) {
                int kr = kc * 8 + t;
                uint32_t af[4][4];
                uint32_t bf[4][2];
                #pragma unroll
                for (int mtl = 0; mtl < 4; mtl++) {
                    int m = warp_m * 64 + mtl * 16 + g;
                    af[mtl][0] = __float_as_uint(As[m    ][kr    ]);
                    af[mtl][1] = __float_as_uint(As[m + 8][kr    ]);
                    af[mtl][2] = __float_as_uint(As[m    ][kr + 4]);
                    af[mtl][3] = __float_as_uint(As[m + 8][kr + 4]);
                }
                #pragma unroll
                for (int ntl = 0; ntl < 4; ntl++) {
                    int n = warp_n * 32 + ntl * 8 + g;
                    bf[ntl][0] = __float_as_uint(Ws[kr    ][n]);
                    bf[ntl][1] = __float_as_uint(Ws[kr + 4][n]);
                }
                #pragma unroll
                for (int mtl = 0; mtl < 4; mtl++)
                    #pragma unroll
                    for (int ntl = 0; ntl < 4; ntl++)
                        mma_tf32(acc[mtl][ntl][0], acc[mtl][ntl][1],
                                 acc[mtl][ntl][2], acc[mtl][ntl][3],
                                 af[mtl][0], af[mtl][1], af[mtl][2], af[mtl][3],
                                 bf[ntl][0], bf[ntl][1]);
            }
        }
    }

    // ---- epilogue ----
    #pragma unroll
    for (int mt = 0; mt < 4; mt++) {
        int r0 = bm + warp_m * 64 + mt * 16 + g;
        #pragma unroll
        for (int nt = 0; nt < 4; nt++) {
            int gcol = bn + warp_n * 32 + nt * 8 + t * 2;
            int col  = cn + warp_n * 32 + nt * 8 + t * 2;
            float b0 = bias[gcol], b1 = bias[gcol + 1];
            #pragma unroll
            for (int h = 0; h < 2; h++) {
                int row = r0 + h * 8;
                float v0 = acc[mt][nt][h * 2 + 0] + b0;
                float v1 = acc[mt][nt][h * 2 + 1] + b1;
                if (EPI == 1) {
                    const float* rp = res + (size_t)row * outN + col;
                    v0 += rp[0]; v1 += rp[1];
                }
                if (EPI == 2) {
                    v0 = cvt_tf32(gelu_exact(v0));
                    v1 = cvt_tf32(gelu_exact(v1));
                }
                *(float2*)(C + (size_t)row * outN + col) = make_float2(v0, v1);
            }
        }
    }
}

// ---------------- Tensor-core flash attention (causal, tf32) ----------------
#define KS_STR 68
#define VS_STR 72

__global__ __launch_bounds__(128)
void attn_tc_kernel(const float* __restrict__ Q,
                    const float* __restrict__ K,
                    const float* __restrict__ V,
                    float* __restrict__ Y) {
    __shared__ float KPs[64][KS_STR];
    __shared__ float Vs [64][VS_STR];

    int qt = blockIdx.x, h = blockIdx.y, b = blockIdx.z;
    int tid = threadIdx.x;
    int lane = tid & 31, w = tid >> 5;
    int g = lane >> 2, t = lane & 3;
    int qbase = qt * 64;
    const int hoff = h * DH;

    int lrow = tid >> 1;
    int ld0  = (tid & 1) * 32;

    {
        const float* qp = Q + (size_t)(b * TT + qbase + lrow) * CC + hoff + ld0;
        #pragma unroll
        for (int i = 0; i < 8; i++) {
            float4 v4 = ((const float4*)qp)[i];
            KPs[lrow][ld0 + 4*i + 0] = cvt_tf32(v4.x * 0.125f);
            KPs[lrow][ld0 + 4*i + 1] = cvt_tf32(v4.y * 0.125f);
            KPs[lrow][ld0 + 4*i + 2] = cvt_tf32(v4.z * 0.125f);
            KPs[lrow][ld0 + 4*i + 3] = cvt_tf32(v4.w * 0.125f);
        }
    }
    __syncthreads();
    uint32_t qf[8][4];
    {
        int rA = 16 * w + g;
        #pragma unroll
        for (int kc = 0; kc < 8; kc++) {
            qf[kc][0] = __float_as_uint(KPs[rA    ][kc*8 + t    ]);
            qf[kc][1] = __float_as_uint(KPs[rA + 8][kc*8 + t    ]);
            qf[kc][2] = __float_as_uint(KPs[rA    ][kc*8 + t + 4]);
            qf[kc][3] = __float_as_uint(KPs[rA + 8][kc*8 + t + 4]);
        }
    }
    __syncthreads();

    float o[8][4];
    #pragma unroll
    for (int nt = 0; nt < 8; nt++)
        #pragma unroll
        for (int j = 0; j < 4; j++) o[nt][j] = 0.f;
    float mA = -1e30f, mB = -1e30f, lA = 0.f, lB = 0.f;

    float4 kr[8], vr[8];
    {
        const float4* kp = (const float4*)(K + (size_t)(b * TT + lrow) * CC + hoff + ld0);
        const float4* vp = (const float4*)(V + (size_t)(b * TT + lrow) * CC + hoff + ld0);
        #pragma unroll
        for (int i = 0; i < 8; i++) { kr[i] = kp[i]; vr[i] = vp[i]; }
    }

    for (int kt = 0; kt <= qt; kt++) {
        #pragma unroll
        for (int i = 0; i < 8; i++) {
            float4 kv = kr[i];
            KPs[lrow][ld0 + 4*i + 0] = cvt_tf32(kv.x);
            KPs[lrow][ld0 + 4*i + 1] = cvt_tf32(kv.y);
            KPs[lrow][ld0 + 4*i + 2] = cvt_tf32(kv.z);
            KPs[lrow][ld0 + 4*i + 3] = cvt_tf32(kv.w);
            float4 vv = vr[i];
            Vs[lrow][ld0 + 4*i + 0] = cvt_tf32(vv.x);
            Vs[lrow][ld0 + 4*i + 1] = cvt_tf32(vv.y);
            Vs[lrow][ld0 + 4*i + 2] = cvt_tf32(vv.z);
            Vs[lrow][ld0 + 4*i + 3] = cvt_tf32(vv.w);
        }
        __syncthreads();

        if (kt < qt) {
            const float4* kp = (const float4*)(K + (size_t)(b * TT + (kt+1) * 64 + lrow) * CC + hoff + ld0);
            const float4* vp = (const float4*)(V + (size_t)(b * TT + (kt+1) * 64 + lrow) * CC + hoff + ld0);
            #pragma unroll
            for (int i = 0; i < 8; i++) { kr[i] = kp[i]; vr[i] = vp[i]; }
        }

        float s[8][4];
        #pragma unroll
        for (int nt = 0; nt < 8; nt++)
            #pragma unroll
            for (int j = 0; j < 4; j++) s[nt][j] = 0.f;
        #pragma unroll
        for (int kc = 0; kc < 8; kc++) {
            #pragma unroll
            for (int nt = 0; nt < 8; nt++) {
                uint32_t b0 = __float_as_uint(KPs[nt*8 + g][kc*8 + t    ]);
                uint32_t b1 = __float_as_uint(KPs[nt*8 + g][kc*8 + t + 4]);
                mma_tf32(s[nt][0], s[nt][1], s[nt][2], s[nt][3],
                         qf[kc][0], qf[kc][1], qf[kc][2], qf[kc][3], b0, b1);
            }
        }

        int rA = 16 * w + g;
        int rB = rA + 8;

        if (kt == qt) {
            #pragma unroll
            for (int nt = 0; nt < 8; nt++) {
                int c0 = nt * 8 + 2 * t;
                if (c0     > rA) s[nt][0] = -1e30f;
                if (c0 + 1 > rA) s[nt][1] = -1e30f;
                if (c0     > rB) s[nt][2] = -1e30f;
                if (c0 + 1 > rB) s[nt][3] = -1e30f;
            }
        }

        float mxA = -1e30f, mxB = -1e30f;
        #pragma unroll
        for (int nt = 0; nt < 8; nt++) {
            mxA = fmaxf(mxA, fmaxf(s[nt][0], s[nt][1]));
            mxB = fmaxf(mxB, fmaxf(s[nt][2], s[nt][3]));
        }
        mxA = fmaxf(mxA, __shfl_xor_sync(0xffffffffu, mxA, 1));
        mxA = fmaxf(mxA, __shfl_xor_sync(0xffffffffu, mxA, 2));
        mxB = fmaxf(mxB, __shfl_xor_sync(0xffffffffu, mxB, 1));
        mxB = fmaxf(mxB, __shfl_xor_sync(0xffffffffu, mxB, 2));
        float mnA = fmaxf(mA, mxA);
        float mnB = fmaxf(mB, mxB);
        float corrA = __expf(mA - mnA);
        float corrB = __expf(mB - mnB);

        float sumA = 0.f, sumB = 0.f;
        #pragma unroll
        for (int nt = 0; nt < 8; nt++) {
            s[nt][0] = __expf(s[nt][0] - mnA); sumA += s[nt][0];
            s[nt][1] = __expf(s[nt][1] - mnA); sumA += s[nt][1];
            s[nt][2] = __expf(s[nt][2] - mnB); sumB += s[nt][2];
            s[nt][3] = __expf(s[nt][3] - mnB); sumB += s[nt][3];
        }
        sumA += __shfl_xor_sync(0xffffffffu, sumA, 1);
        sumA += __shfl_xor_sync(0xffffffffu, sumA, 2);
        sumB += __shfl_xor_sync(0xffffffffu, sumB, 1);
        sumB += __shfl_xor_sync(0xffffffffu, sumB, 2);
        lA = lA * corrA + sumA;
        lB = lB * corrB + sumB;
        mA = mnA; mB = mnB;

        #pragma unroll
        for (int nt = 0; nt < 8; nt++) {
            o[nt][0] *= corrA; o[nt][1] *= corrA;
            o[nt][2] *= corrB; o[nt][3] *= corrB;
        }

        __syncthreads();
        #pragma unroll
        for (int nt = 0; nt < 8; nt++) {
            int c0 = nt * 8 + 2 * t;
            KPs[rA][c0    ] = cvt_tf32(s[nt][0]);
            KPs[rA][c0 + 1] = cvt_tf32(s[nt][1]);
            KPs[rB][c0    ] = cvt_tf32(s[nt][2]);
            KPs[rB][c0 + 1] = cvt_tf32(s[nt][3]);
        }
        __syncwarp();

        #pragma unroll
        for (int kc = 0; kc < 8; kc++) {
            uint32_t a0 = __float_as_uint(KPs[rA][kc*8 + t    ]);
            uint32_t a1 = __float_as_uint(KPs[rB][kc*8 + t    ]);
            uint32_t a2 = __float_as_uint(KPs[rA][kc*8 + t + 4]);
            uint32_t a3 = __float_as_uint(KPs[rB][kc*8 + t + 4]);
            #pragma unroll
            for (int nt = 0; nt < 8; nt++) {
                uint32_t b0 = __float_as_uint(Vs[kc*8 + t    ][nt*8 + g]);
                uint32_t b1 = __float_as_uint(Vs[kc*8 + t + 4][nt*8 + g]);
                mma_tf32(o[nt][0], o[nt][1], o[nt][2], o[nt][3],
                         a0, a1, a2, a3, b0, b1);
            }
        }
        __syncthreads();
    }

    float invA = 1.0f / lA, invB = 1.0f / lB;
    int rowA = qbase + 16 * w + g;
    float* yA = Y + (size_t)(b * TT + rowA) * CC + hoff;
    float* yB = Y + (size_t)(b * TT + rowA + 8) * CC + hoff;
    #pragma unroll
    for (int nt = 0; nt < 8; nt++) {
        int c0 = nt * 8 + 2 * t;
        *(float2*)(yA + c0) = make_float2(cvt_tf32(o[nt][0] * invA), cvt_tf32(o[nt][1] * invA));
        *(float2*)(yB + c0) = make_float2(cvt_tf32(o[nt][2] * invB), cvt_tf32(o[nt][3] * invB));
    }
}

// ---------------- launcher ----------------
extern "C" void kernel_launch(void* const* d_in, const int* in_sizes, int n_in,
                              void* d_out, int out_size) {
    const float* x     = (const float*)d_in[0];
    const float* ln1_g = (const float*)d_in[1];
    const float* ln1_b = (const float*)d_in[2];
    const float* Wq    = (const float*)d_in[3];
    const float* bq    = (const float*)d_in[4];
    const float* Wk    = (const float*)d_in[5];
    const float* bk    = (const float*)d_in[6];
    const float* Wv    = (const float*)d_in[7];
    const float* bv    = (const float*)d_in[8];
    const float* Wo    = (const float*)d_in[9];
    const float* bo    = (const float*)d_in[10];
    const float* ln2_g = (const float*)d_in[11];
    const float* ln2_b = (const float*)d_in[12];
    const float* W1    = (const float*)d_in[13];
    const float* b1    = (const float*)d_in[14];
    const float* W2    = (const float*)d_in[15];
    const float* b2    = (const float*)d_in[16];
    float* out = (float*)d_out;

    float *h, *q, *k, *v, *y, *x1, *m;
    float *wqkv, *bqkv, *wo, *w1, *w2;
    cudaGetSymbolAddress((void**)&h,    g_h);
    cudaGetSymbolAddress((void**)&q,    g_q);
    cudaGetSymbolAddress((void**)&k,    g_k);
    cudaGetSymbolAddress((void**)&v,    g_v);
    cudaGetSymbolAddress((void**)&y,    g_y);
    cudaGetSymbolAddress((void**)&x1,   g_x1);
    cudaGetSymbolAddress((void**)&m,    g_m);
    cudaGetSymbolAddress((void**)&wqkv, g_wqkv);
    cudaGetSymbolAddress((void**)&bqkv, g_bqkv);
    cudaGetSymbolAddress((void**)&wo,   g_wo);
    cudaGetSymbolAddress((void**)&w1,   g_w1);
    cudaGetSymbolAddress((void**)&w2,   g_w2);

    cudaFuncSetAttribute(gemm_tc<0>, cudaFuncAttributeMaxDynamicSharedMemorySize, GEMM_SMEM);
    cudaFuncSetAttribute(gemm_tc<1>, cudaFuncAttributeMaxDynamicSharedMemorySize, GEMM_SMEM);
    cudaFuncSetAttribute(gemm_tc<2>, cudaFuncAttributeMaxDynamicSharedMemorySize, GEMM_SMEM);

    // 0) weight prep (rna rounding; QKV concat)
    round_copy_cat<<<dim3(CC/(256*4), CC), 256>>>(Wq, wqkv, CC, 0);
    round_copy_cat<<<dim3(CC/(256*4), CC), 256>>>(Wk, wqkv, CC, CC);
    round_copy_cat<<<dim3(CC/(256*4), CC), 256>>>(Wv, wqkv, CC, 2*CC);
    cat_bias<<<CC/256, 256>>>(bq, bk, bv, bqkv);
    round_copy<<<(CC*CC)/(256*4), 256>>>(Wo, wo, CC*CC);
    round_copy<<<(CC*FF)/(256*4), 256>>>(W1, w1, CC*FF);
    round_copy<<<(FF*CC)/(256*4), 256>>>(W2, w2, FF*CC);

    dim3 gQKV(3*CC / 128, ROWS / 128);
    dim3 gC(CC / 128, ROWS / 128);
    dim3 gF(FF / 128, ROWS / 128);

    ln_kernel<<<ROWS, 256>>>(x, ln1_g, ln1_b, h);
    gemm_tc<0><<<gQKV, 256, GEMM_SMEM>>>(h, wqkv, bqkv, nullptr, q, k, v,
                                         ROWS, 3*CC, CC, CC);
    attn_tc_kernel<<<dim3(TT / 64, NH, BB), 128>>>(q, k, v, y);
    gemm_tc<1><<<gC, 256, GEMM_SMEM>>>(y, wo, bo, x, x1, x1, x1,
                                       ROWS, CC, CC, CC);
    ln_kernel<<<ROWS, 256>>>(x1, ln2_g, ln2_b, h);
    gemm_tc<2><<<gF, 256, GEMM_SMEM>>>(h, w1, b1, nullptr, m, m, m,
                                       ROWS, FF, CC, FF);
    gemm_tc<1><<<gC, 256, GEMM_SMEM>>>(m, w2, b2, x1, out, out, out,
                                       ROWS, CC, FF, CC);
}

// round 11
// speedup vs baseline: 1.2563x; 1.0021x over previous
#include <cuda_runtime.h>
#include <cuda_bf16.h>
#include <math.h>
#include <stdint.h>

// Problem constants
#define BB   4
#define TT   2048
#define CC   1024
#define NH   16
#define DH   64
#define ROWS (BB * TT)        // 8192
#define FF   (4 * CC)         // 4096

// ---------------- scratch (no allocs allowed) ----------------
__device__ float g_h [ROWS * CC];
__device__ float g_q [ROWS * CC];
__device__ float g_k [ROWS * CC];
__device__ float g_v [ROWS * CC];
__device__ float g_y [ROWS * CC];
__device__ float g_x1[ROWS * CC];
__device__ float g_m [ROWS * FF];
// rna-rounded weight copies
__device__ float g_wqkv[CC * 3 * CC];   // [K=1024][N=3072] (Wq|Wk|Wv)
__device__ float g_bqkv[3 * CC];
__device__ float g_wo  [CC * CC];
__device__ float g_w1  [CC * FF];
__device__ float g_w2  [FF * CC];

// ---------------- common helpers ----------------
__device__ __forceinline__ float gelu_exact(float x) {
    return 0.5f * x * (1.0f + erff(x * 0.70710678118654752f));
}

__device__ __forceinline__ float cvt_tf32(float x) {
    uint32_t r;
    asm("cvt.rna.tf32.f32 %0, %1;" : "=r"(r) : "f"(x));
    return __uint_as_float(r);
}

__device__ __forceinline__ void mma_tf32(float& d0, float& d1, float& d2, float& d3,
                                         uint32_t a0, uint32_t a1, uint32_t a2, uint32_t a3,
                                         uint32_t b0, uint32_t b1) {
    asm volatile(
        "mma.sync.aligned.m16n8k8.row.col.f32.tf32.tf32.f32 "
        "{%0,%1,%2,%3}, {%4,%5,%6,%7}, {%8,%9}, {%0,%1,%2,%3};"
        : "+f"(d0), "+f"(d1), "+f"(d2), "+f"(d3)
        : "r"(a0), "r"(a1), "r"(a2), "r"(a3), "r"(b0), "r"(b1));
}

#define CP_ASYNC16(dst, src) \
    asm volatile("cp.async.cg.shared.global [%0], [%1], 16;\n" :: "r"(dst), "l"(src))
#define CP_COMMIT() asm volatile("cp.async.commit_group;\n" ::: "memory")

// ---------------- weight prep: rna-rounded copy ----------------
__global__ void round_copy(const float* __restrict__ src, float* __restrict__ dst,
                           int n) {
    int i = (blockIdx.x * blockDim.x + threadIdx.x) * 4;
    if (i < n) {
        float4 v = *(const float4*)(src + i);
        v.x = cvt_tf32(v.x); v.y = cvt_tf32(v.y);
        v.z = cvt_tf32(v.z); v.w = cvt_tf32(v.w);
        *(float4*)(dst + i) = v;
    }
}

__global__ void round_copy_cat(const float* __restrict__ src, float* __restrict__ dst,
                               int K, int coloff) {
    int k = blockIdx.y;
    int n = (blockIdx.x * blockDim.x + threadIdx.x) * 4;
    float4 v = *(const float4*)(src + (size_t)k * CC + n);
    v.x = cvt_tf32(v.x); v.y = cvt_tf32(v.y);
    v.z = cvt_tf32(v.z); v.w = cvt_tf32(v.w);
    *(float4*)(dst + (size_t)k * (3 * CC) + coloff + n) = v;
}

__global__ void cat_bias(const float* __restrict__ b0, const float* __restrict__ b1,
                         const float* __restrict__ b2, float* __restrict__ dst) {
    int i = blockIdx.x * blockDim.x + threadIdx.x;
    dst[i]          = b0[i];
    dst[i + CC]     = b1[i];
    dst[i + 2 * CC] = b2[i];
}

// ---------------- LayerNorm: one block per row (rna-rounded out) --------------
__global__ void ln_kernel(const float* __restrict__ X,
                          const float* __restrict__ gam,
                          const float* __restrict__ bet,
                          float* __restrict__ out) {
    int row = blockIdx.x;
    int tid = threadIdx.x;
    const float4* x4 = (const float4*)(X + (size_t)row * CC);
    float4 v = x4[tid];
    float s  = v.x + v.y + v.z + v.w;
    float ss = v.x*v.x + v.y*v.y + v.z*v.z + v.w*v.w;
    #pragma unroll
    for (int off = 16; off > 0; off >>= 1) {
        s  += __shfl_down_sync(0xffffffffu, s,  off);
        ss += __shfl_down_sync(0xffffffffu, ss, off);
    }
    __shared__ float smS[8], smQ[8];
    __shared__ float sh_mu, sh_rstd;
    int lane = tid & 31, w = tid >> 5;
    if (lane == 0) { smS[w] = s; smQ[w] = ss; }
    __syncthreads();
    if (tid == 0) {
        float ts = 0.f, tq = 0.f;
        #pragma unroll
        for (int i = 0; i < 8; i++) { ts += smS[i]; tq += smQ[i]; }
        float mu  = ts * (1.0f / CC);
        float var = tq * (1.0f / CC) - mu * mu;
        sh_mu = mu;
        sh_rstd = rsqrtf(var + 1e-5f);
    }
    __syncthreads();
    float mu = sh_mu, rstd = sh_rstd;
    float4 gv = ((const float4*)gam)[tid];
    float4 bv = ((const float4*)bet)[tid];
    float4 o;
    o.x = cvt_tf32((v.x - mu) * rstd * gv.x + bv.x);
    o.y = cvt_tf32((v.y - mu) * rstd * gv.y + bv.y);
    o.z = cvt_tf32((v.z - mu) * rstd * gv.z + bv.z);
    o.w = cvt_tf32((v.w - mu) * rstd * gv.w + bv.w);
    ((float4*)(out + (size_t)row * CC))[tid] = o;
}

// ---------------- TF32 HMMA GEMM: 16-k stages, 5-stage ring, 2 stages/barrier --
// C = A[M,K] @ W[K,N] + bias (+res) (+gelu+round); output split for QKV fusion.
#define AST 20
#define WST 132
#define GST 5
#define STG_FLOATS (128 * AST + 16 * WST)   // 4672 floats = 18688 B
#define STG_BYTES  (STG_FLOATS * 4)
#define GEMM_SMEM  (GST * STG_BYTES)        // 93440 B

template <int EPI>
__global__ __launch_bounds__(256, 2)
void gemm_tc(const float* __restrict__ A, const float* __restrict__ W,
             const float* __restrict__ bias, const float* __restrict__ res,
             float* __restrict__ C0, float* __restrict__ C1, float* __restrict__ C2,
             int M, int N, int K, int outN) {
    extern __shared__ __align__(16) float dsm[];

    int tid  = threadIdx.x;
    int lane = tid & 31;
    int wid  = tid >> 5;
    int warp_m = wid >> 2;
    int warp_n = wid & 3;
    int g = lane >> 2, t = lane & 3;
    int bm = blockIdx.y * 128;
    int bn = blockIdx.x * 128;

    int bi = bn / outN;
    float* C = (bi == 0) ? C0 : ((bi == 1) ? C1 : C2);
    int cn = bn - bi * outN;

    // staging map (identical to R8)
    int am  = tid >> 2;             // 0..63: rows am, am+64
    int akq = (tid & 3) * 4;        // 0,4,8,12
    int wk  = tid >> 5;             // 0..7: rows wk, wk+8
    int wn4 = (tid & 31) * 4;

    const float* Apb = A + (size_t)(bm + am) * K + akq;
    const float* Wpb = W + (size_t)wk * N + bn + wn4;

    // base smem addresses for stage 0 (stage s = base + s*STG_BYTES)
    uint32_t bA0 = (uint32_t)__cvta_generic_to_shared(dsm + am * AST + akq);
    uint32_t bA1 = (uint32_t)__cvta_generic_to_shared(dsm + (am + 64) * AST + akq);
    uint32_t bW0 = (uint32_t)__cvta_generic_to_shared(dsm + 128 * AST + wk * WST + wn4);
    uint32_t bW1 = (uint32_t)__cvta_generic_to_shared(dsm + 128 * AST + (wk + 8) * WST + wn4);

    float acc[4][4][4];
    #pragma unroll
    for (int i = 0; i < 4; i++)
        #pragma unroll
        for (int j = 0; j < 4; j++)
            #pragma unroll
            for (int r = 0; r < 4; r++) acc[i][j][r] = 0.f;

    int NT = K >> 4;   // K/16 (even)

    // prologue: issue stages 0,1,2 (3 commit groups)
    #pragma unroll
    for (int s = 0; s < 3; s++) {
        uint32_t so = (uint32_t)s * STG_BYTES;
        int k0 = s << 4;
        CP_ASYNC16(bA0 + so, Apb + k0);
        CP_ASYNC16(bA1 + so, Apb + (size_t)64 * K + k0);
        CP_ASYNC16(bW0 + so, Wpb + (size_t)k0 * N);
        CP_ASYNC16(bW1 + so, Wpb + (size_t)(k0 + 8) * N);
        CP_COMMIT();
    }

    for (int kt = 0; kt < NT; kt += 2) {
        asm volatile("cp.async.wait_group 1;" ::: "memory");
        __syncthreads();

        // issue stages kt+3 and kt+4 (buffers (kt+3)%5 and (kt-1)%5 — both dead)
        #pragma unroll
        for (int d = 3; d <= 4; d++) {
            int ks = kt + d;
            if (ks < NT) {
                uint32_t so = (uint32_t)(ks % GST) * STG_BYTES;
                int k0 = ks << 4;
                CP_ASYNC16(bA0 + so, Apb + k0);
                CP_ASYNC16(bA1 + so, Apb + (size_t)64 * K + k0);
                CP_ASYNC16(bW0 + so, Wpb + (size_t)k0 * N);
                CP_ASYNC16(bW1 + so, Wpb + (size_t)(k0 + 8) * N);
            }
            CP_COMMIT();
        }

        // compute stages kt and kt+1 back-to-back (one barrier covers both)
        #pragma unroll
        for (int d = 0; d < 2; d++) {
            int st = (kt + d) % GST;
            float* base = dsm + st * STG_FLOATS;
            float (*As)[AST] = (float(*)[AST])base;
            float (*Ws)[WST] = (float(*)[WST])(base + 128 * AST);

            #pragma unroll
            for (int kc = 0; kc < 2; kc++) {
                int kr = kc * 8 + t;
                uint32_t af[4][4];
                uint32_t bf[4][2];
                #pragma unroll
                for (int mtl = 0; mtl < 4; mtl++) {
                    int m = warp_m * 64 + mtl * 16 + g;
                    af[mtl][0] = __float_as_uint(As[m    ][kr    ]);
                    af[mtl][1] = __float_as_uint(As[m + 8][kr    ]);
                    af[mtl][2] = __float_as_uint(As[m    ][kr + 4]);
                    af[mtl][3] = __float_as_uint(As[m + 8][kr + 4]);
                }
                #pragma unroll
                for (int ntl = 0; ntl < 4; ntl++) {
                    int n = warp_n * 32 + ntl * 8 + g;
                    bf[ntl][0] = __float_as_uint(Ws[kr    ][n]);
                    bf[ntl][1] = __float_as_uint(Ws[kr + 4][n]);
                }
                #pragma unroll
                for (int mtl = 0; mtl < 4; mtl++)
                    #pragma unroll
                    for (int ntl = 0; ntl < 4; ntl++)
                        mma_tf32(acc[mtl][ntl][0], acc[mtl][ntl][1],
                                 acc[mtl][ntl][2], acc[mtl][ntl][3],
                                 af[mtl][0], af[mtl][1], af[mtl][2], af[mtl][3],
                                 bf[ntl][0], bf[ntl][1]);
            }
        }
    }

    // ---- epilogue ----
    #pragma unroll
    for (int mt = 0; mt < 4; mt++) {
        int r0 = bm + warp_m * 64 + mt * 16 + g;
        #pragma unroll
        for (int nt = 0; nt < 4; nt++) {
            int gcol = bn + warp_n * 32 + nt * 8 + t * 2;
            int col  = cn + warp_n * 32 + nt * 8 + t * 2;
            float b0 = bias[gcol], b1 = bias[gcol + 1];
            #pragma unroll
            for (int h = 0; h < 2; h++) {
                int row = r0 + h * 8;
                float v0 = acc[mt][nt][h * 2 + 0] + b0;
                float v1 = acc[mt][nt][h * 2 + 1] + b1;
                if (EPI == 1) {
                    const float* rp = res + (size_t)row * outN + col;
                    v0 += rp[0]; v1 += rp[1];
                }
                if (EPI == 2) {
                    v0 = cvt_tf32(gelu_exact(v0));
                    v1 = cvt_tf32(gelu_exact(v1));
                }
                *(float2*)(C + (size_t)row * outN + col) = make_float2(v0, v1);
            }
        }
    }
}

// ---------------- Tensor-core flash attention (causal, tf32) ----------------
#define KS_STR 68
#define VS_STR 72

__global__ __launch_bounds__(128)
void attn_tc_kernel(const float* __restrict__ Q,
                    const float* __restrict__ K,
                    const float* __restrict__ V,
                    float* __restrict__ Y) {
    __shared__ float KPs[64][KS_STR];
    __shared__ float Vs [64][VS_STR];

    int qt = blockIdx.x, h = blockIdx.y, b = blockIdx.z;
    int tid = threadIdx.x;
    int lane = tid & 31, w = tid >> 5;
    int g = lane >> 2, t = lane & 3;
    int qbase = qt * 64;
    const int hoff = h * DH;

    int lrow = tid >> 1;
    int ld0  = (tid & 1) * 32;

    {
        const float* qp = Q + (size_t)(b * TT + qbase + lrow) * CC + hoff + ld0;
        #pragma unroll
        for (int i = 0; i < 8; i++) {
            float4 v4 = ((const float4*)qp)[i];
            KPs[lrow][ld0 + 4*i + 0] = cvt_tf32(v4.x * 0.125f);
            KPs[lrow][ld0 + 4*i + 1] = cvt_tf32(v4.y * 0.125f);
            KPs[lrow][ld0 + 4*i + 2] = cvt_tf32(v4.z * 0.125f);
            KPs[lrow][ld0 + 4*i + 3] = cvt_tf32(v4.w * 0.125f);
        }
    }
    __syncthreads();
    uint32_t qf[8][4];
    {
        int rA = 16 * w + g;
        #pragma unroll
        for (int kc = 0; kc < 8; kc++) {
            qf[kc][0] = __float_as_uint(KPs[rA    ][kc*8 + t    ]);
            qf[kc][1] = __float_as_uint(KPs[rA + 8][kc*8 + t    ]);
            qf[kc][2] = __float_as_uint(KPs[rA    ][kc*8 + t + 4]);
            qf[kc][3] = __float_as_uint(KPs[rA + 8][kc*8 + t + 4]);
        }
    }
    __syncthreads();

    float o[8][4];
    #pragma unroll
    for (int nt = 0; nt < 8; nt++)
        #pragma unroll
        for (int j = 0; j < 4; j++) o[nt][j] = 0.f;
    float mA = -1e30f, mB = -1e30f, lA = 0.f, lB = 0.f;

    float4 kr[8], vr[8];
    {
        const float4* kp = (const float4*)(K + (size_t)(b * TT + lrow) * CC + hoff + ld0);
        const float4* vp = (const float4*)(V + (size_t)(b * TT + lrow) * CC + hoff + ld0);
        #pragma unroll
        for (int i = 0; i < 8; i++) { kr[i] = kp[i]; vr[i] = vp[i]; }
    }

    for (int kt = 0; kt <= qt; kt++) {
        #pragma unroll
        for (int i = 0; i < 8; i++) {
            float4 kv = kr[i];
            KPs[lrow][ld0 + 4*i + 0] = cvt_tf32(kv.x);
            KPs[lrow][ld0 + 4*i + 1] = cvt_tf32(kv.y);
            KPs[lrow][ld0 + 4*i + 2] = cvt_tf32(kv.z);
            KPs[lrow][ld0 + 4*i + 3] = cvt_tf32(kv.w);
            float4 vv = vr[i];
            Vs[lrow][ld0 + 4*i + 0] = cvt_tf32(vv.x);
            Vs[lrow][ld0 + 4*i + 1] = cvt_tf32(vv.y);
            Vs[lrow][ld0 + 4*i + 2] = cvt_tf32(vv.z);
            Vs[lrow][ld0 + 4*i + 3] = cvt_tf32(vv.w);
        }
        __syncthreads();

        if (kt < qt) {
            const float4* kp = (const float4*)(K + (size_t)(b * TT + (kt+1) * 64 + lrow) * CC + hoff + ld0);
            const float4* vp = (const float4*)(V + (size_t)(b * TT + (kt+1) * 64 + lrow) * CC + hoff + ld0);
            #pragma unroll
            for (int i = 0; i < 8; i++) { kr[i] = kp[i]; vr[i] = vp[i]; }
        }

        float s[8][4];
        #pragma unroll
        for (int nt = 0; nt < 8; nt++)
            #pragma unroll
            for (int j = 0; j < 4; j++) s[nt][j] = 0.f;
        #pragma unroll
        for (int kc = 0; kc < 8; kc++) {
            #pragma unroll
            for (int nt = 0; nt < 8; nt++) {
                uint32_t b0 = __float_as_uint(KPs[nt*8 + g][kc*8 + t    ]);
                uint32_t b1 = __float_as_uint(KPs[nt*8 + g][kc*8 + t + 4]);
                mma_tf32(s[nt][0], s[nt][1], s[nt][2], s[nt][3],
                         qf[kc][0], qf[kc][1], qf[kc][2], qf[kc][3], b0, b1);
            }
        }

        int rA = 16 * w + g;
        int rB = rA + 8;

        if (kt == qt) {
            #pragma unroll
            for (int nt = 0; nt < 8; nt++) {
                int c0 = nt * 8 + 2 * t;
                if (c0     > rA) s[nt][0] = -1e30f;
                if (c0 + 1 > rA) s[nt][1] = -1e30f;
                if (c0     > rB) s[nt][2] = -1e30f;
                if (c0 + 1 > rB) s[nt][3] = -1e30f;
            }
        }

        float mxA = -1e30f, mxB = -1e30f;
        #pragma unroll
        for (int nt = 0; nt < 8; nt++) {
            mxA = fmaxf(mxA, fmaxf(s[nt][0], s[nt][1]));
            mxB = fmaxf(mxB, fmaxf(s[nt][2], s[nt][3]));
        }
        mxA = fmaxf(mxA, __shfl_xor_sync(0xffffffffu, mxA, 1));
        mxA = fmaxf(mxA, __shfl_xor_sync(0xffffffffu, mxA, 2));
        mxB = fmaxf(mxB, __shfl_xor_sync(0xffffffffu, mxB, 1));
        mxB = fmaxf(mxB, __shfl_xor_sync(0xffffffffu, mxB, 2));
        float mnA = fmaxf(mA, mxA);
        float mnB = fmaxf(mB, mxB);
        float corrA = __expf(mA - mnA);
        float corrB = __expf(mB - mnB);

        float sumA = 0.f, sumB = 0.f;
        #pragma unroll
        for (int nt = 0; nt < 8; nt++) {
            s[nt][0] = __expf(s[nt][0] - mnA); sumA += s[nt][0];
            s[nt][1] = __expf(s[nt][1] - mnA); sumA += s[nt][1];
            s[nt][2] = __expf(s[nt][2] - mnB); sumB += s[nt][2];
            s[nt][3] = __expf(s[nt][3] - mnB); sumB += s[nt][3];
        }
        sumA += __shfl_xor_sync(0xffffffffu, sumA, 1);
        sumA += __shfl_xor_sync(0xffffffffu, sumA, 2);
        sumB += __shfl_xor_sync(0xffffffffu, sumB, 1);
        sumB += __shfl_xor_sync(0xffffffffu, sumB, 2);
        lA = lA * corrA + sumA;
        lB = lB * corrB + sumB;
        mA = mnA; mB = mnB;

        #pragma unroll
        for (int nt = 0; nt < 8; nt++) {
            o[nt][0] *= corrA; o[nt][1] *= corrA;
            o[nt][2] *= corrB; o[nt][3] *= corrB;
        }

        __syncthreads();
        #pragma unroll
        for (int nt = 0; nt < 8; nt++) {
            int c0 = nt * 8 + 2 * t;
            KPs[rA][c0    ] = cvt_tf32(s[nt][0]);
            KPs[rA][c0 + 1] = cvt_tf32(s[nt][1]);
            KPs[rB][c0    ] = cvt_tf32(s[nt][2]);
            KPs[rB][c0 + 1] = cvt_tf32(s[nt][3]);
        }
        __syncwarp();

        #pragma unroll
        for (int kc = 0; kc < 8; kc++) {
            uint32_t a0 = __float_as_uint(KPs[rA][kc*8 + t    ]);
            uint32_t a1 = __float_as_uint(KPs[rB][kc*8 + t    ]);
            uint32_t a2 = __float_as_uint(KPs[rA][kc*8 + t + 4]);
            uint32_t a3 = __float_as_uint(KPs[rB][kc*8 + t + 4]);
            #pragma unroll
            for (int nt = 0; nt < 8; nt++) {
                uint32_t b0 = __float_as_uint(Vs[kc*8 + t    ][nt*8 + g]);
                uint32_t b1 = __float_as_uint(Vs[kc*8 + t + 4][nt*8 + g]);
                mma_tf32(o[nt][0], o[nt][1], o[nt][2], o[nt][3],
                         a0, a1, a2, a3, b0, b1);
            }
        }
        __syncthreads();
    }

    float invA = 1.0f / lA, invB = 1.0f / lB;
    int rowA = qbase + 16 * w + g;
    float* yA = Y + (size_t)(b * TT + rowA) * CC + hoff;
    float* yB = Y + (size_t)(b * TT + rowA + 8) * CC + hoff;
    #pragma unroll
    for (int nt = 0; nt < 8; nt++) {
        int c0 = nt * 8 + 2 * t;
        *(float2*)(yA + c0) = make_float2(cvt_tf32(o[nt][0] * invA), cvt_tf32(o[nt][1] * invA));
        *(float2*)(yB + c0) = make_float2(cvt_tf32(o[nt][2] * invB), cvt_tf32(o[nt][3] * invB));
    }
}

// ---------------- launcher ----------------
extern "C" void kernel_launch(void* const* d_in, const int* in_sizes, int n_in,
                              void* d_out, int out_size) {
    const float* x     = (const float*)d_in[0];
    const float* ln1_g = (const float*)d_in[1];
    const float* ln1_b = (const float*)d_in[2];
    const float* Wq    = (const float*)d_in[3];
    const float* bq    = (const float*)d_in[4];
    const float* Wk    = (const float*)d_in[5];
    const float* bk    = (const float*)d_in[6];
    const float* Wv    = (const float*)d_in[7];
    const float* bv    = (const float*)d_in[8];
    const float* Wo    = (const float*)d_in[9];
    const float* bo    = (const float*)d_in[10];
    const float* ln2_g = (const float*)d_in[11];
    const float* ln2_b = (const float*)d_in[12];
    const float* W1    = (const float*)d_in[13];
    const float* b1    = (const float*)d_in[14];
    const float* W2    = (const float*)d_in[15];
    const float* b2    = (const float*)d_in[16];
    float* out = (float*)d_out;

    float *h, *q, *k, *v, *y, *x1, *m;
    float *wqkv, *bqkv, *wo, *w1, *w2;
    cudaGetSymbolAddress((void**)&h,    g_h);
    cudaGetSymbolAddress((void**)&q,    g_q);
    cudaGetSymbolAddress((void**)&k,    g_k);
    cudaGetSymbolAddress((void**)&v,    g_v);
    cudaGetSymbolAddress((void**)&y,    g_y);
    cudaGetSymbolAddress((void**)&x1,   g_x1);
    cudaGetSymbolAddress((void**)&m,    g_m);
    cudaGetSymbolAddress((void**)&wqkv, g_wqkv);
    cudaGetSymbolAddress((void**)&bqkv, g_bqkv);
    cudaGetSymbolAddress((void**)&wo,   g_wo);
    cudaGetSymbolAddress((void**)&w1,   g_w1);
    cudaGetSymbolAddress((void**)&w2,   g_w2);

    cudaFuncSetAttribute(gemm_tc<0>, cudaFuncAttributeMaxDynamicSharedMemorySize, GEMM_SMEM);
    cudaFuncSetAttribute(gemm_tc<1>, cudaFuncAttributeMaxDynamicSharedMemorySize, GEMM_SMEM);
    cudaFuncSetAttribute(gemm_tc<2>, cudaFuncAttributeMaxDynamicSharedMemorySize, GEMM_SMEM);

    // 0) weight prep (rna rounding; QKV concat)
    round_copy_cat<<<dim3(CC/(256*4), CC), 256>>>(Wq, wqkv, CC, 0);
    round_copy_cat<<<dim3(CC/(256*4), CC), 256>>>(Wk, wqkv, CC, CC);
    round_copy_cat<<<dim3(CC/(256*4), CC), 256>>>(Wv, wqkv, CC, 2*CC);
    cat_bias<<<CC/256, 256>>>(bq, bk, bv, bqkv);
    round_copy<<<(CC*CC)/(256*4), 256>>>(Wo, wo, CC*CC);
    round_copy<<<(CC*FF)/(256*4), 256>>>(W1, w1, CC*FF);
    round_copy<<<(FF*CC)/(256*4), 256>>>(W2, w2, FF*CC);

    dim3 gQKV(3*CC / 128, ROWS / 128);
    dim3 gC(CC / 128, ROWS / 128);
    dim3 gF(FF / 128, ROWS / 128);

    ln_kernel<<<ROWS, 256>>>(x, ln1_g, ln1_b, h);
    gemm_tc<0><<<gQKV, 256, GEMM_SMEM>>>(h, wqkv, bqkv, nullptr, q, k, v,
                                         ROWS, 3*CC, CC, CC);
    attn_tc_kernel<<<dim3(TT / 64, NH, BB), 128>>>(q, k, v, y);
    gemm_tc<1><<<gC, 256, GEMM_SMEM>>>(y, wo, bo, x, x1, x1, x1,
                                       ROWS, CC, CC, CC);
    ln_kernel<<<ROWS, 256>>>(x1, ln2_g, ln2_b, h);
    gemm_tc<2><<<gF, 256, GEMM_SMEM>>>(h, w1, b1, nullptr, m, m, m,
                                       ROWS, FF, CC, FF);
    gemm_tc<1><<<gC, 256, GEMM_SMEM>>>(m, w2, b2, x1, out, out, out,
                                       ROWS, CC, FF, CC);
}

// round 12
// speedup vs baseline: 1.2569x; 1.0004x over previous
#include <cuda_runtime.h>
#include <cuda_bf16.h>
#include <math.h>
#include <stdint.h>

// Problem constants
#define BB   4
#define TT   2048
#define CC   1024
#define NH   16
#define DH   64
#define ROWS (BB * TT)        // 8192
#define FF   (4 * CC)         // 4096

// ---------------- scratch (no allocs allowed) ----------------
__device__ float g_h [ROWS * CC];
__device__ float g_q [ROWS * CC];
__device__ float g_k [ROWS * CC];
__device__ float g_v [ROWS * CC];
__device__ float g_y [ROWS * CC];
__device__ float g_x1[ROWS * CC];
__device__ float g_m [ROWS * FF];
// rna-rounded weight copies
__device__ float g_wqkv[CC * 3 * CC];   // [K=1024][N=3072] (Wq|Wk|Wv)
__device__ float g_bqkv[3 * CC];
__device__ float g_wo  [CC * CC];
__device__ float g_w1  [CC * FF];
__device__ float g_w2  [FF * CC];

// ---------------- common helpers ----------------
__device__ __forceinline__ float gelu_exact(float x) {
    return 0.5f * x * (1.0f + erff(x * 0.70710678118654752f));
}

__device__ __forceinline__ float cvt_tf32(float x) {
    uint32_t r;
    asm("cvt.rna.tf32.f32 %0, %1;" : "=r"(r) : "f"(x));
    return __uint_as_float(r);
}

__device__ __forceinline__ void mma_tf32(float& d0, float& d1, float& d2, float& d3,
                                         uint32_t a0, uint32_t a1, uint32_t a2, uint32_t a3,
                                         uint32_t b0, uint32_t b1) {
    asm volatile(
        "mma.sync.aligned.m16n8k8.row.col.f32.tf32.tf32.f32 "
        "{%0,%1,%2,%3}, {%4,%5,%6,%7}, {%8,%9}, {%0,%1,%2,%3};"
        : "+f"(d0), "+f"(d1), "+f"(d2), "+f"(d3)
        : "r"(a0), "r"(a1), "r"(a2), "r"(a3), "r"(b0), "r"(b1));
}

#define CP_ASYNC16(dst, src) \
    asm volatile("cp.async.cg.shared.global [%0], [%1], 16;\n" :: "r"(dst), "l"(src))
#define CP_COMMIT() asm volatile("cp.async.commit_group;\n" ::: "memory")

// ---------------- weight prep: rna-rounded copy ----------------
__global__ void round_copy(const float* __restrict__ src, float* __restrict__ dst,
                           int n) {
    int i = (blockIdx.x * blockDim.x + threadIdx.x) * 4;
    if (i < n) {
        float4 v = *(const float4*)(src + i);
        v.x = cvt_tf32(v.x); v.y = cvt_tf32(v.y);
        v.z = cvt_tf32(v.z); v.w = cvt_tf32(v.w);
        *(float4*)(dst + i) = v;
    }
}

__global__ void round_copy_cat(const float* __restrict__ src, float* __restrict__ dst,
                               int K, int coloff) {
    int k = blockIdx.y;
    int n = (blockIdx.x * blockDim.x + threadIdx.x) * 4;
    float4 v = *(const float4*)(src + (size_t)k * CC + n);
    v.x = cvt_tf32(v.x); v.y = cvt_tf32(v.y);
    v.z = cvt_tf32(v.z); v.w = cvt_tf32(v.w);
    *(float4*)(dst + (size_t)k * (3 * CC) + coloff + n) = v;
}

__global__ void cat_bias(const float* __restrict__ b0, const float* __restrict__ b1,
                         const float* __restrict__ b2, float* __restrict__ dst) {
    int i = blockIdx.x * blockDim.x + threadIdx.x;
    dst[i]          = b0[i];
    dst[i + CC]     = b1[i];
    dst[i + 2 * CC] = b2[i];
}

// ---------------- LayerNorm: one block per row (rna-rounded out) --------------
__global__ void ln_kernel(const float* __restrict__ X,
                          const float* __restrict__ gam,
                          const float* __restrict__ bet,
                          float* __restrict__ out) {
    int row = blockIdx.x;
    int tid = threadIdx.x;
    const float4* x4 = (const float4*)(X + (size_t)row * CC);
    float4 v = x4[tid];
    float s  = v.x + v.y + v.z + v.w;
    float ss = v.x*v.x + v.y*v.y + v.z*v.z + v.w*v.w;
    #pragma unroll
    for (int off = 16; off > 0; off >>= 1) {
        s  += __shfl_down_sync(0xffffffffu, s,  off);
        ss += __shfl_down_sync(0xffffffffu, ss, off);
    }
    __shared__ float smS[8], smQ[8];
    __shared__ float sh_mu, sh_rstd;
    int lane = tid & 31, w = tid >> 5;
    if (lane == 0) { smS[w] = s; smQ[w] = ss; }
    __syncthreads();
    if (tid == 0) {
        float ts = 0.f, tq = 0.f;
        #pragma unroll
        for (int i = 0; i < 8; i++) { ts += smS[i]; tq += smQ[i]; }
        float mu  = ts * (1.0f / CC);
        float var = tq * (1.0f / CC) - mu * mu;
        sh_mu = mu;
        sh_rstd = rsqrtf(var + 1e-5f);
    }
    __syncthreads();
    float mu = sh_mu, rstd = sh_rstd;
    float4 gv = ((const float4*)gam)[tid];
    float4 bv = ((const float4*)bet)[tid];
    float4 o;
    o.x = cvt_tf32((v.x - mu) * rstd * gv.x + bv.x);
    o.y = cvt_tf32((v.y - mu) * rstd * gv.y + bv.y);
    o.z = cvt_tf32((v.z - mu) * rstd * gv.z + bv.z);
    o.w = cvt_tf32((v.w - mu) * rstd * gv.w + bv.w);
    ((float4*)(out + (size_t)row * CC))[tid] = o;
}

// ---------------- TF32 HMMA GEMM: 16-k stages, 5-stage ring, 2 stages/barrier --
// C = A[M,K] @ W[K,N] + bias (+res) (+gelu+round); output split for QKV fusion.
#define AST 20
#define WST 132
#define GST 5
#define STG_FLOATS (128 * AST + 16 * WST)   // 4672 floats = 18688 B
#define STG_BYTES  (STG_FLOATS * 4)
#define GEMM_SMEM  (GST * STG_BYTES)        // 93440 B

template <int EPI>
__global__ __launch_bounds__(256, 2)
void gemm_tc(const float* __restrict__ A, const float* __restrict__ W,
             const float* __restrict__ bias, const float* __restrict__ res,
             float* __restrict__ C0, float* __restrict__ C1, float* __restrict__ C2,
             int M, int N, int K, int outN) {
    extern __shared__ __align__(16) float dsm[];

    int tid  = threadIdx.x;
    int lane = tid & 31;
    int wid  = tid >> 5;
    int warp_m = wid >> 2;
    int warp_n = wid & 3;
    int g = lane >> 2, t = lane & 3;
    int bm = blockIdx.y * 128;
    int bn = blockIdx.x * 128;

    int bi = bn / outN;
    float* C = (bi == 0) ? C0 : ((bi == 1) ? C1 : C2);
    int cn = bn - bi * outN;

    // staging map (identical to R8)
    int am  = tid >> 2;             // 0..63: rows am, am+64
    int akq = (tid & 3) * 4;        // 0,4,8,12
    int wk  = tid >> 5;             // 0..7: rows wk, wk+8
    int wn4 = (tid & 31) * 4;

    const float* Apb = A + (size_t)(bm + am) * K + akq;
    const float* Wpb = W + (size_t)wk * N + bn + wn4;

    // base smem addresses for stage 0 (stage s = base + s*STG_BYTES)
    uint32_t bA0 = (uint32_t)__cvta_generic_to_shared(dsm + am * AST + akq);
    uint32_t bA1 = (uint32_t)__cvta_generic_to_shared(dsm + (am + 64) * AST + akq);
    uint32_t bW0 = (uint32_t)__cvta_generic_to_shared(dsm + 128 * AST + wk * WST + wn4);
    uint32_t bW1 = (uint32_t)__cvta_generic_to_shared(dsm + 128 * AST + (wk + 8) * WST + wn4);

    float acc[4][4][4];
    #pragma unroll
    for (int i = 0; i < 4; i++)
        #pragma unroll
        for (int j = 0; j < 4; j++)
            #pragma unroll
            for (int r = 0; r < 4; r++) acc[i][j][r] = 0.f;

    int NT = K >> 4;   // K/16 (even)

    // prologue: issue stages 0,1,2 (3 commit groups)
    #pragma unroll
    for (int s = 0; s < 3; s++) {
        uint32_t so = (uint32_t)s * STG_BYTES;
        int k0 = s << 4;
        CP_ASYNC16(bA0 + so, Apb + k0);
        CP_ASYNC16(bA1 + so, Apb + (size_t)64 * K + k0);
        CP_ASYNC16(bW0 + so, Wpb + (size_t)k0 * N);
        CP_ASYNC16(bW1 + so, Wpb + (size_t)(k0 + 8) * N);
        CP_COMMIT();
    }

    for (int kt = 0; kt < NT; kt += 2) {
        asm volatile("cp.async.wait_group 1;" ::: "memory");
        __syncthreads();

        // issue stages kt+3 and kt+4 (buffers (kt+3)%5 and (kt-1)%5 — both dead)
        #pragma unroll
        for (int d = 3; d <= 4; d++) {
            int ks = kt + d;
            if (ks < NT) {
                uint32_t so = (uint32_t)(ks % GST) * STG_BYTES;
                int k0 = ks << 4;
                CP_ASYNC16(bA0 + so, Apb + k0);
                CP_ASYNC16(bA1 + so, Apb + (size_t)64 * K + k0);
                CP_ASYNC16(bW0 + so, Wpb + (size_t)k0 * N);
                CP_ASYNC16(bW1 + so, Wpb + (size_t)(k0 + 8) * N);
            }
            CP_COMMIT();
        }

        // compute stages kt and kt+1 back-to-back (one barrier covers both)
        #pragma unroll
        for (int d = 0; d < 2; d++) {
            int st = (kt + d) % GST;
            float* base = dsm + st * STG_FLOATS;
            float (*As)[AST] = (float(*)[AST])base;
            float (*Ws)[WST] = (float(*)[WST])(base + 128 * AST);

            #pragma unroll
            for (int kc = 0; kc < 2; kc++) {
                int kr = kc * 8 + t;
                uint32_t af[4][4];
                uint32_t bf[4][2];
                #pragma unroll
                for (int mtl = 0; mtl < 4; mtl++) {
                    int m = warp_m * 64 + mtl * 16 + g;
                    af[mtl][0] = __float_as_uint(As[m    ][kr    ]);
                    af[mtl][1] = __float_as_uint(As[m + 8][kr    ]);
                    af[mtl][2] = __float_as_uint(As[m    ][kr + 4]);
                    af[mtl][3] = __float_as_uint(As[m + 8][kr + 4]);
                }
                #pragma unroll
                for (int ntl = 0; ntl < 4; ntl++) {
                    int n = warp_n * 32 + ntl * 8 + g;
                    bf[ntl][0] = __float_as_uint(Ws[kr    ][n]);
                    bf[ntl][1] = __float_as_uint(Ws[kr + 4][n]);
                }
                #pragma unroll
                for (int mtl = 0; mtl < 4; mtl++)
                    #pragma unroll
                    for (int ntl = 0; ntl < 4; ntl++)
                        mma_tf32(acc[mtl][ntl][0], acc[mtl][ntl][1],
                                 acc[mtl][ntl][2], acc[mtl][ntl][3],
                                 af[mtl][0], af[mtl][1], af[mtl][2], af[mtl][3],
                                 bf[ntl][0], bf[ntl][1]);
            }
        }
    }

    // ---- epilogue ----
    #pragma unroll
    for (int mt = 0; mt < 4; mt++) {
        int r0 = bm + warp_m * 64 + mt * 16 + g;
        #pragma unroll
        for (int nt = 0; nt < 4; nt++) {
            int gcol = bn + warp_n * 32 + nt * 8 + t * 2;
            int col  = cn + warp_n * 32 + nt * 8 + t * 2;
            float b0 = bias[gcol], b1 = bias[gcol + 1];
            #pragma unroll
            for (int h = 0; h < 2; h++) {
                int row = r0 + h * 8;
                float v0 = acc[mt][nt][h * 2 + 0] + b0;
                float v1 = acc[mt][nt][h * 2 + 1] + b1;
                if (EPI == 1) {
                    const float* rp = res + (size_t)row * outN + col;
                    v0 += rp[0]; v1 += rp[1];
                }
                if (EPI == 2) {
                    v0 = cvt_tf32(gelu_exact(v0));
                    v1 = cvt_tf32(gelu_exact(v1));
                }
                *(float2*)(C + (size_t)row * outN + col) = make_float2(v0, v1);
            }
        }
    }
}

// ---------------- Tensor-core flash attention (causal, tf32) ----------------
#define KS_STR 68
#define VS_STR 72

__global__ __launch_bounds__(128)
void attn_tc_kernel(const float* __restrict__ Q,
                    const float* __restrict__ K,
                    const float* __restrict__ V,
                    float* __restrict__ Y) {
    __shared__ float KPs[64][KS_STR];
    __shared__ float Vs [64][VS_STR];

    int qt = blockIdx.x, h = blockIdx.y, b = blockIdx.z;
    int tid = threadIdx.x;
    int lane = tid & 31, w = tid >> 5;
    int g = lane >> 2, t = lane & 3;
    int qbase = qt * 64;
    const int hoff = h * DH;

    int lrow = tid >> 1;
    int ld0  = (tid & 1) * 32;

    {
        const float* qp = Q + (size_t)(b * TT + qbase + lrow) * CC + hoff + ld0;
        #pragma unroll
        for (int i = 0; i < 8; i++) {
            float4 v4 = ((const float4*)qp)[i];
            KPs[lrow][ld0 + 4*i + 0] = cvt_tf32(v4.x * 0.125f);
            KPs[lrow][ld0 + 4*i + 1] = cvt_tf32(v4.y * 0.125f);
            KPs[lrow][ld0 + 4*i + 2] = cvt_tf32(v4.z * 0.125f);
            KPs[lrow][ld0 + 4*i + 3] = cvt_tf32(v4.w * 0.125f);
        }
    }
    __syncthreads();
    uint32_t qf[8][4];
    {
        int rA = 16 * w + g;
        #pragma unroll
        for (int kc = 0; kc < 8; kc++) {
            qf[kc][0] = __float_as_uint(KPs[rA    ][kc*8 + t    ]);
            qf[kc][1] = __float_as_uint(KPs[rA + 8][kc*8 + t    ]);
            qf[kc][2] = __float_as_uint(KPs[rA    ][kc*8 + t + 4]);
            qf[kc][3] = __float_as_uint(KPs[rA + 8][kc*8 + t + 4]);
        }
    }
    __syncthreads();

    float o[8][4];
    #pragma unroll
    for (int nt = 0; nt < 8; nt++)
        #pragma unroll
        for (int j = 0; j < 4; j++) o[nt][j] = 0.f;
    float mA = -1e30f, mB = -1e30f, lA = 0.f, lB = 0.f;

    float4 kr[8], vr[8];
    {
        const float4* kp = (const float4*)(K + (size_t)(b * TT + lrow) * CC + hoff + ld0);
        const float4* vp = (const float4*)(V + (size_t)(b * TT + lrow) * CC + hoff + ld0);
        #pragma unroll
        for (int i = 0; i < 8; i++) { kr[i] = kp[i]; vr[i] = vp[i]; }
    }

    for (int kt = 0; kt <= qt; kt++) {
        #pragma unroll
        for (int i = 0; i < 8; i++) {
            float4 kv = kr[i];
            KPs[lrow][ld0 + 4*i + 0] = cvt_tf32(kv.x);
            KPs[lrow][ld0 + 4*i + 1] = cvt_tf32(kv.y);
            KPs[lrow][ld0 + 4*i + 2] = cvt_tf32(kv.z);
            KPs[lrow][ld0 + 4*i + 3] = cvt_tf32(kv.w);
            float4 vv = vr[i];
            Vs[lrow][ld0 + 4*i + 0] = cvt_tf32(vv.x);
            Vs[lrow][ld0 + 4*i + 1] = cvt_tf32(vv.y);
            Vs[lrow][ld0 + 4*i + 2] = cvt_tf32(vv.z);
            Vs[lrow][ld0 + 4*i + 3] = cvt_tf32(vv.w);
        }
        __syncthreads();

        if (kt < qt) {
            const float4* kp = (const float4*)(K + (size_t)(b * TT + (kt+1) * 64 + lrow) * CC + hoff + ld0);
            const float4* vp = (const float4*)(V + (size_t)(b * TT + (kt+1) * 64 + lrow) * CC + hoff + ld0);
            #pragma unroll
            for (int i = 0; i < 8; i++) { kr[i] = kp[i]; vr[i] = vp[i]; }
        }

        float s[8][4];
        #pragma unroll
        for (int nt = 0; nt < 8; nt++)
            #pragma unroll
            for (int j = 0; j < 4; j++) s[nt][j] = 0.f;
        #pragma unroll
        for (int kc = 0; kc < 8; kc++) {
            #pragma unroll
            for (int nt = 0; nt < 8; nt++) {
                uint32_t b0 = __float_as_uint(KPs[nt*8 + g][kc*8 + t    ]);
                uint32_t b1 = __float_as_uint(KPs[nt*8 + g][kc*8 + t + 4]);
                mma_tf32(s[nt][0], s[nt][1], s[nt][2], s[nt][3],
                         qf[kc][0], qf[kc][1], qf[kc][2], qf[kc][3], b0, b1);
            }
        }

        int rA = 16 * w + g;
        int rB = rA + 8;

        if (kt == qt) {
            #pragma unroll
            for (int nt = 0; nt < 8; nt++) {
                int c0 = nt * 8 + 2 * t;
                if (c0     > rA) s[nt][0] = -1e30f;
                if (c0 + 1 > rA) s[nt][1] = -1e30f;
                if (c0     > rB) s[nt][2] = -1e30f;
                if (c0 + 1 > rB) s[nt][3] = -1e30f;
            }
        }

        float mxA = -1e30f, mxB = -1e30f;
        #pragma unroll
        for (int nt = 0; nt < 8; nt++) {
            mxA = fmaxf(mxA, fmaxf(s[nt][0], s[nt][1]));
            mxB = fmaxf(mxB, fmaxf(s[nt][2], s[nt][3]));
        }
        mxA = fmaxf(mxA, __shfl_xor_sync(0xffffffffu, mxA, 1));
        mxA = fmaxf(mxA, __shfl_xor_sync(0xffffffffu, mxA, 2));
        mxB = fmaxf(mxB, __shfl_xor_sync(0xffffffffu, mxB, 1));
        mxB = fmaxf(mxB, __shfl_xor_sync(0xffffffffu, mxB, 2));
        float mnA = fmaxf(mA, mxA);
        float mnB = fmaxf(mB, mxB);
        float corrA = __expf(mA - mnA);
        float corrB = __expf(mB - mnB);

        float sumA = 0.f, sumB = 0.f;
        #pragma unroll
        for (int nt = 0; nt < 8; nt++) {
            s[nt][0] = __expf(s[nt][0] - mnA); sumA += s[nt][0];
            s[nt][1] = __expf(s[nt][1] - mnA); sumA += s[nt][1];
            s[nt][2] = __expf(s[nt][2] - mnB); sumB += s[nt][2];
            s[nt][3] = __expf(s[nt][3] - mnB); sumB += s[nt][3];
        }
        sumA += __shfl_xor_sync(0xffffffffu, sumA, 1);
        sumA += __shfl_xor_sync(0xffffffffu, sumA, 2);
        sumB += __shfl_xor_sync(0xffffffffu, sumB, 1);
        sumB += __shfl_xor_sync(0xffffffffu, sumB, 2);
        lA = lA * corrA + sumA;
        lB = lB * corrB + sumB;
        mA = mnA; mB = mnB;

        #pragma unroll
        for (int nt = 0; nt < 8; nt++) {
            o[nt][0] *= corrA; o[nt][1] *= corrA;
            o[nt][2] *= corrB; o[nt][3] *= corrB;
        }

        __syncthreads();
        #pragma unroll
        for (int nt = 0; nt < 8; nt++) {
            int c0 = nt * 8 + 2 * t;
            KPs[rA][c0    ] = cvt_tf32(s[nt][0]);
            KPs[rA][c0 + 1] = cvt_tf32(s[nt][1]);
            KPs[rB][c0    ] = cvt_tf32(s[nt][2]);
            KPs[rB][c0 + 1] = cvt_tf32(s[nt][3]);
        }
        __syncwarp();

        #pragma unroll
        for (int kc = 0; kc < 8; kc++) {
            uint32_t a0 = __float_as_uint(KPs[rA][kc*8 + t    ]);
            uint32_t a1 = __float_as_uint(KPs[rB][kc*8 + t    ]);
            uint32_t a2 = __float_as_uint(KPs[rA][kc*8 + t + 4]);
            uint32_t a3 = __float_as_uint(KPs[rB][kc*8 + t + 4]);
            #pragma unroll
            for (int nt = 0; nt < 8; nt++) {
                uint32_t b0 = __float_as_uint(Vs[kc*8 + t    ][nt*8 + g]);
                uint32_t b1 = __float_as_uint(Vs[kc*8 + t + 4][nt*8 + g]);
                mma_tf32(o[nt][0], o[nt][1], o[nt][2], o[nt][3],
                         a0, a1, a2, a3, b0, b1);
            }
        }
        __syncthreads();
    }

    float invA = 1.0f / lA, invB = 1.0f / lB;
    int rowA = qbase + 16 * w + g;
    float* yA = Y + (size_t)(b * TT + rowA) * CC + hoff;
    float* yB = Y + (size_t)(b * TT + rowA + 8) * CC + hoff;
    #pragma unroll
    for (int nt = 0; nt < 8; nt++) {
        int c0 = nt * 8 + 2 * t;
        *(float2*)(yA + c0) = make_float2(cvt_tf32(o[nt][0] * invA), cvt_tf32(o[nt][1] * invA));
        *(float2*)(yB + c0) = make_float2(cvt_tf32(o[nt][2] * invB), cvt_tf32(o[nt][3] * invB));
    }
}

// ---------------- launcher ----------------
extern "C" void kernel_launch(void* const* d_in, const int* in_sizes, int n_in,
                              void* d_out, int out_size) {
    const float* x     = (const float*)d_in[0];
    const float* ln1_g = (const float*)d_in[1];
    const float* ln1_b = (const float*)d_in[2];
    const float* Wq    = (const float*)d_in[3];
    const float* bq    = (const float*)d_in[4];
    const float* Wk    = (const float*)d_in[5];
    const float* bk    = (const float*)d_in[6];
    const float* Wv    = (const float*)d_in[7];
    const float* bv    = (const float*)d_in[8];
    const float* Wo    = (const float*)d_in[9];
    const float* bo    = (const float*)d_in[10];
    const float* ln2_g = (const float*)d_in[11];
    const float* ln2_b = (const float*)d_in[12];
    const float* W1    = (const float*)d_in[13];
    const float* b1    = (const float*)d_in[14];
    const float* W2    = (const float*)d_in[15];
    const float* b2    = (const float*)d_in[16];
    float* out = (float*)d_out;

    float *h, *q, *k, *v, *y, *x1, *m;
    float *wqkv, *bqkv, *wo, *w1, *w2;
    cudaGetSymbolAddress((void**)&h,    g_h);
    cudaGetSymbolAddress((void**)&q,    g_q);
    cudaGetSymbolAddress((void**)&k,    g_k);
    cudaGetSymbolAddress((void**)&v,    g_v);
    cudaGetSymbolAddress((void**)&y,    g_y);
    cudaGetSymbolAddress((void**)&x1,   g_x1);
    cudaGetSymbolAddress((void**)&m,    g_m);
    cudaGetSymbolAddress((void**)&wqkv, g_wqkv);
    cudaGetSymbolAddress((void**)&bqkv, g_bqkv);
    cudaGetSymbolAddress((void**)&wo,   g_wo);
    cudaGetSymbolAddress((void**)&w1,   g_w1);
    cudaGetSymbolAddress((void**)&w2,   g_w2);

    cudaFuncSetAttribute(gemm_tc<0>, cudaFuncAttributeMaxDynamicSharedMemorySize, GEMM_SMEM);
    cudaFuncSetAttribute(gemm_tc<1>, cudaFuncAttributeMaxDynamicSharedMemorySize, GEMM_SMEM);
    cudaFuncSetAttribute(gemm_tc<2>, cudaFuncAttributeMaxDynamicSharedMemorySize, GEMM_SMEM);

    // 0) weight prep (rna rounding; QKV concat)
    round_copy_cat<<<dim3(CC/(256*4), CC), 256>>>(Wq, wqkv, CC, 0);
    round_copy_cat<<<dim3(CC/(256*4), CC), 256>>>(Wk, wqkv, CC, CC);
    round_copy_cat<<<dim3(CC/(256*4), CC), 256>>>(Wv, wqkv, CC, 2*CC);
    cat_bias<<<CC/256, 256>>>(bq, bk, bv, bqkv);
    round_copy<<<(CC*CC)/(256*4), 256>>>(Wo, wo, CC*CC);
    round_copy<<<(CC*FF)/(256*4), 256>>>(W1, w1, CC*FF);
    round_copy<<<(FF*CC)/(256*4), 256>>>(W2, w2, FF*CC);

    dim3 gQKV(3*CC / 128, ROWS / 128);
    dim3 gC(CC / 128, ROWS / 128);
    dim3 gF(FF / 128, ROWS / 128);

    ln_kernel<<<ROWS, 256>>>(x, ln1_g, ln1_b, h);
    gemm_tc<0><<<gQKV, 256, GEMM_SMEM>>>(h, wqkv, bqkv, nullptr, q, k, v,
                                         ROWS, 3*CC, CC, CC);
    attn_tc_kernel<<<dim3(TT / 64, NH, BB), 128>>>(q, k, v, y);
    gemm_tc<1><<<gC, 256, GEMM_SMEM>>>(y, wo, bo, x, x1, x1, x1,
                                       ROWS, CC, CC, CC);
    ln_kernel<<<ROWS, 256>>>(x1, ln2_g, ln2_b, h);
    gemm_tc<2><<<gF, 256, GEMM_SMEM>>>(h, w1, b1, nullptr, m, m, m,
                                       ROWS, FF, CC, FF);
    gemm_tc<1><<<gC, 256, GEMM_SMEM>>>(m, w2, b2, x1, out, out, out,
                                       ROWS, CC, FF, CC);
}

// round 13
// speedup vs baseline: 1.3407x; 1.0667x over previous
#include <cuda_runtime.h>
#include <cuda_bf16.h>
#include <math.h>
#include <stdint.h>

// Problem constants
#define BB   4
#define TT   2048
#define CC   1024
#define NH   16
#define DH   64
#define ROWS (BB * TT)        // 8192
#define FF   (4 * CC)         // 4096

// ---------------- scratch (no allocs allowed) ----------------
__device__ float g_h [ROWS * CC];
__device__ float g_q [ROWS * CC];
__device__ float g_k [ROWS * CC];
__device__ float g_v [ROWS * CC];
__device__ float g_y [ROWS * CC];
__device__ float g_x1[ROWS * CC];
__device__ float g_m [ROWS * FF];
// rna-rounded weight copies
__device__ float g_wqkv[CC * 3 * CC];   // [K=1024][N=3072] (Wq|Wk|Wv)
__device__ float g_bqkv[3 * CC];
__device__ float g_wo  [CC * CC];
__device__ float g_w1  [CC * FF];
__device__ float g_w2  [FF * CC];

// ---------------- common helpers ----------------
__device__ __forceinline__ float gelu_exact(float x) {
    return 0.5f * x * (1.0f + erff(x * 0.70710678118654752f));
}

__device__ __forceinline__ float cvt_tf32(float x) {
    uint32_t r;
    asm("cvt.rna.tf32.f32 %0, %1;" : "=r"(r) : "f"(x));
    return __uint_as_float(r);
}

__device__ __forceinline__ void mma_tf32(float& d0, float& d1, float& d2, float& d3,
                                         uint32_t a0, uint32_t a1, uint32_t a2, uint32_t a3,
                                         uint32_t b0, uint32_t b1) {
    asm volatile(
        "mma.sync.aligned.m16n8k8.row.col.f32.tf32.tf32.f32 "
        "{%0,%1,%2,%3}, {%4,%5,%6,%7}, {%8,%9}, {%0,%1,%2,%3};"
        : "+f"(d0), "+f"(d1), "+f"(d2), "+f"(d3)
        : "r"(a0), "r"(a1), "r"(a2), "r"(a3), "r"(b0), "r"(b1));
}

#define CP_ASYNC16(dst, src) \
    asm volatile("cp.async.cg.shared.global [%0], [%1], 16;\n" :: "r"(dst), "l"(src))
#define CP_COMMIT() asm volatile("cp.async.commit_group;\n" ::: "memory")

// ---------------- weight prep (4 launches total) ----------------
// prep_qkv: one Wx -> wqkv column block (rounded) + its bias (raw copy)
__global__ void prep_qkv(const float* __restrict__ W, float* __restrict__ dst, int coloff,
                         const float* __restrict__ bsrc, float* __restrict__ bdst) {
    int k = blockIdx.y;                 // 0..1023
    int n = threadIdx.x * 4;            // 0..1020
    float4 v = *(const float4*)(W + (size_t)k * CC + n);
    v.x = cvt_tf32(v.x); v.y = cvt_tf32(v.y);
    v.z = cvt_tf32(v.z); v.w = cvt_tf32(v.w);
    *(float4*)(dst + (size_t)k * (3 * CC) + coloff + n) = v;
    if (k == 0) {
        float4 bv = *(const float4*)(bsrc + n);
        *(float4*)(bdst + n) = bv;
    }
}

// prep_rest: Wo, W1, W2 rounded copies in one kernel
__global__ void prep_rest(const float* __restrict__ wo_s, float* __restrict__ wo_d,
                          const float* __restrict__ w1_s, float* __restrict__ w1_d,
                          const float* __restrict__ w2_s, float* __restrict__ w2_d) {
    size_t i = ((size_t)blockIdx.x * 256 + threadIdx.x) * 4;
    const size_t n0 = (size_t)CC * CC;          // 1M
    const size_t n1 = n0 + (size_t)CC * FF;     // 5M
    const float* s; float* d; size_t off;
    if (i < n0)      { s = wo_s; d = wo_d; off = i; }
    else if (i < n1) { s = w1_s; d = w1_d; off = i - n0; }
    else             { s = w2_s; d = w2_d; off = i - n1; }
    float4 v = *(const float4*)(s + off);
    v.x = cvt_tf32(v.x); v.y = cvt_tf32(v.y);
    v.z = cvt_tf32(v.z); v.w = cvt_tf32(v.w);
    *(float4*)(d + off) = v;
}

// ---------------- LayerNorm: one block per row (rna-rounded out) --------------
__global__ void ln_kernel(const float* __restrict__ X,
                          const float* __restrict__ gam,
                          const float* __restrict__ bet,
                          float* __restrict__ out) {
    int row = blockIdx.x;
    int tid = threadIdx.x;
    const float4* x4 = (const float4*)(X + (size_t)row * CC);
    float4 v = x4[tid];
    float s  = v.x + v.y + v.z + v.w;
    float ss = v.x*v.x + v.y*v.y + v.z*v.z + v.w*v.w;
    #pragma unroll
    for (int off = 16; off > 0; off >>= 1) {
        s  += __shfl_down_sync(0xffffffffu, s,  off);
        ss += __shfl_down_sync(0xffffffffu, ss, off);
    }
    __shared__ float smS[8], smQ[8];
    __shared__ float sh_mu, sh_rstd;
    int lane = tid & 31, w = tid >> 5;
    if (lane == 0) { smS[w] = s; smQ[w] = ss; }
    __syncthreads();
    if (tid == 0) {
        float ts = 0.f, tq = 0.f;
        #pragma unroll
        for (int i = 0; i < 8; i++) { ts += smS[i]; tq += smQ[i]; }
        float mu  = ts * (1.0f / CC);
        float var = tq * (1.0f / CC) - mu * mu;
        sh_mu = mu;
        sh_rstd = rsqrtf(var + 1e-5f);
    }
    __syncthreads();
    float mu = sh_mu, rstd = sh_rstd;
    float4 gv = ((const float4*)gam)[tid];
    float4 bv = ((const float4*)bet)[tid];
    float4 o;
    o.x = cvt_tf32((v.x - mu) * rstd * gv.x + bv.x);
    o.y = cvt_tf32((v.y - mu) * rstd * gv.y + bv.y);
    o.z = cvt_tf32((v.z - mu) * rstd * gv.z + bv.z);
    o.w = cvt_tf32((v.w - mu) * rstd * gv.w + bv.w);
    ((float4*)(out + (size_t)row * CC))[tid] = o;
}

// ---------------- TF32 HMMA GEMM: 16-k stages, 5-stage ring, 2 stages/barrier --
// EPI: 0 = bias + rna-round (QKV), 1 = bias + residual, 2 = bias + GELU + round
#define AST 20
#define WST 132
#define GST 5
#define STG_FLOATS (128 * AST + 16 * WST)   // 4672 floats = 18688 B
#define STG_BYTES  (STG_FLOATS * 4)
#define GEMM_SMEM  (GST * STG_BYTES)        // 93440 B

template <int EPI>
__global__ __launch_bounds__(256, 2)
void gemm_tc(const float* __restrict__ A, const float* __restrict__ W,
             const float* __restrict__ bias, const float* __restrict__ res,
             float* __restrict__ C0, float* __restrict__ C1, float* __restrict__ C2,
             int M, int N, int K, int outN) {
    extern __shared__ __align__(16) float dsm[];

    int tid  = threadIdx.x;
    int lane = tid & 31;
    int wid  = tid >> 5;
    int warp_m = wid >> 2;
    int warp_n = wid & 3;
    int g = lane >> 2, t = lane & 3;
    int bm = blockIdx.y * 128;
    int bn = blockIdx.x * 128;

    int bi = bn / outN;
    float* C = (bi == 0) ? C0 : ((bi == 1) ? C1 : C2);
    int cn = bn - bi * outN;

    int am  = tid >> 2;             // 0..63: rows am, am+64
    int akq = (tid & 3) * 4;        // 0,4,8,12
    int wk  = tid >> 5;             // 0..7: rows wk, wk+8
    int wn4 = (tid & 31) * 4;

    const float* Apb = A + (size_t)(bm + am) * K + akq;
    const float* Wpb = W + (size_t)wk * N + bn + wn4;

    uint32_t bA0 = (uint32_t)__cvta_generic_to_shared(dsm + am * AST + akq);
    uint32_t bA1 = (uint32_t)__cvta_generic_to_shared(dsm + (am + 64) * AST + akq);
    uint32_t bW0 = (uint32_t)__cvta_generic_to_shared(dsm + 128 * AST + wk * WST + wn4);
    uint32_t bW1 = (uint32_t)__cvta_generic_to_shared(dsm + 128 * AST + (wk + 8) * WST + wn4);

    float acc[4][4][4];
    #pragma unroll
    for (int i = 0; i < 4; i++)
        #pragma unroll
        for (int j = 0; j < 4; j++)
            #pragma unroll
            for (int r = 0; r < 4; r++) acc[i][j][r] = 0.f;

    int NT = K >> 4;

    #pragma unroll
    for (int s = 0; s < 3; s++) {
        uint32_t so = (uint32_t)s * STG_BYTES;
        int k0 = s << 4;
        CP_ASYNC16(bA0 + so, Apb + k0);
        CP_ASYNC16(bA1 + so, Apb + (size_t)64 * K + k0);
        CP_ASYNC16(bW0 + so, Wpb + (size_t)k0 * N);
        CP_ASYNC16(bW1 + so, Wpb + (size_t)(k0 + 8) * N);
        CP_COMMIT();
    }

    for (int kt = 0; kt < NT; kt += 2) {
        asm volatile("cp.async.wait_group 1;" ::: "memory");
        __syncthreads();

        #pragma unroll
        for (int d = 3; d <= 4; d++) {
            int ks = kt + d;
            if (ks < NT) {
                uint32_t so = (uint32_t)(ks % GST) * STG_BYTES;
                int k0 = ks << 4;
                CP_ASYNC16(bA0 + so, Apb + k0);
                CP_ASYNC16(bA1 + so, Apb + (size_t)64 * K + k0);
                CP_ASYNC16(bW0 + so, Wpb + (size_t)k0 * N);
                CP_ASYNC16(bW1 + so, Wpb + (size_t)(k0 + 8) * N);
            }
            CP_COMMIT();
        }

        #pragma unroll
        for (int d = 0; d < 2; d++) {
            int st = (kt + d) % GST;
            float* base = dsm + st * STG_FLOATS;
            float (*As)[AST] = (float(*)[AST])base;
            float (*Ws)[WST] = (float(*)[WST])(base + 128 * AST);

            #pragma unroll
            for (int kc = 0; kc < 2; kc++) {
                int kr = kc * 8 + t;
                uint32_t af[4][4];
                uint32_t bf[4][2];
                #pragma unroll
                for (int mtl = 0; mtl < 4; mtl++) {
                    int m = warp_m * 64 + mtl * 16 + g;
                    af[mtl][0] = __float_as_uint(As[m    ][kr    ]);
                    af[mtl][1] = __float_as_uint(As[m + 8][kr    ]);
                    af[mtl][2] = __float_as_uint(As[m    ][kr + 4]);
                    af[mtl][3] = __float_as_uint(As[m + 8][kr + 4]);
                }
                #pragma unroll
                for (int ntl = 0; ntl < 4; ntl++) {
                    int n = warp_n * 32 + ntl * 8 + g;
                    bf[ntl][0] = __float_as_uint(Ws[kr    ][n]);
                    bf[ntl][1] = __float_as_uint(Ws[kr + 4][n]);
                }
                #pragma unroll
                for (int mtl = 0; mtl < 4; mtl++)
                    #pragma unroll
                    for (int ntl = 0; ntl < 4; ntl++)
                        mma_tf32(acc[mtl][ntl][0], acc[mtl][ntl][1],
                                 acc[mtl][ntl][2], acc[mtl][ntl][3],
                                 af[mtl][0], af[mtl][1], af[mtl][2], af[mtl][3],
                                 bf[ntl][0], bf[ntl][1]);
            }
        }
    }

    // ---- epilogue ----
    #pragma unroll
    for (int mt = 0; mt < 4; mt++) {
        int r0 = bm + warp_m * 64 + mt * 16 + g;
        #pragma unroll
        for (int nt = 0; nt < 4; nt++) {
            int gcol = bn + warp_n * 32 + nt * 8 + t * 2;
            int col  = cn + warp_n * 32 + nt * 8 + t * 2;
            float b0 = bias[gcol], b1 = bias[gcol + 1];
            #pragma unroll
            for (int h = 0; h < 2; h++) {
                int row = r0 + h * 8;
                float v0 = acc[mt][nt][h * 2 + 0] + b0;
                float v1 = acc[mt][nt][h * 2 + 1] + b1;
                if (EPI == 0) {       // QKV: pre-round for attention
                    v0 = cvt_tf32(v0);
                    v1 = cvt_tf32(v1);
                }
                if (EPI == 1) {
                    const float* rp = res + (size_t)row * outN + col;
                    v0 += rp[0]; v1 += rp[1];
                }
                if (EPI == 2) {
                    v0 = cvt_tf32(gelu_exact(v0));
                    v1 = cvt_tf32(gelu_exact(v1));
                }
                *(float2*)(C + (size_t)row * outN + col) = make_float2(v0, v1);
            }
        }
    }
}

// ---------------- Tensor-core flash attention (causal, tf32) ----------------
// K/V (pre-rounded by QKV epilogue) streamed via cp.async double buffering.
#define KS_STR 68
#define VS_STR 72
#define ATT_K_FLOATS (64 * KS_STR)               // 4352
#define ATT_V_FLOATS (64 * VS_STR)               // 4608
#define ATT_SMEM ((2 * ATT_K_FLOATS + 2 * ATT_V_FLOATS) * 4)   // 71680 B

__global__ __launch_bounds__(128)
void attn_tc_kernel(const float* __restrict__ Q,
                    const float* __restrict__ K,
                    const float* __restrict__ V,
                    float* __restrict__ Y) {
    extern __shared__ __align__(16) float dsm[];
    float (*Ks)[64][KS_STR] = (float(*)[64][KS_STR])dsm;                       // 2 bufs (also P)
    float (*Vs)[64][VS_STR] = (float(*)[64][VS_STR])(dsm + 2 * ATT_K_FLOATS);  // 2 bufs

    int qt = blockIdx.x, h = blockIdx.y, b = blockIdx.z;
    int tid = threadIdx.x;
    int lane = tid & 31, w = tid >> 5;
    int g = lane >> 2, t = lane & 3;
    int qbase = qt * 64;
    const int hoff = h * DH;

    int lrow = tid >> 1;            // staging row 0..63
    int ld0  = (tid & 1) * 32;      // staging col 0/32

    uint32_t ksm[2], vsm[2];
    #pragma unroll
    for (int s = 0; s < 2; s++) {
        ksm[s] = (uint32_t)__cvta_generic_to_shared(&Ks[s][lrow][ld0]);
        vsm[s] = (uint32_t)__cvta_generic_to_shared(&Vs[s][lrow][ld0]);
    }

    // ---- issue tile 0 loads ----
    {
        const float* kp = K + (size_t)(b * TT + lrow) * CC + hoff + ld0;
        const float* vp = V + (size_t)(b * TT + lrow) * CC + hoff + ld0;
        #pragma unroll
        for (int i = 0; i < 8; i++) {
            CP_ASYNC16(ksm[0] + i * 16, kp + i * 4);
            CP_ASYNC16(vsm[0] + i * 16, vp + i * 4);
        }
        CP_COMMIT();
    }

    // ---- stage Q (x 1/8, exact) into Vs[1]; extract fragments ----
    {
        const float* qp = Q + (size_t)(b * TT + qbase + lrow) * CC + hoff + ld0;
        #pragma unroll
        for (int i = 0; i < 8; i++) {
            float4 v4 = ((const float4*)qp)[i];
            Vs[1][lrow][ld0 + 4*i + 0] = v4.x * 0.125f;
            Vs[1][lrow][ld0 + 4*i + 1] = v4.y * 0.125f;
            Vs[1][lrow][ld0 + 4*i + 2] = v4.z * 0.125f;
            Vs[1][lrow][ld0 + 4*i + 3] = v4.w * 0.125f;
        }
    }
    __syncthreads();
    uint32_t qf[8][4];
    {
        int rA = 16 * w + g;
        #pragma unroll
        for (int kc = 0; kc < 8; kc++) {
            qf[kc][0] = __float_as_uint(Vs[1][rA    ][kc*8 + t    ]);
            qf[kc][1] = __float_as_uint(Vs[1][rA + 8][kc*8 + t    ]);
            qf[kc][2] = __float_as_uint(Vs[1][rA    ][kc*8 + t + 4]);
            qf[kc][3] = __float_as_uint(Vs[1][rA + 8][kc*8 + t + 4]);
        }
    }

    float o[8][4];
    #pragma unroll
    for (int nt = 0; nt < 8; nt++)
        #pragma unroll
        for (int j = 0; j < 4; j++) o[nt][j] = 0.f;
    float mA = -1e30f, mB = -1e30f, lA = 0.f, lB = 0.f;

    int rA = 16 * w + g;
    int rB = rA + 8;

    for (int kt = 0; kt <= qt; kt++) {
        int c = kt & 1;
        asm volatile("cp.async.wait_group 0;" ::: "memory");
        __syncthreads();   // tile kt landed; prior-tile P/V reads done; qf extraction done

        // issue tile kt+1 into the other buffer (flies during compute)
        if (kt < qt) {
            const float* kp = K + (size_t)(b * TT + (kt+1) * 64 + lrow) * CC + hoff + ld0;
            const float* vp = V + (size_t)(b * TT + (kt+1) * 64 + lrow) * CC + hoff + ld0;
            #pragma unroll
            for (int i = 0; i < 8; i++) {
                CP_ASYNC16(ksm[1 - c] + i * 16, kp + i * 4);
                CP_ASYNC16(vsm[1 - c] + i * 16, vp + i * 4);
            }
            CP_COMMIT();
        }

        // ---- S = Q K^T ----
        float s[8][4];
        #pragma unroll
        for (int nt = 0; nt < 8; nt++)
            #pragma unroll
            for (int j = 0; j < 4; j++) s[nt][j] = 0.f;
        #pragma unroll
        for (int kc = 0; kc < 8; kc++) {
            #pragma unroll
            for (int nt = 0; nt < 8; nt++) {
                uint32_t b0 = __float_as_uint(Ks[c][nt*8 + g][kc*8 + t    ]);
                uint32_t b1 = __float_as_uint(Ks[c][nt*8 + g][kc*8 + t + 4]);
                mma_tf32(s[nt][0], s[nt][1], s[nt][2], s[nt][3],
                         qf[kc][0], qf[kc][1], qf[kc][2], qf[kc][3], b0, b1);
            }
        }

        if (kt == qt) {
            #pragma unroll
            for (int nt = 0; nt < 8; nt++) {
                int c0 = nt * 8 + 2 * t;
                if (c0     > rA) s[nt][0] = -1e30f;
                if (c0 + 1 > rA) s[nt][1] = -1e30f;
                if (c0     > rB) s[nt][2] = -1e30f;
                if (c0 + 1 > rB) s[nt][3] = -1e30f;
            }
        }

        float mxA = -1e30f, mxB = -1e30f;
        #pragma unroll
        for (int nt = 0; nt < 8; nt++) {
            mxA = fmaxf(mxA, fmaxf(s[nt][0], s[nt][1]));
            mxB = fmaxf(mxB, fmaxf(s[nt][2], s[nt][3]));
        }
        mxA = fmaxf(mxA, __shfl_xor_sync(0xffffffffu, mxA, 1));
        mxA = fmaxf(mxA, __shfl_xor_sync(0xffffffffu, mxA, 2));
        mxB = fmaxf(mxB, __shfl_xor_sync(0xffffffffu, mxB, 1));
        mxB = fmaxf(mxB, __shfl_xor_sync(0xffffffffu, mxB, 2));
        float mnA = fmaxf(mA, mxA);
        float mnB = fmaxf(mB, mxB);
        float corrA = __expf(mA - mnA);
        float corrB = __expf(mB - mnB);

        float sumA = 0.f, sumB = 0.f;
        #pragma unroll
        for (int nt = 0; nt < 8; nt++) {
            s[nt][0] = __expf(s[nt][0] - mnA); sumA += s[nt][0];
            s[nt][1] = __expf(s[nt][1] - mnA); sumA += s[nt][1];
            s[nt][2] = __expf(s[nt][2] - mnB); sumB += s[nt][2];
            s[nt][3] = __expf(s[nt][3] - mnB); sumB += s[nt][3];
        }
        sumA += __shfl_xor_sync(0xffffffffu, sumA, 1);
        sumA += __shfl_xor_sync(0xffffffffu, sumA, 2);
        sumB += __shfl_xor_sync(0xffffffffu, sumB, 1);
        sumB += __shfl_xor_sync(0xffffffffu, sumB, 2);
        lA = lA * corrA + sumA;
        lB = lB * corrB + sumB;
        mA = mnA; mB = mnB;

        #pragma unroll
        for (int nt = 0; nt < 8; nt++) {
            o[nt][0] *= corrA; o[nt][1] *= corrA;
            o[nt][2] *= corrB; o[nt][3] *= corrB;
        }

        __syncthreads();   // all warps done reading Ks[c] (S mma)
        // ---- write P into Ks[c] (rna) ----
        #pragma unroll
        for (int nt = 0; nt < 8; nt++) {
            int c0 = nt * 8 + 2 * t;
            Ks[c][rA][c0    ] = cvt_tf32(s[nt][0]);
            Ks[c][rA][c0 + 1] = cvt_tf32(s[nt][1]);
            Ks[c][rB][c0    ] = cvt_tf32(s[nt][2]);
            Ks[c][rB][c0 + 1] = cvt_tf32(s[nt][3]);
        }
        __syncwarp();      // P rows for this warp are warp-private

        // ---- O += P V ----
        #pragma unroll
        for (int kc = 0; kc < 8; kc++) {
            uint32_t a0 = __float_as_uint(Ks[c][rA][kc*8 + t    ]);
            uint32_t a1 = __float_as_uint(Ks[c][rB][kc*8 + t    ]);
            uint32_t a2 = __float_as_uint(Ks[c][rA][kc*8 + t + 4]);
            uint32_t a3 = __float_as_uint(Ks[c][rB][kc*8 + t + 4]);
            #pragma unroll
            for (int nt = 0; nt < 8; nt++) {
                uint32_t b0 = __float_as_uint(Vs[c][kc*8 + t    ][nt*8 + g]);
                uint32_t b1 = __float_as_uint(Vs[c][kc*8 + t + 4][nt*8 + g]);
                mma_tf32(o[nt][0], o[nt][1], o[nt][2], o[nt][3],
                         a0, a1, a2, a3, b0, b1);
            }
        }
        // no trailing sync: next iter's wait+sync orders buffer reuse
    }

    // epilogue: rna-rounded y (feeds proj GEMM A operand)
    float invA = 1.0f / lA, invB = 1.0f / lB;
    int rowA = qbase + rA;
    float* yA = Y + (size_t)(b * TT + rowA) * CC + hoff;
    float* yB = Y + (size_t)(b * TT + rowA + 8) * CC + hoff;
    #pragma unroll
    for (int nt = 0; nt < 8; nt++) {
        int c0 = nt * 8 + 2 * t;
        *(float2*)(yA + c0) = make_float2(cvt_tf32(o[nt][0] * invA), cvt_tf32(o[nt][1] * invA));
        *(float2*)(yB + c0) = make_float2(cvt_tf32(o[nt][2] * invB), cvt_tf32(o[nt][3] * invB));
    }
}

// ---------------- launcher ----------------
extern "C" void kernel_launch(void* const* d_in, const int* in_sizes, int n_in,
                              void* d_out, int out_size) {
    const float* x     = (const float*)d_in[0];
    const float* ln1_g = (const float*)d_in[1];
    const float* ln1_b = (const float*)d_in[2];
    const float* Wq    = (const float*)d_in[3];
    const float* bq    = (const float*)d_in[4];
    const float* Wk    = (const float*)d_in[5];
    const float* bk    = (const float*)d_in[6];
    const float* Wv    = (const float*)d_in[7];
    const float* bv    = (const float*)d_in[8];
    const float* Wo    = (const float*)d_in[9];
    const float* bo    = (const float*)d_in[10];
    const float* ln2_g = (const float*)d_in[11];
    const float* ln2_b = (const float*)d_in[12];
    const float* W1    = (const float*)d_in[13];
    const float* b1    = (const float*)d_in[14];
    const float* W2    = (const float*)d_in[15];
    const float* b2    = (const float*)d_in[16];
    float* out = (float*)d_out;

    float *h, *q, *k, *v, *y, *x1, *m;
    float *wqkv, *bqkv, *wo, *w1, *w2;
    cudaGetSymbolAddress((void**)&h,    g_h);
    cudaGetSymbolAddress((void**)&q,    g_q);
    cudaGetSymbolAddress((void**)&k,    g_k);
    cudaGetSymbolAddress((void**)&v,    g_v);
    cudaGetSymbolAddress((void**)&y,    g_y);
    cudaGetSymbolAddress((void**)&x1,   g_x1);
    cudaGetSymbolAddress((void**)&m,    g_m);
    cudaGetSymbolAddress((void**)&wqkv, g_wqkv);
    cudaGetSymbolAddress((void**)&bqkv, g_bqkv);
    cudaGetSymbolAddress((void**)&wo,   g_wo);
    cudaGetSymbolAddress((void**)&w1,   g_w1);
    cudaGetSymbolAddress((void**)&w2,   g_w2);

    cudaFuncSetAttribute(gemm_tc<0>, cudaFuncAttributeMaxDynamicSharedMemorySize, GEMM_SMEM);
    cudaFuncSetAttribute(gemm_tc<1>, cudaFuncAttributeMaxDynamicSharedMemorySize, GEMM_SMEM);
    cudaFuncSetAttribute(gemm_tc<2>, cudaFuncAttributeMaxDynamicSharedMemorySize, GEMM_SMEM);
    cudaFuncSetAttribute(attn_tc_kernel, cudaFuncAttributeMaxDynamicSharedMemorySize, ATT_SMEM);

    // 0) weight prep — exactly 4 launches (so launch #5 is the QKV GEMM for ncu)
    prep_qkv<<<dim3(1, CC), 256>>>(Wq, wqkv, 0,      bq, bqkv);
    prep_qkv<<<dim3(1, CC), 256>>>(Wk, wqkv, CC,     bk, bqkv + CC);
    prep_qkv<<<dim3(1, CC), 256>>>(Wv, wqkv, 2 * CC, bv, bqkv + 2 * CC);
    prep_rest<<<(9 * 1024 * 1024) / (256 * 4), 256>>>(Wo, wo, W1, w1, W2, w2);

    dim3 gQKV(3*CC / 128, ROWS / 128);
    dim3 gC(CC / 128, ROWS / 128);
    dim3 gF(FF / 128, ROWS / 128);

    ln_kernel<<<ROWS, 256>>>(x, ln1_g, ln1_b, h);                       // launch 4
    gemm_tc<0><<<gQKV, 256, GEMM_SMEM>>>(h, wqkv, bqkv, nullptr, q, k, v,
                                         ROWS, 3*CC, CC, CC);           // launch 5 (profiled)
    attn_tc_kernel<<<dim3(TT / 64, NH, BB), 128, ATT_SMEM>>>(q, k, v, y);
    gemm_tc<1><<<gC, 256, GEMM_SMEM>>>(y, wo, bo, x, x1, x1, x1,
                                       ROWS, CC, CC, CC);
    ln_kernel<<<ROWS, 256>>>(x1, ln2_g, ln2_b, h);
    gemm_tc<2><<<gF, 256, GEMM_SMEM>>>(h, w1, b1, nullptr, m, m, m,
                                       ROWS, FF, CC, FF);
    gemm_tc<1><<<gC, 256, GEMM_SMEM>>>(m, w2, b2, x1, out, out, out,
                                       ROWS, CC, FF, CC);
}

// round 14
// speedup vs baseline: 1.3409x; 1.0001x over previous
#include <cuda_runtime.h>
#include <cuda_bf16.h>
#include <math.h>
#include <stdint.h>

// Problem constants
#define BB   4
#define TT   2048
#define CC   1024
#define NH   16
#define DH   64
#define ROWS (BB * TT)        // 8192
#define FF   (4 * CC)         // 4096

// ---------------- scratch (no allocs allowed) ----------------
__device__ float g_h [ROWS * CC];
__device__ float g_q [ROWS * CC];
__device__ float g_k [ROWS * CC];
__device__ float g_v [ROWS * CC];
__device__ float g_y [ROWS * CC];
__device__ float g_x1[ROWS * CC];
__device__ float g_m [ROWS * FF];
// rna-rounded weight copies
__device__ float g_wqkv[CC * 3 * CC];   // [K=1024][N=3072] (Wq|Wk|Wv)
__device__ float g_bqkv[3 * CC];
__device__ float g_wo  [CC * CC];
__device__ float g_w1  [CC * FF];
__device__ float g_w2  [FF * CC];

// ---------------- common helpers ----------------
__device__ __forceinline__ float gelu_exact(float x) {
    return 0.5f * x * (1.0f + erff(x * 0.70710678118654752f));
}

__device__ __forceinline__ float cvt_tf32(float x) {
    uint32_t r;
    asm("cvt.rna.tf32.f32 %0, %1;" : "=r"(r) : "f"(x));
    return __uint_as_float(r);
}

__device__ __forceinline__ void mma_tf32(float& d0, float& d1, float& d2, float& d3,
                                         uint32_t a0, uint32_t a1, uint32_t a2, uint32_t a3,
                                         uint32_t b0, uint32_t b1) {
    asm volatile(
        "mma.sync.aligned.m16n8k8.row.col.f32.tf32.tf32.f32 "
        "{%0,%1,%2,%3}, {%4,%5,%6,%7}, {%8,%9}, {%0,%1,%2,%3};"
        : "+f"(d0), "+f"(d1), "+f"(d2), "+f"(d3)
        : "r"(a0), "r"(a1), "r"(a2), "r"(a3), "r"(b0), "r"(b1));
}

#define CP_ASYNC16(dst, src) \
    asm volatile("cp.async.cg.shared.global [%0], [%1], 16;\n" :: "r"(dst), "l"(src))
#define CP_COMMIT() asm volatile("cp.async.commit_group;\n" ::: "memory")

// ---------------- weight prep (4 launches total) ----------------
// prep_qkv: one Wx -> wqkv column block (rounded) + its bias (raw copy)
__global__ void prep_qkv(const float* __restrict__ W, float* __restrict__ dst, int coloff,
                         const float* __restrict__ bsrc, float* __restrict__ bdst) {
    int k = blockIdx.y;                 // 0..1023
    int n = threadIdx.x * 4;            // 0..1020
    float4 v = *(const float4*)(W + (size_t)k * CC + n);
    v.x = cvt_tf32(v.x); v.y = cvt_tf32(v.y);
    v.z = cvt_tf32(v.z); v.w = cvt_tf32(v.w);
    *(float4*)(dst + (size_t)k * (3 * CC) + coloff + n) = v;
    if (k == 0) {
        float4 bv = *(const float4*)(bsrc + n);
        *(float4*)(bdst + n) = bv;
    }
}

// prep_rest: Wo, W1, W2 rounded copies in one kernel
__global__ void prep_rest(const float* __restrict__ wo_s, float* __restrict__ wo_d,
                          const float* __restrict__ w1_s, float* __restrict__ w1_d,
                          const float* __restrict__ w2_s, float* __restrict__ w2_d) {
    size_t i = ((size_t)blockIdx.x * 256 + threadIdx.x) * 4;
    const size_t n0 = (size_t)CC * CC;          // 1M
    const size_t n1 = n0 + (size_t)CC * FF;     // 5M
    const float* s; float* d; size_t off;
    if (i < n0)      { s = wo_s; d = wo_d; off = i; }
    else if (i < n1) { s = w1_s; d = w1_d; off = i - n0; }
    else             { s = w2_s; d = w2_d; off = i - n1; }
    float4 v = *(const float4*)(s + off);
    v.x = cvt_tf32(v.x); v.y = cvt_tf32(v.y);
    v.z = cvt_tf32(v.z); v.w = cvt_tf32(v.w);
    *(float4*)(d + off) = v;
}

// ---------------- LayerNorm: one block per row (rna-rounded out) --------------
__global__ void ln_kernel(const float* __restrict__ X,
                          const float* __restrict__ gam,
                          const float* __restrict__ bet,
                          float* __restrict__ out) {
    int row = blockIdx.x;
    int tid = threadIdx.x;
    const float4* x4 = (const float4*)(X + (size_t)row * CC);
    float4 v = x4[tid];
    float s  = v.x + v.y + v.z + v.w;
    float ss = v.x*v.x + v.y*v.y + v.z*v.z + v.w*v.w;
    #pragma unroll
    for (int off = 16; off > 0; off >>= 1) {
        s  += __shfl_down_sync(0xffffffffu, s,  off);
        ss += __shfl_down_sync(0xffffffffu, ss, off);
    }
    __shared__ float smS[8], smQ[8];
    __shared__ float sh_mu, sh_rstd;
    int lane = tid & 31, w = tid >> 5;
    if (lane == 0) { smS[w] = s; smQ[w] = ss; }
    __syncthreads();
    if (tid == 0) {
        float ts = 0.f, tq = 0.f;
        #pragma unroll
        for (int i = 0; i < 8; i++) { ts += smS[i]; tq += smQ[i]; }
        float mu  = ts * (1.0f / CC);
        float var = tq * (1.0f / CC) - mu * mu;
        sh_mu = mu;
        sh_rstd = rsqrtf(var + 1e-5f);
    }
    __syncthreads();
    float mu = sh_mu, rstd = sh_rstd;
    float4 gv = ((const float4*)gam)[tid];
    float4 bv = ((const float4*)bet)[tid];
    float4 o;
    o.x = cvt_tf32((v.x - mu) * rstd * gv.x + bv.x);
    o.y = cvt_tf32((v.y - mu) * rstd * gv.y + bv.y);
    o.z = cvt_tf32((v.z - mu) * rstd * gv.z + bv.z);
    o.w = cvt_tf32((v.w - mu) * rstd * gv.w + bv.w);
    ((float4*)(out + (size_t)row * CC))[tid] = o;
}

// ---------------- TF32 HMMA GEMM: 16-k stages, 5-stage ring, 2 stages/barrier --
// EPI: 0 = bias + rna-round (QKV), 1 = bias + residual, 2 = bias + GELU + round
#define AST 20
#define WST 132
#define GST 5
#define STG_FLOATS (128 * AST + 16 * WST)   // 4672 floats = 18688 B
#define STG_BYTES  (STG_FLOATS * 4)
#define GEMM_SMEM  (GST * STG_BYTES)        // 93440 B

template <int EPI>
__global__ __launch_bounds__(256, 2)
void gemm_tc(const float* __restrict__ A, const float* __restrict__ W,
             const float* __restrict__ bias, const float* __restrict__ res,
             float* __restrict__ C0, float* __restrict__ C1, float* __restrict__ C2,
             int M, int N, int K, int outN) {
    extern __shared__ __align__(16) float dsm[];

    int tid  = threadIdx.x;
    int lane = tid & 31;
    int wid  = tid >> 5;
    int warp_m = wid >> 2;
    int warp_n = wid & 3;
    int g = lane >> 2, t = lane & 3;
    int bm = blockIdx.y * 128;
    int bn = blockIdx.x * 128;

    int bi = bn / outN;
    float* C = (bi == 0) ? C0 : ((bi == 1) ? C1 : C2);
    int cn = bn - bi * outN;

    int am  = tid >> 2;             // 0..63: rows am, am+64
    int akq = (tid & 3) * 4;        // 0,4,8,12
    int wk  = tid >> 5;             // 0..7: rows wk, wk+8
    int wn4 = (tid & 31) * 4;

    const float* Apb = A + (size_t)(bm + am) * K + akq;
    const float* Wpb = W + (size_t)wk * N + bn + wn4;

    uint32_t bA0 = (uint32_t)__cvta_generic_to_shared(dsm + am * AST + akq);
    uint32_t bA1 = (uint32_t)__cvta_generic_to_shared(dsm + (am + 64) * AST + akq);
    uint32_t bW0 = (uint32_t)__cvta_generic_to_shared(dsm + 128 * AST + wk * WST + wn4);
    uint32_t bW1 = (uint32_t)__cvta_generic_to_shared(dsm + 128 * AST + (wk + 8) * WST + wn4);

    float acc[4][4][4];
    #pragma unroll
    for (int i = 0; i < 4; i++)
        #pragma unroll
        for (int j = 0; j < 4; j++)
            #pragma unroll
            for (int r = 0; r < 4; r++) acc[i][j][r] = 0.f;

    int NT = K >> 4;

    #pragma unroll
    for (int s = 0; s < 3; s++) {
        uint32_t so = (uint32_t)s * STG_BYTES;
        int k0 = s << 4;
        CP_ASYNC16(bA0 + so, Apb + k0);
        CP_ASYNC16(bA1 + so, Apb + (size_t)64 * K + k0);
        CP_ASYNC16(bW0 + so, Wpb + (size_t)k0 * N);
        CP_ASYNC16(bW1 + so, Wpb + (size_t)(k0 + 8) * N);
        CP_COMMIT();
    }

    for (int kt = 0; kt < NT; kt += 2) {
        asm volatile("cp.async.wait_group 1;" ::: "memory");
        __syncthreads();

        #pragma unroll
        for (int d = 3; d <= 4; d++) {
            int ks = kt + d;
            if (ks < NT) {
                uint32_t so = (uint32_t)(ks % GST) * STG_BYTES;
                int k0 = ks << 4;
                CP_ASYNC16(bA0 + so, Apb + k0);
                CP_ASYNC16(bA1 + so, Apb + (size_t)64 * K + k0);
                CP_ASYNC16(bW0 + so, Wpb + (size_t)k0 * N);
                CP_ASYNC16(bW1 + so, Wpb + (size_t)(k0 + 8) * N);
            }
            CP_COMMIT();
        }

        #pragma unroll
        for (int d = 0; d < 2; d++) {
            int st = (kt + d) % GST;
            float* base = dsm + st * STG_FLOATS;
            float (*As)[AST] = (float(*)[AST])base;
            float (*Ws)[WST] = (float(*)[WST])(base + 128 * AST);

            #pragma unroll
            for (int kc = 0; kc < 2; kc++) {
                int kr = kc * 8 + t;
                uint32_t af[4][4];
                uint32_t bf[4][2];
                #pragma unroll
                for (int mtl = 0; mtl < 4; mtl++) {
                    int m = warp_m * 64 + mtl * 16 + g;
                    af[mtl][0] = __float_as_uint(As[m    ][kr    ]);
                    af[mtl][1] = __float_as_uint(As[m + 8][kr    ]);
                    af[mtl][2] = __float_as_uint(As[m    ][kr + 4]);
                    af[mtl][3] = __float_as_uint(As[m + 8][kr + 4]);
                }
                #pragma unroll
                for (int ntl = 0; ntl < 4; ntl++) {
                    int n = warp_n * 32 + ntl * 8 + g;
                    bf[ntl][0] = __float_as_uint(Ws[kr    ][n]);
                    bf[ntl][1] = __float_as_uint(Ws[kr + 4][n]);
                }
                #pragma unroll
                for (int mtl = 0; mtl < 4; mtl++)
                    #pragma unroll
                    for (int ntl = 0; ntl < 4; ntl++)
                        mma_tf32(acc[mtl][ntl][0], acc[mtl][ntl][1],
                                 acc[mtl][ntl][2], acc[mtl][ntl][3],
                                 af[mtl][0], af[mtl][1], af[mtl][2], af[mtl][3],
                                 bf[ntl][0], bf[ntl][1]);
            }
        }
    }

    // ---- epilogue ----
    #pragma unroll
    for (int mt = 0; mt < 4; mt++) {
        int r0 = bm + warp_m * 64 + mt * 16 + g;
        #pragma unroll
        for (int nt = 0; nt < 4; nt++) {
            int gcol = bn + warp_n * 32 + nt * 8 + t * 2;
            int col  = cn + warp_n * 32 + nt * 8 + t * 2;
            float b0 = bias[gcol], b1 = bias[gcol + 1];
            #pragma unroll
            for (int h = 0; h < 2; h++) {
                int row = r0 + h * 8;
                float v0 = acc[mt][nt][h * 2 + 0] + b0;
                float v1 = acc[mt][nt][h * 2 + 1] + b1;
                if (EPI == 0) {       // QKV: pre-round for attention
                    v0 = cvt_tf32(v0);
                    v1 = cvt_tf32(v1);
                }
                if (EPI == 1) {
                    const float* rp = res + (size_t)row * outN + col;
                    v0 += rp[0]; v1 += rp[1];
                }
                if (EPI == 2) {
                    v0 = cvt_tf32(gelu_exact(v0));
                    v1 = cvt_tf32(gelu_exact(v1));
                }
                *(float2*)(C + (size_t)row * outN + col) = make_float2(v0, v1);
            }
        }
    }
}

// ---------------- Tensor-core flash attention (causal, tf32) ----------------
// K/V (pre-rounded by QKV epilogue) streamed via cp.async double buffering.
#define KS_STR 68
#define VS_STR 72
#define ATT_K_FLOATS (64 * KS_STR)               // 4352
#define ATT_V_FLOATS (64 * VS_STR)               // 4608
#define ATT_SMEM ((2 * ATT_K_FLOATS + 2 * ATT_V_FLOATS) * 4)   // 71680 B

__global__ __launch_bounds__(128)
void attn_tc_kernel(const float* __restrict__ Q,
                    const float* __restrict__ K,
                    const float* __restrict__ V,
                    float* __restrict__ Y) {
    extern __shared__ __align__(16) float dsm[];
    float (*Ks)[64][KS_STR] = (float(*)[64][KS_STR])dsm;                       // 2 bufs (also P)
    float (*Vs)[64][VS_STR] = (float(*)[64][VS_STR])(dsm + 2 * ATT_K_FLOATS);  // 2 bufs

    int qt = blockIdx.x, h = blockIdx.y, b = blockIdx.z;
    int tid = threadIdx.x;
    int lane = tid & 31, w = tid >> 5;
    int g = lane >> 2, t = lane & 3;
    int qbase = qt * 64;
    const int hoff = h * DH;

    int lrow = tid >> 1;            // staging row 0..63
    int ld0  = (tid & 1) * 32;      // staging col 0/32

    uint32_t ksm[2], vsm[2];
    #pragma unroll
    for (int s = 0; s < 2; s++) {
        ksm[s] = (uint32_t)__cvta_generic_to_shared(&Ks[s][lrow][ld0]);
        vsm[s] = (uint32_t)__cvta_generic_to_shared(&Vs[s][lrow][ld0]);
    }

    // ---- issue tile 0 loads ----
    {
        const float* kp = K + (size_t)(b * TT + lrow) * CC + hoff + ld0;
        const float* vp = V + (size_t)(b * TT + lrow) * CC + hoff + ld0;
        #pragma unroll
        for (int i = 0; i < 8; i++) {
            CP_ASYNC16(ksm[0] + i * 16, kp + i * 4);
            CP_ASYNC16(vsm[0] + i * 16, vp + i * 4);
        }
        CP_COMMIT();
    }

    // ---- stage Q (x 1/8, exact) into Vs[1]; extract fragments ----
    {
        const float* qp = Q + (size_t)(b * TT + qbase + lrow) * CC + hoff + ld0;
        #pragma unroll
        for (int i = 0; i < 8; i++) {
            float4 v4 = ((const float4*)qp)[i];
            Vs[1][lrow][ld0 + 4*i + 0] = v4.x * 0.125f;
            Vs[1][lrow][ld0 + 4*i + 1] = v4.y * 0.125f;
            Vs[1][lrow][ld0 + 4*i + 2] = v4.z * 0.125f;
            Vs[1][lrow][ld0 + 4*i + 3] = v4.w * 0.125f;
        }
    }
    __syncthreads();
    uint32_t qf[8][4];
    {
        int rA = 16 * w + g;
        #pragma unroll
        for (int kc = 0; kc < 8; kc++) {
            qf[kc][0] = __float_as_uint(Vs[1][rA    ][kc*8 + t    ]);
            qf[kc][1] = __float_as_uint(Vs[1][rA + 8][kc*8 + t    ]);
            qf[kc][2] = __float_as_uint(Vs[1][rA    ][kc*8 + t + 4]);
            qf[kc][3] = __float_as_uint(Vs[1][rA + 8][kc*8 + t + 4]);
        }
    }

    float o[8][4];
    #pragma unroll
    for (int nt = 0; nt < 8; nt++)
        #pragma unroll
        for (int j = 0; j < 4; j++) o[nt][j] = 0.f;
    float mA = -1e30f, mB = -1e30f, lA = 0.f, lB = 0.f;

    int rA = 16 * w + g;
    int rB = rA + 8;

    for (int kt = 0; kt <= qt; kt++) {
        int c = kt & 1;
        asm volatile("cp.async.wait_group 0;" ::: "memory");
        __syncthreads();   // tile kt landed; prior-tile P/V reads done; qf extraction done

        // issue tile kt+1 into the other buffer (flies during compute)
        if (kt < qt) {
            const float* kp = K + (size_t)(b * TT + (kt+1) * 64 + lrow) * CC + hoff + ld0;
            const float* vp = V + (size_t)(b * TT + (kt+1) * 64 + lrow) * CC + hoff + ld0;
            #pragma unroll
            for (int i = 0; i < 8; i++) {
                CP_ASYNC16(ksm[1 - c] + i * 16, kp + i * 4);
                CP_ASYNC16(vsm[1 - c] + i * 16, vp + i * 4);
            }
            CP_COMMIT();
        }

        // ---- S = Q K^T ----
        float s[8][4];
        #pragma unroll
        for (int nt = 0; nt < 8; nt++)
            #pragma unroll
            for (int j = 0; j < 4; j++) s[nt][j] = 0.f;
        #pragma unroll
        for (int kc = 0; kc < 8; kc++) {
            #pragma unroll
            for (int nt = 0; nt < 8; nt++) {
                uint32_t b0 = __float_as_uint(Ks[c][nt*8 + g][kc*8 + t    ]);
                uint32_t b1 = __float_as_uint(Ks[c][nt*8 + g][kc*8 + t + 4]);
                mma_tf32(s[nt][0], s[nt][1], s[nt][2], s[nt][3],
                         qf[kc][0], qf[kc][1], qf[kc][2], qf[kc][3], b0, b1);
            }
        }

        if (kt == qt) {
            #pragma unroll
            for (int nt = 0; nt < 8; nt++) {
                int c0 = nt * 8 + 2 * t;
                if (c0     > rA) s[nt][0] = -1e30f;
                if (c0 + 1 > rA) s[nt][1] = -1e30f;
                if (c0     > rB) s[nt][2] = -1e30f;
                if (c0 + 1 > rB) s[nt][3] = -1e30f;
            }
        }

        float mxA = -1e30f, mxB = -1e30f;
        #pragma unroll
        for (int nt = 0; nt < 8; nt++) {
            mxA = fmaxf(mxA, fmaxf(s[nt][0], s[nt][1]));
            mxB = fmaxf(mxB, fmaxf(s[nt][2], s[nt][3]));
        }
        mxA = fmaxf(mxA, __shfl_xor_sync(0xffffffffu, mxA, 1));
        mxA = fmaxf(mxA, __shfl_xor_sync(0xffffffffu, mxA, 2));
        mxB = fmaxf(mxB, __shfl_xor_sync(0xffffffffu, mxB, 1));
        mxB = fmaxf(mxB, __shfl_xor_sync(0xffffffffu, mxB, 2));
        float mnA = fmaxf(mA, mxA);
        float mnB = fmaxf(mB, mxB);
        float corrA = __expf(mA - mnA);
        float corrB = __expf(mB - mnB);

        float sumA = 0.f, sumB = 0.f;
        #pragma unroll
        for (int nt = 0; nt < 8; nt++) {
            s[nt][0] = __expf(s[nt][0] - mnA); sumA += s[nt][0];
            s[nt][1] = __expf(s[nt][1] - mnA); sumA += s[nt][1];
            s[nt][2] = __expf(s[nt][2] - mnB); sumB += s[nt][2];
            s[nt][3] = __expf(s[nt][3] - mnB); sumB += s[nt][3];
        }
        sumA += __shfl_xor_sync(0xffffffffu, sumA, 1);
        sumA += __shfl_xor_sync(0xffffffffu, sumA, 2);
        sumB += __shfl_xor_sync(0xffffffffu, sumB, 1);
        sumB += __shfl_xor_sync(0xffffffffu, sumB, 2);
        lA = lA * corrA + sumA;
        lB = lB * corrB + sumB;
        mA = mnA; mB = mnB;

        #pragma unroll
        for (int nt = 0; nt < 8; nt++) {
            o[nt][0] *= corrA; o[nt][1] *= corrA;
            o[nt][2] *= corrB; o[nt][3] *= corrB;
        }

        __syncthreads();   // all warps done reading Ks[c] (S mma)
        // ---- write P into Ks[c] (rna) ----
        #pragma unroll
        for (int nt = 0; nt < 8; nt++) {
            int c0 = nt * 8 + 2 * t;
            Ks[c][rA][c0    ] = cvt_tf32(s[nt][0]);
            Ks[c][rA][c0 + 1] = cvt_tf32(s[nt][1]);
            Ks[c][rB][c0    ] = cvt_tf32(s[nt][2]);
            Ks[c][rB][c0 + 1] = cvt_tf32(s[nt][3]);
        }
        __syncwarp();      // P rows for this warp are warp-private

        // ---- O += P V ----
        #pragma unroll
        for (int kc = 0; kc < 8; kc++) {
            uint32_t a0 = __float_as_uint(Ks[c][rA][kc*8 + t    ]);
            uint32_t a1 = __float_as_uint(Ks[c][rB][kc*8 + t    ]);
            uint32_t a2 = __float_as_uint(Ks[c][rA][kc*8 + t + 4]);
            uint32_t a3 = __float_as_uint(Ks[c][rB][kc*8 + t + 4]);
            #pragma unroll
            for (int nt = 0; nt < 8; nt++) {
                uint32_t b0 = __float_as_uint(Vs[c][kc*8 + t    ][nt*8 + g]);
                uint32_t b1 = __float_as_uint(Vs[c][kc*8 + t + 4][nt*8 + g]);
                mma_tf32(o[nt][0], o[nt][1], o[nt][2], o[nt][3],
                         a0, a1, a2, a3, b0, b1);
            }
        }
        // no trailing sync: next iter's wait+sync orders buffer reuse
    }

    // epilogue: rna-rounded y (feeds proj GEMM A operand)
    float invA = 1.0f / lA, invB = 1.0f / lB;
    int rowA = qbase + rA;
    float* yA = Y + (size_t)(b * TT + rowA) * CC + hoff;
    float* yB = Y + (size_t)(b * TT + rowA + 8) * CC + hoff;
    #pragma unroll
    for (int nt = 0; nt < 8; nt++) {
        int c0 = nt * 8 + 2 * t;
        *(float2*)(yA + c0) = make_float2(cvt_tf32(o[nt][0] * invA), cvt_tf32(o[nt][1] * invA));
        *(float2*)(yB + c0) = make_float2(cvt_tf32(o[nt][2] * invB), cvt_tf32(o[nt][3] * invB));
    }
}

// ---------------- launcher ----------------
extern "C" void kernel_launch(void* const* d_in, const int* in_sizes, int n_in,
                              void* d_out, int out_size) {
    const float* x     = (const float*)d_in[0];
    const float* ln1_g = (const float*)d_in[1];
    const float* ln1_b = (const float*)d_in[2];
    const float* Wq    = (const float*)d_in[3];
    const float* bq    = (const float*)d_in[4];
    const float* Wk    = (const float*)d_in[5];
    const float* bk    = (const float*)d_in[6];
    const float* Wv    = (const float*)d_in[7];
    const float* bv    = (const float*)d_in[8];
    const float* Wo    = (const float*)d_in[9];
    const float* bo    = (const float*)d_in[10];
    const float* ln2_g = (const float*)d_in[11];
    const float* ln2_b = (const float*)d_in[12];
    const float* W1    = (const float*)d_in[13];
    const float* b1    = (const float*)d_in[14];
    const float* W2    = (const float*)d_in[15];
    const float* b2    = (const float*)d_in[16];
    float* out = (float*)d_out;

    float *h, *q, *k, *v, *y, *x1, *m;
    float *wqkv, *bqkv, *wo, *w1, *w2;
    cudaGetSymbolAddress((void**)&h,    g_h);
    cudaGetSymbolAddress((void**)&q,    g_q);
    cudaGetSymbolAddress((void**)&k,    g_k);
    cudaGetSymbolAddress((void**)&v,    g_v);
    cudaGetSymbolAddress((void**)&y,    g_y);
    cudaGetSymbolAddress((void**)&x1,   g_x1);
    cudaGetSymbolAddress((void**)&m,    g_m);
    cudaGetSymbolAddress((void**)&wqkv, g_wqkv);
    cudaGetSymbolAddress((void**)&bqkv, g_bqkv);
    cudaGetSymbolAddress((void**)&wo,   g_wo);
    cudaGetSymbolAddress((void**)&w1,   g_w1);
    cudaGetSymbolAddress((void**)&w2,   g_w2);

    cudaFuncSetAttribute(gemm_tc<0>, cudaFuncAttributeMaxDynamicSharedMemorySize, GEMM_SMEM);
    cudaFuncSetAttribute(gemm_tc<1>, cudaFuncAttributeMaxDynamicSharedMemorySize, GEMM_SMEM);
    cudaFuncSetAttribute(gemm_tc<2>, cudaFuncAttributeMaxDynamicSharedMemorySize, GEMM_SMEM);
    cudaFuncSetAttribute(attn_tc_kernel, cudaFuncAttributeMaxDynamicSharedMemorySize, ATT_SMEM);

    // 0) weight prep — exactly 4 launches (so launch #5 is the QKV GEMM for ncu)
    prep_qkv<<<dim3(1, CC), 256>>>(Wq, wqkv, 0,      bq, bqkv);
    prep_qkv<<<dim3(1, CC), 256>>>(Wk, wqkv, CC,     bk, bqkv + CC);
    prep_qkv<<<dim3(1, CC), 256>>>(Wv, wqkv, 2 * CC, bv, bqkv + 2 * CC);
    prep_rest<<<(9 * 1024 * 1024) / (256 * 4), 256>>>(Wo, wo, W1, w1, W2, w2);

    dim3 gQKV(3*CC / 128, ROWS / 128);
    dim3 gC(CC / 128, ROWS / 128);
    dim3 gF(FF / 128, ROWS / 128);

    ln_kernel<<<ROWS, 256>>>(x, ln1_g, ln1_b, h);                       // launch 4
    gemm_tc<0><<<gQKV, 256, GEMM_SMEM>>>(h, wqkv, bqkv, nullptr, q, k, v,
                                         ROWS, 3*CC, CC, CC);           // launch 5 (profiled)
    attn_tc_kernel<<<dim3(TT / 64, NH, BB), 128, ATT_SMEM>>>(q, k, v, y);
    gemm_tc<1><<<gC, 256, GEMM_SMEM>>>(y, wo, bo, x, x1, x1, x1,
                                       ROWS, CC, CC, CC);
    ln_kernel<<<ROWS, 256>>>(x1, ln2_g, ln2_b, h);
    gemm_tc<2><<<gF, 256, GEMM_SMEM>>>(h, w1, b1, nullptr, m, m, m,
                                       ROWS, FF, CC, FF);
    gemm_tc<1><<<gC, 256, GEMM_SMEM>>>(m, w2, b2, x1, out, out, out,
                                       ROWS, CC, FF, CC);
}

// round 15
// speedup vs baseline: 1.3470x; 1.0046x over previous
#include <cuda_runtime.h>
#include <cuda_bf16.h>
#include <math.h>
#include <stdint.h>

// Problem constants
#define BB   4
#define TT   2048
#define CC   1024
#define NH   16
#define DH   64
#define ROWS (BB * TT)        // 8192
#define FF   (4 * CC)         // 4096

// ---------------- scratch (no allocs allowed) ----------------
__device__ float g_h [ROWS * CC];
__device__ float g_q [ROWS * CC];
__device__ float g_k [ROWS * CC];
__device__ float g_v [ROWS * CC];
__device__ float g_y [ROWS * CC];
__device__ float g_x1[ROWS * CC];
__device__ float g_m [ROWS * FF];
// rna-rounded weight copies
__device__ float g_wqkv[CC * 3 * CC];   // [K=1024][N=3072] (Wq|Wk|Wv)
__device__ float g_bqkv[3 * CC];
__device__ float g_wo  [CC * CC];
__device__ float g_w1  [CC * FF];
__device__ float g_w2  [FF * CC];

// ---------------- common helpers ----------------
__device__ __forceinline__ float gelu_exact(float x) {
    return 0.5f * x * (1.0f + erff(x * 0.70710678118654752f));
}

__device__ __forceinline__ float cvt_tf32(float x) {
    uint32_t r;
    asm("cvt.rna.tf32.f32 %0, %1;" : "=r"(r) : "f"(x));
    return __uint_as_float(r);
}

__device__ __forceinline__ void mma_tf32(float& d0, float& d1, float& d2, float& d3,
                                         uint32_t a0, uint32_t a1, uint32_t a2, uint32_t a3,
                                         uint32_t b0, uint32_t b1) {
    asm volatile(
        "mma.sync.aligned.m16n8k8.row.col.f32.tf32.tf32.f32 "
        "{%0,%1,%2,%3}, {%4,%5,%6,%7}, {%8,%9}, {%0,%1,%2,%3};"
        : "+f"(d0), "+f"(d1), "+f"(d2), "+f"(d3)
        : "r"(a0), "r"(a1), "r"(a2), "r"(a3), "r"(b0), "r"(b1));
}

#define CP_ASYNC16(dst, src) \
    asm volatile("cp.async.cg.shared.global [%0], [%1], 16;\n" :: "r"(dst), "l"(src))
#define CP_COMMIT() asm volatile("cp.async.commit_group;\n" ::: "memory")

// ---------------- weight prep (4 launches total) ----------------
// prep_qkv: one Wx -> wqkv column block (rounded) + its bias (raw copy)
__global__ void prep_qkv(const float* __restrict__ W, float* __restrict__ dst, int coloff,
                         const float* __restrict__ bsrc, float* __restrict__ bdst) {
    int k = blockIdx.y;                 // 0..1023
    int n = threadIdx.x * 4;            // 0..1020
    float4 v = *(const float4*)(W + (size_t)k * CC + n);
    v.x = cvt_tf32(v.x); v.y = cvt_tf32(v.y);
    v.z = cvt_tf32(v.z); v.w = cvt_tf32(v.w);
    *(float4*)(dst + (size_t)k * (3 * CC) + coloff + n) = v;
    if (k == 0) {
        float4 bv = *(const float4*)(bsrc + n);
        *(float4*)(bdst + n) = bv;
    }
}

// prep_rest: Wo, W1, W2 rounded copies in one kernel
__global__ void prep_rest(const float* __restrict__ wo_s, float* __restrict__ wo_d,
                          const float* __restrict__ w1_s, float* __restrict__ w1_d,
                          const float* __restrict__ w2_s, float* __restrict__ w2_d) {
    size_t i = ((size_t)blockIdx.x * 256 + threadIdx.x) * 4;
    const size_t n0 = (size_t)CC * CC;          // 1M
    const size_t n1 = n0 + (size_t)CC * FF;     // 5M
    const float* s; float* d; size_t off;
    if (i < n0)      { s = wo_s; d = wo_d; off = i; }
    else if (i < n1) { s = w1_s; d = w1_d; off = i - n0; }
    else             { s = w2_s; d = w2_d; off = i - n1; }
    float4 v = *(const float4*)(s + off);
    v.x = cvt_tf32(v.x); v.y = cvt_tf32(v.y);
    v.z = cvt_tf32(v.z); v.w = cvt_tf32(v.w);
    *(float4*)(d + off) = v;
}

// ---------------- LayerNorm: one block per row (rna-rounded out) --------------
__global__ void ln_kernel(const float* __restrict__ X,
                          const float* __restrict__ gam,
                          const float* __restrict__ bet,
                          float* __restrict__ out) {
    int row = blockIdx.x;
    int tid = threadIdx.x;
    const float4* x4 = (const float4*)(X + (size_t)row * CC);
    float4 v = x4[tid];
    float s  = v.x + v.y + v.z + v.w;
    float ss = v.x*v.x + v.y*v.y + v.z*v.z + v.w*v.w;
    #pragma unroll
    for (int off = 16; off > 0; off >>= 1) {
        s  += __shfl_down_sync(0xffffffffu, s,  off);
        ss += __shfl_down_sync(0xffffffffu, ss, off);
    }
    __shared__ float smS[8], smQ[8];
    __shared__ float sh_mu, sh_rstd;
    int lane = tid & 31, w = tid >> 5;
    if (lane == 0) { smS[w] = s; smQ[w] = ss; }
    __syncthreads();
    if (tid == 0) {
        float ts = 0.f, tq = 0.f;
        #pragma unroll
        for (int i = 0; i < 8; i++) { ts += smS[i]; tq += smQ[i]; }
        float mu  = ts * (1.0f / CC);
        float var = tq * (1.0f / CC) - mu * mu;
        sh_mu = mu;
        sh_rstd = rsqrtf(var + 1e-5f);
    }
    __syncthreads();
    float mu = sh_mu, rstd = sh_rstd;
    float4 gv = ((const float4*)gam)[tid];
    float4 bv = ((const float4*)bet)[tid];
    float4 o;
    o.x = cvt_tf32((v.x - mu) * rstd * gv.x + bv.x);
    o.y = cvt_tf32((v.y - mu) * rstd * gv.y + bv.y);
    o.z = cvt_tf32((v.z - mu) * rstd * gv.z + bv.z);
    o.w = cvt_tf32((v.w - mu) * rstd * gv.w + bv.w);
    ((float4*)(out + (size_t)row * CC))[tid] = o;
}

// ---------------- TF32 HMMA GEMM: 16-k stages, 5-stage ring, 2 stages/barrier --
// EPI: 0 = bias + rna-round (QKV), 1 = bias + residual, 2 = bias + GELU + round
#define AST 20
#define WST 132
#define GST 5
#define STG_FLOATS (128 * AST + 16 * WST)   // 4672 floats = 18688 B
#define STG_BYTES  (STG_FLOATS * 4)
#define GEMM_SMEM  (GST * STG_BYTES)        // 93440 B

template <int EPI>
__global__ __launch_bounds__(256, 2)
void gemm_tc(const float* __restrict__ A, const float* __restrict__ W,
             const float* __restrict__ bias, const float* __restrict__ res,
             float* __restrict__ C0, float* __restrict__ C1, float* __restrict__ C2,
             int M, int N, int K, int outN) {
    extern __shared__ __align__(16) float dsm[];

    int tid  = threadIdx.x;
    int lane = tid & 31;
    int wid  = tid >> 5;
    int warp_m = wid >> 2;
    int warp_n = wid & 3;
    int g = lane >> 2, t = lane & 3;
    int bm = blockIdx.y * 128;
    int bn = blockIdx.x * 128;

    int bi = bn / outN;
    float* C = (bi == 0) ? C0 : ((bi == 1) ? C1 : C2);
    int cn = bn - bi * outN;

    int am  = tid >> 2;             // 0..63: rows am, am+64
    int akq = (tid & 3) * 4;        // 0,4,8,12
    int wk  = tid >> 5;             // 0..7: rows wk, wk+8
    int wn4 = (tid & 31) * 4;

    const float* Apb = A + (size_t)(bm + am) * K + akq;
    const float* Wpb = W + (size_t)wk * N + bn + wn4;

    uint32_t bA0 = (uint32_t)__cvta_generic_to_shared(dsm + am * AST + akq);
    uint32_t bA1 = (uint32_t)__cvta_generic_to_shared(dsm + (am + 64) * AST + akq);
    uint32_t bW0 = (uint32_t)__cvta_generic_to_shared(dsm + 128 * AST + wk * WST + wn4);
    uint32_t bW1 = (uint32_t)__cvta_generic_to_shared(dsm + 128 * AST + (wk + 8) * WST + wn4);

    float acc[4][4][4];
    #pragma unroll
    for (int i = 0; i < 4; i++)
        #pragma unroll
        for (int j = 0; j < 4; j++)
            #pragma unroll
            for (int r = 0; r < 4; r++) acc[i][j][r] = 0.f;

    int NT = K >> 4;

    #pragma unroll
    for (int s = 0; s < 3; s++) {
        uint32_t so = (uint32_t)s * STG_BYTES;
        int k0 = s << 4;
        CP_ASYNC16(bA0 + so, Apb + k0);
        CP_ASYNC16(bA1 + so, Apb + (size_t)64 * K + k0);
        CP_ASYNC16(bW0 + so, Wpb + (size_t)k0 * N);
        CP_ASYNC16(bW1 + so, Wpb + (size_t)(k0 + 8) * N);
        CP_COMMIT();
    }

    for (int kt = 0; kt < NT; kt += 2) {
        asm volatile("cp.async.wait_group 1;" ::: "memory");
        __syncthreads();

        #pragma unroll
        for (int d = 3; d <= 4; d++) {
            int ks = kt + d;
            if (ks < NT) {
                uint32_t so = (uint32_t)(ks % GST) * STG_BYTES;
                int k0 = ks << 4;
                CP_ASYNC16(bA0 + so, Apb + k0);
                CP_ASYNC16(bA1 + so, Apb + (size_t)64 * K + k0);
                CP_ASYNC16(bW0 + so, Wpb + (size_t)k0 * N);
                CP_ASYNC16(bW1 + so, Wpb + (size_t)(k0 + 8) * N);
            }
            CP_COMMIT();
        }

        #pragma unroll
        for (int d = 0; d < 2; d++) {
            int st = (kt + d) % GST;
            float* base = dsm + st * STG_FLOATS;
            float (*As)[AST] = (float(*)[AST])base;
            float (*Ws)[WST] = (float(*)[WST])(base + 128 * AST);

            #pragma unroll
            for (int kc = 0; kc < 2; kc++) {
                int kr = kc * 8 + t;
                uint32_t af[4][4];
                uint32_t bf[4][2];
                #pragma unroll
                for (int mtl = 0; mtl < 4; mtl++) {
                    int m = warp_m * 64 + mtl * 16 + g;
                    af[mtl][0] = __float_as_uint(As[m    ][kr    ]);
                    af[mtl][1] = __float_as_uint(As[m + 8][kr    ]);
                    af[mtl][2] = __float_as_uint(As[m    ][kr + 4]);
                    af[mtl][3] = __float_as_uint(As[m + 8][kr + 4]);
                }
                #pragma unroll
                for (int ntl = 0; ntl < 4; ntl++) {
                    int n = warp_n * 32 + ntl * 8 + g;
                    bf[ntl][0] = __float_as_uint(Ws[kr    ][n]);
                    bf[ntl][1] = __float_as_uint(Ws[kr + 4][n]);
                }
                #pragma unroll
                for (int mtl = 0; mtl < 4; mtl++)
                    #pragma unroll
                    for (int ntl = 0; ntl < 4; ntl++)
                        mma_tf32(acc[mtl][ntl][0], acc[mtl][ntl][1],
                                 acc[mtl][ntl][2], acc[mtl][ntl][3],
                                 af[mtl][0], af[mtl][1], af[mtl][2], af[mtl][3],
                                 bf[ntl][0], bf[ntl][1]);
            }
        }
    }

    // ---- epilogue ----
    #pragma unroll
    for (int mt = 0; mt < 4; mt++) {
        int r0 = bm + warp_m * 64 + mt * 16 + g;
        #pragma unroll
        for (int nt = 0; nt < 4; nt++) {
            int gcol = bn + warp_n * 32 + nt * 8 + t * 2;
            int col  = cn + warp_n * 32 + nt * 8 + t * 2;
            float b0 = bias[gcol], b1 = bias[gcol + 1];
            #pragma unroll
            for (int h = 0; h < 2; h++) {
                int row = r0 + h * 8;
                float v0 = acc[mt][nt][h * 2 + 0] + b0;
                float v1 = acc[mt][nt][h * 2 + 1] + b1;
                if (EPI == 0) {       // QKV: pre-round for attention
                    v0 = cvt_tf32(v0);
                    v1 = cvt_tf32(v1);
                }
                if (EPI == 1) {
                    const float* rp = res + (size_t)row * outN + col;
                    v0 += rp[0]; v1 += rp[1];
                }
                if (EPI == 2) {
                    v0 = cvt_tf32(gelu_exact(v0));
                    v1 = cvt_tf32(gelu_exact(v1));
                }
                *(float2*)(C + (size_t)row * outN + col) = make_float2(v0, v1);
            }
        }
    }
}

// ---------------- Tensor-core flash attention (causal, tf32) ----------------
// K/V (pre-rounded by QKV epilogue) streamed via cp.async double buffering.
#define KS_STR 68
#define VS_STR 72
#define ATT_K_FLOATS (64 * KS_STR)               // 4352
#define ATT_V_FLOATS (64 * VS_STR)               // 4608
#define ATT_SMEM ((2 * ATT_K_FLOATS + 2 * ATT_V_FLOATS) * 4)   // 71680 B

__global__ __launch_bounds__(128)
void attn_tc_kernel(const float* __restrict__ Q,
                    const float* __restrict__ K,
                    const float* __restrict__ V,
                    float* __restrict__ Y) {
    extern __shared__ __align__(16) float dsm[];
    float (*Ks)[64][KS_STR] = (float(*)[64][KS_STR])dsm;                       // 2 bufs (also P)
    float (*Vs)[64][VS_STR] = (float(*)[64][VS_STR])(dsm + 2 * ATT_K_FLOATS);  // 2 bufs

    int qt = blockIdx.x, h = blockIdx.y, b = blockIdx.z;
    int tid = threadIdx.x;
    int lane = tid & 31, w = tid >> 5;
    int g = lane >> 2, t = lane & 3;
    int qbase = qt * 64;
    const int hoff = h * DH;

    int lrow = tid >> 1;            // staging row 0..63
    int ld0  = (tid & 1) * 32;      // staging col 0/32

    uint32_t ksm[2], vsm[2];
    #pragma unroll
    for (int s = 0; s < 2; s++) {
        ksm[s] = (uint32_t)__cvta_generic_to_shared(&Ks[s][lrow][ld0]);
        vsm[s] = (uint32_t)__cvta_generic_to_shared(&Vs[s][lrow][ld0]);
    }

    // ---- issue tile 0 loads ----
    {
        const float* kp = K + (size_t)(b * TT + lrow) * CC + hoff + ld0;
        const float* vp = V + (size_t)(b * TT + lrow) * CC + hoff + ld0;
        #pragma unroll
        for (int i = 0; i < 8; i++) {
            CP_ASYNC16(ksm[0] + i * 16, kp + i * 4);
            CP_ASYNC16(vsm[0] + i * 16, vp + i * 4);
        }
        CP_COMMIT();
    }

    // ---- stage Q (x 1/8, exact) into Vs[1]; extract fragments ----
    {
        const float* qp = Q + (size_t)(b * TT + qbase + lrow) * CC + hoff + ld0;
        #pragma unroll
        for (int i = 0; i < 8; i++) {
            float4 v4 = ((const float4*)qp)[i];
            Vs[1][lrow][ld0 + 4*i + 0] = v4.x * 0.125f;
            Vs[1][lrow][ld0 + 4*i + 1] = v4.y * 0.125f;
            Vs[1][lrow][ld0 + 4*i + 2] = v4.z * 0.125f;
            Vs[1][lrow][ld0 + 4*i + 3] = v4.w * 0.125f;
        }
    }
    __syncthreads();
    uint32_t qf[8][4];
    {
        int rA = 16 * w + g;
        #pragma unroll
        for (int kc = 0; kc < 8; kc++) {
            qf[kc][0] = __float_as_uint(Vs[1][rA    ][kc*8 + t    ]);
            qf[kc][1] = __float_as_uint(Vs[1][rA + 8][kc*8 + t    ]);
            qf[kc][2] = __float_as_uint(Vs[1][rA    ][kc*8 + t + 4]);
            qf[kc][3] = __float_as_uint(Vs[1][rA + 8][kc*8 + t + 4]);
        }
    }

    float o[8][4];
    #pragma unroll
    for (int nt = 0; nt < 8; nt++)
        #pragma unroll
        for (int j = 0; j < 4; j++) o[nt][j] = 0.f;
    float mA = -1e30f, mB = -1e30f, lA = 0.f, lB = 0.f;

    int rA = 16 * w + g;
    int rB = rA + 8;

    for (int kt = 0; kt <= qt; kt++) {
        int c = kt & 1;
        asm volatile("cp.async.wait_group 0;" ::: "memory");
        __syncthreads();   // tile kt landed; prior-tile P/V reads done; qf extraction done

        // issue tile kt+1 into the other buffer (flies during compute)
        if (kt < qt) {
            const float* kp = K + (size_t)(b * TT + (kt+1) * 64 + lrow) * CC + hoff + ld0;
            const float* vp = V + (size_t)(b * TT + (kt+1) * 64 + lrow) * CC + hoff + ld0;
            #pragma unroll
            for (int i = 0; i < 8; i++) {
                CP_ASYNC16(ksm[1 - c] + i * 16, kp + i * 4);
                CP_ASYNC16(vsm[1 - c] + i * 16, vp + i * 4);
            }
            CP_COMMIT();
        }

        // ---- S = Q K^T ----
        float s[8][4];
        #pragma unroll
        for (int nt = 0; nt < 8; nt++)
            #pragma unroll
            for (int j = 0; j < 4; j++) s[nt][j] = 0.f;
        #pragma unroll
        for (int kc = 0; kc < 8; kc++) {
            #pragma unroll
            for (int nt = 0; nt < 8; nt++) {
                uint32_t b0 = __float_as_uint(Ks[c][nt*8 + g][kc*8 + t    ]);
                uint32_t b1 = __float_as_uint(Ks[c][nt*8 + g][kc*8 + t + 4]);
                mma_tf32(s[nt][0], s[nt][1], s[nt][2], s[nt][3],
                         qf[kc][0], qf[kc][1], qf[kc][2], qf[kc][3], b0, b1);
            }
        }

        if (kt == qt) {
            #pragma unroll
            for (int nt = 0; nt < 8; nt++) {
                int c0 = nt * 8 + 2 * t;
                if (c0     > rA) s[nt][0] = -1e30f;
                if (c0 + 1 > rA) s[nt][1] = -1e30f;
                if (c0     > rB) s[nt][2] = -1e30f;
                if (c0 + 1 > rB) s[nt][3] = -1e30f;
            }
        }

        float mxA = -1e30f, mxB = -1e30f;
        #pragma unroll
        for (int nt = 0; nt < 8; nt++) {
            mxA = fmaxf(mxA, fmaxf(s[nt][0], s[nt][1]));
            mxB = fmaxf(mxB, fmaxf(s[nt][2], s[nt][3]));
        }
        mxA = fmaxf(mxA, __shfl_xor_sync(0xffffffffu, mxA, 1));
        mxA = fmaxf(mxA, __shfl_xor_sync(0xffffffffu, mxA, 2));
        mxB = fmaxf(mxB, __shfl_xor_sync(0xffffffffu, mxB, 1));
        mxB = fmaxf(mxB, __shfl_xor_sync(0xffffffffu, mxB, 2));
        float mnA = fmaxf(mA, mxA);
        float mnB = fmaxf(mB, mxB);
        float corrA = __expf(mA - mnA);
        float corrB = __expf(mB - mnB);

        float sumA = 0.f, sumB = 0.f;
        #pragma unroll
        for (int nt = 0; nt < 8; nt++) {
            s[nt][0] = __expf(s[nt][0] - mnA); sumA += s[nt][0];
            s[nt][1] = __expf(s[nt][1] - mnA); sumA += s[nt][1];
            s[nt][2] = __expf(s[nt][2] - mnB); sumB += s[nt][2];
            s[nt][3] = __expf(s[nt][3] - mnB); sumB += s[nt][3];
        }
        sumA += __shfl_xor_sync(0xffffffffu, sumA, 1);
        sumA += __shfl_xor_sync(0xffffffffu, sumA, 2);
        sumB += __shfl_xor_sync(0xffffffffu, sumB, 1);
        sumB += __shfl_xor_sync(0xffffffffu, sumB, 2);
        lA = lA * corrA + sumA;
        lB = lB * corrB + sumB;
        mA = mnA; mB = mnB;

        #pragma unroll
        for (int nt = 0; nt < 8; nt++) {
            o[nt][0] *= corrA; o[nt][1] *= corrA;
            o[nt][2] *= corrB; o[nt][3] *= corrB;
        }

        __syncthreads();   // all warps done reading Ks[c] (S mma)
        // ---- write P into Ks[c] (rna) ----
        #pragma unroll
        for (int nt = 0; nt < 8; nt++) {
            int c0 = nt * 8 + 2 * t;
            Ks[c][rA][c0    ] = cvt_tf32(s[nt][0]);
            Ks[c][rA][c0 + 1] = cvt_tf32(s[nt][1]);
            Ks[c][rB][c0    ] = cvt_tf32(s[nt][2]);
            Ks[c][rB][c0 + 1] = cvt_tf32(s[nt][3]);
        }
        __syncwarp();      // P rows for this warp are warp-private

        // ---- O += P V ----
        #pragma unroll
        for (int kc = 0; kc < 8; kc++) {
            uint32_t a0 = __float_as_uint(Ks[c][rA][kc*8 + t    ]);
            uint32_t a1 = __float_as_uint(Ks[c][rB][kc*8 + t    ]);
            uint32_t a2 = __float_as_uint(Ks[c][rA][kc*8 + t + 4]);
            uint32_t a3 = __float_as_uint(Ks[c][rB][kc*8 + t + 4]);
            #pragma unroll
            for (int nt = 0; nt < 8; nt++) {
                uint32_t b0 = __float_as_uint(Vs[c][kc*8 + t    ][nt*8 + g]);
                uint32_t b1 = __float_as_uint(Vs[c][kc*8 + t + 4][nt*8 + g]);
                mma_tf32(o[nt][0], o[nt][1], o[nt][2], o[nt][3],
                         a0, a1, a2, a3, b0, b1);
            }
        }
        // no trailing sync: next iter's wait+sync orders buffer reuse
    }

    // epilogue: rna-rounded y (feeds proj GEMM A operand)
    float invA = 1.0f / lA, invB = 1.0f / lB;
    int rowA = qbase + rA;
    float* yA = Y + (size_t)(b * TT + rowA) * CC + hoff;
    float* yB = Y + (size_t)(b * TT + rowA + 8) * CC + hoff;
    #pragma unroll
    for (int nt = 0; nt < 8; nt++) {
        int c0 = nt * 8 + 2 * t;
        *(float2*)(yA + c0) = make_float2(cvt_tf32(o[nt][0] * invA), cvt_tf32(o[nt][1] * invA));
        *(float2*)(yB + c0) = make_float2(cvt_tf32(o[nt][2] * invB), cvt_tf32(o[nt][3] * invB));
    }
}

// ---------------- launcher ----------------
extern "C" void kernel_launch(void* const* d_in, const int* in_sizes, int n_in,
                              void* d_out, int out_size) {
    const float* x     = (const float*)d_in[0];
    const float* ln1_g = (const float*)d_in[1];
    const float* ln1_b = (const float*)d_in[2];
    const float* Wq    = (const float*)d_in[3];
    const float* bq    = (const float*)d_in[4];
    const float* Wk    = (const float*)d_in[5];
    const float* bk    = (const float*)d_in[6];
    const float* Wv    = (const float*)d_in[7];
    const float* bv    = (const float*)d_in[8];
    const float* Wo    = (const float*)d_in[9];
    const float* bo    = (const float*)d_in[10];
    const float* ln2_g = (const float*)d_in[11];
    const float* ln2_b = (const float*)d_in[12];
    const float* W1    = (const float*)d_in[13];
    const float* b1    = (const float*)d_in[14];
    const float* W2    = (const float*)d_in[15];
    const float* b2    = (const float*)d_in[16];
    float* out = (float*)d_out;

    float *h, *q, *k, *v, *y, *x1, *m;
    float *wqkv, *bqkv, *wo, *w1, *w2;
    cudaGetSymbolAddress((void**)&h,    g_h);
    cudaGetSymbolAddress((void**)&q,    g_q);
    cudaGetSymbolAddress((void**)&k,    g_k);
    cudaGetSymbolAddress((void**)&v,    g_v);
    cudaGetSymbolAddress((void**)&y,    g_y);
    cudaGetSymbolAddress((void**)&x1,   g_x1);
    cudaGetSymbolAddress((void**)&m,    g_m);
    cudaGetSymbolAddress((void**)&wqkv, g_wqkv);
    cudaGetSymbolAddress((void**)&bqkv, g_bqkv);
    cudaGetSymbolAddress((void**)&wo,   g_wo);
    cudaGetSymbolAddress((void**)&w1,   g_w1);
    cudaGetSymbolAddress((void**)&w2,   g_w2);

    cudaFuncSetAttribute(gemm_tc<0>, cudaFuncAttributeMaxDynamicSharedMemorySize, GEMM_SMEM);
    cudaFuncSetAttribute(gemm_tc<1>, cudaFuncAttributeMaxDynamicSharedMemorySize, GEMM_SMEM);
    cudaFuncSetAttribute(gemm_tc<2>, cudaFuncAttributeMaxDynamicSharedMemorySize, GEMM_SMEM);
    cudaFuncSetAttribute(attn_tc_kernel, cudaFuncAttributeMaxDynamicSharedMemorySize, ATT_SMEM);

    // 0) weight prep — exactly 4 launches (so launch #5 is the QKV GEMM for ncu)
    prep_qkv<<<dim3(1, CC), 256>>>(Wq, wqkv, 0,      bq, bqkv);
    prep_qkv<<<dim3(1, CC), 256>>>(Wk, wqkv, CC,     bk, bqkv + CC);
    prep_qkv<<<dim3(1, CC), 256>>>(Wv, wqkv, 2 * CC, bv, bqkv + 2 * CC);
    prep_rest<<<(9 * 1024 * 1024) / (256 * 4), 256>>>(Wo, wo, W1, w1, W2, w2);

    dim3 gQKV(3*CC / 128, ROWS / 128);
    dim3 gC(CC / 128, ROWS / 128);
    dim3 gF(FF / 128, ROWS / 128);

    ln_kernel<<<ROWS, 256>>>(x, ln1_g, ln1_b, h);                       // launch 4
    gemm_tc<0><<<gQKV, 256, GEMM_SMEM>>>(h, wqkv, bqkv, nullptr, q, k, v,
                                         ROWS, 3*CC, CC, CC);           // launch 5 (profiled)
    attn_tc_kernel<<<dim3(TT / 64, NH, BB), 128, ATT_SMEM>>>(q, k, v, y);
    gemm_tc<1><<<gC, 256, GEMM_SMEM>>>(y, wo, bo, x, x1, x1, x1,
                                       ROWS, CC, CC, CC);
    ln_kernel<<<ROWS, 256>>>(x1, ln2_g, ln2_b, h);
    gemm_tc<2><<<gF, 256, GEMM_SMEM>>>(h, w1, b1, nullptr, m, m, m,
                                       ROWS, FF, CC, FF);
    gemm_tc<1><<<gC, 256, GEMM_SMEM>>>(m, w2, b2, x1, out, out, out,
                                       ROWS, CC, FF, CC);
}

// round 16
// speedup vs baseline: 1.9308x; 1.4334x over previous
#include <cuda_runtime.h>
#include <cuda_fp16.h>
#include <math.h>
#include <stdint.h>

// Problem constants
#define BB   4
#define TT   2048
#define CC   1024
#define NH   16
#define DH   64
#define ROWS (BB * TT)        // 8192
#define FF   (4 * CC)         // 4096

// ---------------- scratch (no allocs allowed) ----------------
__device__ __half g_h16[ROWS * CC];     // LN outputs (fp16)
__device__ float  g_q [ROWS * CC];
__device__ float  g_k [ROWS * CC];
__device__ float  g_v [ROWS * CC];
__device__ __half g_y16[ROWS * CC];     // attention output (fp16)
__device__ float  g_x1[ROWS * CC];
__device__ __half g_m16[ROWS * FF];     // GELU output (fp16)
// fp16 transposed weights [N][K]
__device__ __half g_wqkvt[3 * CC * CC];
__device__ float  g_bqkv [3 * CC];
__device__ __half g_wot  [CC * CC];
__device__ __half g_w1t  [FF * CC];
__device__ __half g_w2t  [CC * FF];

// ---------------- common helpers ----------------
__device__ __forceinline__ float gelu_exact(float x) {
    return 0.5f * x * (1.0f + erff(x * 0.70710678118654752f));
}

__device__ __forceinline__ float cvt_tf32(float x) {
    uint32_t r;
    asm("cvt.rna.tf32.f32 %0, %1;" : "=r"(r) : "f"(x));
    return __uint_as_float(r);
}

// tf32 mma (attention only)
__device__ __forceinline__ void mma_tf32(float& d0, float& d1, float& d2, float& d3,
                                         uint32_t a0, uint32_t a1, uint32_t a2, uint32_t a3,
                                         uint32_t b0, uint32_t b1) {
    asm volatile(
        "mma.sync.aligned.m16n8k8.row.col.f32.tf32.tf32.f32 "
        "{%0,%1,%2,%3}, {%4,%5,%6,%7}, {%8,%9}, {%0,%1,%2,%3};"
        : "+f"(d0), "+f"(d1), "+f"(d2), "+f"(d3)
        : "r"(a0), "r"(a1), "r"(a2), "r"(a3), "r"(b0), "r"(b1));
}

// fp16 mma (GEMMs)
__device__ __forceinline__ void mma_fp16(float& d0, float& d1, float& d2, float& d3,
                                         uint32_t a0, uint32_t a1, uint32_t a2, uint32_t a3,
                                         uint32_t b0, uint32_t b1) {
    asm volatile(
        "mma.sync.aligned.m16n8k16.row.col.f32.f16.f16.f32 "
        "{%0,%1,%2,%3}, {%4,%5,%6,%7}, {%8,%9}, {%0,%1,%2,%3};"
        : "+f"(d0), "+f"(d1), "+f"(d2), "+f"(d3)
        : "r"(a0), "r"(a1), "r"(a2), "r"(a3), "r"(b0), "r"(b1));
}

#define CP_ASYNC16(dst, src) \
    asm volatile("cp.async.cg.shared.global [%0], [%1], 16;\n" :: "r"(dst), "l"(src))
#define CP_COMMIT() asm volatile("cp.async.commit_group;\n" ::: "memory")

// ---------------- weight prep: transpose + fp16 convert ----------------
// src[K][N] fp32 -> dst[N][K] fp16 (dst row stride = K). Optional bias copy.
__global__ void prep_t(const float* __restrict__ src, __half* __restrict__ dst,
                       int K, int N,
                       const float* __restrict__ bsrc, float* __restrict__ bdst) {
    __shared__ float t[32][33];
    int n0 = blockIdx.x * 32, k0 = blockIdx.y * 32;
    int tx = threadIdx.x & 31, ty = threadIdx.x >> 5;   // 32 x 8
    #pragma unroll
    for (int i = 0; i < 4; i++)
        t[ty + 8*i][tx] = src[(size_t)(k0 + ty + 8*i) * N + n0 + tx];
    __syncthreads();
    #pragma unroll
    for (int i = 0; i < 4; i++)
        dst[(size_t)(n0 + ty + 8*i) * K + k0 + tx] = __float2half_rn(t[tx][ty + 8*i]);
    if (bsrc && blockIdx.y == 0 && ty == 0)
        bdst[n0 + tx] = bsrc[n0 + tx];
}

// ---------------- LayerNorm: one block per row -> fp16 out --------------
__global__ void ln_kernel(const float* __restrict__ X,
                          const float* __restrict__ gam,
                          const float* __restrict__ bet,
                          __half* __restrict__ out) {
    int row = blockIdx.x;
    int tid = threadIdx.x;
    const float4* x4 = (const float4*)(X + (size_t)row * CC);
    float4 v = x4[tid];
    float s  = v.x + v.y + v.z + v.w;
    float ss = v.x*v.x + v.y*v.y + v.z*v.z + v.w*v.w;
    #pragma unroll
    for (int off = 16; off > 0; off >>= 1) {
        s  += __shfl_down_sync(0xffffffffu, s,  off);
        ss += __shfl_down_sync(0xffffffffu, ss, off);
    }
    __shared__ float smS[8], smQ[8];
    __shared__ float sh_mu, sh_rstd;
    int lane = tid & 31, w = tid >> 5;
    if (lane == 0) { smS[w] = s; smQ[w] = ss; }
    __syncthreads();
    if (tid == 0) {
        float ts = 0.f, tq = 0.f;
        #pragma unroll
        for (int i = 0; i < 8; i++) { ts += smS[i]; tq += smQ[i]; }
        float mu  = ts * (1.0f / CC);
        float var = tq * (1.0f / CC) - mu * mu;
        sh_mu = mu;
        sh_rstd = rsqrtf(var + 1e-5f);
    }
    __syncthreads();
    float mu = sh_mu, rstd = sh_rstd;
    float4 gv = ((const float4*)gam)[tid];
    float4 bv = ((const float4*)bet)[tid];
    __half2* o2 = (__half2*)(out + (size_t)row * CC);
    o2[tid * 2 + 0] = __floats2half2_rn((v.x - mu) * rstd * gv.x + bv.x,
                                        (v.y - mu) * rstd * gv.y + bv.y);
    o2[tid * 2 + 1] = __floats2half2_rn((v.z - mu) * rstd * gv.z + bv.z,
                                        (v.w - mu) * rstd * gv.w + bv.w);
}

// ---------------- FP16 HMMA GEMM: 32-k stages, 5-stage ring, 2/barrier ----
// C = A[M,K](fp16) @ Wt[N,K](fp16)^T + bias; EPI: 0=QKV(fp32+tf32 round,
// split 3 bufs), 1=residual fp32, 2=GELU->fp16.
#define ASTH 40                              // halves per A/W smem row (80 B)
#define ASTG (128 * 80)                      // 10240 B per operand per stage
#define STG_BYTES (2 * ASTG)                 // 20480 B
#define GST 5
#define GEMM_SMEM (GST * STG_BYTES)          // 102400 B

template <int EPI>
__global__ __launch_bounds__(256, 2)
void gemm_fp16(const __half* __restrict__ A, const __half* __restrict__ Wt,
               const float* __restrict__ bias, const float* __restrict__ res,
               void* C0v, void* C1v, void* C2v,
               int M, int N, int K, int outN) {
    extern __shared__ __align__(16) char dsm[];

    int tid  = threadIdx.x;
    int lane = tid & 31;
    int wid  = tid >> 5;
    int warp_m = wid >> 2;          // 0..1
    int warp_n = wid & 3;           // 0..3
    int g = lane >> 2, t = lane & 3;
    int bm = blockIdx.y * 128;
    int bn = blockIdx.x * 128;

    int bi = bn / outN;
    int cn = bn - bi * outN;

    // staging: thread -> row rr (0..127), 32B chunk pair at half-col hc (0/16)
    int rr = tid >> 1;
    int hc = (tid & 1) * 16;

    const __half* Apb = A  + (size_t)(bm + rr) * K + hc;
    const __half* Wpb = Wt + (size_t)(bn + rr) * K + hc;

    uint32_t sA0 = (uint32_t)__cvta_generic_to_shared(dsm + rr * 80 + (tid & 1) * 32);
    uint32_t sW0 = sA0 + ASTG;

    float acc[4][4][4];
    #pragma unroll
    for (int i = 0; i < 4; i++)
        #pragma unroll
        for (int j = 0; j < 4; j++)
            #pragma unroll
            for (int r = 0; r < 4; r++) acc[i][j][r] = 0.f;

    int NT = K >> 5;    // 32-k stages

    // prologue: stages 0,1,2
    #pragma unroll
    for (int s = 0; s < 3; s++) {
        uint32_t so = (uint32_t)s * STG_BYTES;
        int k0 = s << 5;
        CP_ASYNC16(sA0 + so,      Apb + k0);
        CP_ASYNC16(sA0 + so + 16, Apb + k0 + 8);
        CP_ASYNC16(sW0 + so,      Wpb + k0);
        CP_ASYNC16(sW0 + so + 16, Wpb + k0 + 8);
        CP_COMMIT();
    }

    for (int kt = 0; kt < NT; kt += 2) {
        asm volatile("cp.async.wait_group 1;" ::: "memory");
        __syncthreads();

        #pragma unroll
        for (int d = 3; d <= 4; d++) {
            int ks = kt + d;
            if (ks < NT) {
                uint32_t so = (uint32_t)(ks % GST) * STG_BYTES;
                int k0 = ks << 5;
                CP_ASYNC16(sA0 + so,      Apb + k0);
                CP_ASYNC16(sA0 + so + 16, Apb + k0 + 8);
                CP_ASYNC16(sW0 + so,      Wpb + k0);
                CP_ASYNC16(sW0 + so + 16, Wpb + k0 + 8);
            }
            CP_COMMIT();
        }

        #pragma unroll
        for (int d = 0; d < 2; d++) {
            int st = (kt + d) % GST;
            const __half* Ash = (const __half*)(dsm + st * STG_BYTES);
            const __half* Wsh = (const __half*)(dsm + st * STG_BYTES + ASTG);

            #pragma unroll
            for (int kc = 0; kc < 2; kc++) {
                int kb = kc * 16 + 2 * t;
                uint32_t af[4][4];
                uint32_t bf[4][2];
                #pragma unroll
                for (int mtl = 0; mtl < 4; mtl++) {
                    int m = warp_m * 64 + mtl * 16 + g;
                    af[mtl][0] = *(const uint32_t*)(Ash + m * ASTH + kb);
                    af[mtl][1] = *(const uint32_t*)(Ash + (m + 8) * ASTH + kb);
                    af[mtl][2] = *(const uint32_t*)(Ash + m * ASTH + kb + 8);
                    af[mtl][3] = *(const uint32_t*)(Ash + (m + 8) * ASTH + kb + 8);
                }
                #pragma unroll
                for (int ntl = 0; ntl < 4; ntl++) {
                    int n = warp_n * 32 + ntl * 8 + g;
                    bf[ntl][0] = *(const uint32_t*)(Wsh + n * ASTH + kb);
                    bf[ntl][1] = *(const uint32_t*)(Wsh + n * ASTH + kb + 8);
                }
                #pragma unroll
                for (int mtl = 0; mtl < 4; mtl++)
                    #pragma unroll
                    for (int ntl = 0; ntl < 4; ntl++)
                        mma_fp16(acc[mtl][ntl][0], acc[mtl][ntl][1],
                                 acc[mtl][ntl][2], acc[mtl][ntl][3],
                                 af[mtl][0], af[mtl][1], af[mtl][2], af[mtl][3],
                                 bf[ntl][0], bf[ntl][1]);
            }
        }
    }

    // ---- epilogue ----
    #pragma unroll
    for (int mt = 0; mt < 4; mt++) {
        int r0 = bm + warp_m * 64 + mt * 16 + g;
        #pragma unroll
        for (int nt = 0; nt < 4; nt++) {
            int gcol = bn + warp_n * 32 + nt * 8 + t * 2;
            int col  = cn + warp_n * 32 + nt * 8 + t * 2;
            float b0 = bias[gcol], b1 = bias[gcol + 1];
            #pragma unroll
            for (int hh = 0; hh < 2; hh++) {
                int row = r0 + hh * 8;
                float v0 = acc[mt][nt][hh * 2 + 0] + b0;
                float v1 = acc[mt][nt][hh * 2 + 1] + b1;
                if (EPI == 0) {
                    float* Cf = (bi == 0) ? (float*)C0v : ((bi == 1) ? (float*)C1v : (float*)C2v);
                    v0 = cvt_tf32(v0);
                    v1 = cvt_tf32(v1);
                    *(float2*)(Cf + (size_t)row * outN + col) = make_float2(v0, v1);
                }
                if (EPI == 1) {
                    const float* rp = res + (size_t)row * outN + col;
                    float* Cf = (float*)C0v;
                    *(float2*)(Cf + (size_t)row * outN + col) =
                        make_float2(v0 + rp[0], v1 + rp[1]);
                }
                if (EPI == 2) {
                    __half* Ch = (__half*)C0v;
                    *(__half2*)(Ch + (size_t)row * outN + col) =
                        __floats2half2_rn(gelu_exact(v0), gelu_exact(v1));
                }
            }
        }
    }
}

// ---------------- Tensor-core flash attention (causal, tf32) ----------------
// q/k/v fp32 (tf32-rounded by QKV epilogue); K/V streamed via cp.async.
#define KS_STR 68
#define VS_STR 72
#define ATT_K_FLOATS (64 * KS_STR)
#define ATT_V_FLOATS (64 * VS_STR)
#define ATT_SMEM ((2 * ATT_K_FLOATS + 2 * ATT_V_FLOATS) * 4)

__global__ __launch_bounds__(128)
void attn_tc_kernel(const float* __restrict__ Q,
                    const float* __restrict__ K,
                    const float* __restrict__ V,
                    __half* __restrict__ Y) {
    extern __shared__ __align__(16) float dsmf[];
    float (*Ks)[64][KS_STR] = (float(*)[64][KS_STR])dsmf;
    float (*Vs)[64][VS_STR] = (float(*)[64][VS_STR])(dsmf + 2 * ATT_K_FLOATS);

    int qt = blockIdx.x, h = blockIdx.y, b = blockIdx.z;
    int tid = threadIdx.x;
    int lane = tid & 31, w = tid >> 5;
    int g = lane >> 2, t = lane & 3;
    int qbase = qt * 64;
    const int hoff = h * DH;

    int lrow = tid >> 1;
    int ld0  = (tid & 1) * 32;

    uint32_t ksm[2], vsm[2];
    #pragma unroll
    for (int s = 0; s < 2; s++) {
        ksm[s] = (uint32_t)__cvta_generic_to_shared(&Ks[s][lrow][ld0]);
        vsm[s] = (uint32_t)__cvta_generic_to_shared(&Vs[s][lrow][ld0]);
    }

    {
        const float* kp = K + (size_t)(b * TT + lrow) * CC + hoff + ld0;
        const float* vp = V + (size_t)(b * TT + lrow) * CC + hoff + ld0;
        #pragma unroll
        for (int i = 0; i < 8; i++) {
            CP_ASYNC16(ksm[0] + i * 16, kp + i * 4);
            CP_ASYNC16(vsm[0] + i * 16, vp + i * 4);
        }
        CP_COMMIT();
    }

    {
        const float* qp = Q + (size_t)(b * TT + qbase + lrow) * CC + hoff + ld0;
        #pragma unroll
        for (int i = 0; i < 8; i++) {
            float4 v4 = ((const float4*)qp)[i];
            Vs[1][lrow][ld0 + 4*i + 0] = v4.x * 0.125f;
            Vs[1][lrow][ld0 + 4*i + 1] = v4.y * 0.125f;
            Vs[1][lrow][ld0 + 4*i + 2] = v4.z * 0.125f;
            Vs[1][lrow][ld0 + 4*i + 3] = v4.w * 0.125f;
        }
    }
    __syncthreads();
    uint32_t qf[8][4];
    {
        int rAq = 16 * w + g;
        #pragma unroll
        for (int kc = 0; kc < 8; kc++) {
            qf[kc][0] = __float_as_uint(Vs[1][rAq    ][kc*8 + t    ]);
            qf[kc][1] = __float_as_uint(Vs[1][rAq + 8][kc*8 + t    ]);
            qf[kc][2] = __float_as_uint(Vs[1][rAq    ][kc*8 + t + 4]);
            qf[kc][3] = __float_as_uint(Vs[1][rAq + 8][kc*8 + t + 4]);
        }
    }

    float o[8][4];
    #pragma unroll
    for (int nt = 0; nt < 8; nt++)
        #pragma unroll
        for (int j = 0; j < 4; j++) o[nt][j] = 0.f;
    float mA = -1e30f, mB = -1e30f, lA = 0.f, lB = 0.f;

    int rA = 16 * w + g;
    int rB = rA + 8;

    for (int kt = 0; kt <= qt; kt++) {
        int c = kt & 1;
        asm volatile("cp.async.wait_group 0;" ::: "memory");
        __syncthreads();

        if (kt < qt) {
            const float* kp = K + (size_t)(b * TT + (kt+1) * 64 + lrow) * CC + hoff + ld0;
            const float* vp = V + (size_t)(b * TT + (kt+1) * 64 + lrow) * CC + hoff + ld0;
            #pragma unroll
            for (int i = 0; i < 8; i++) {
                CP_ASYNC16(ksm[1 - c] + i * 16, kp + i * 4);
                CP_ASYNC16(vsm[1 - c] + i * 16, vp + i * 4);
            }
            CP_COMMIT();
        }

        float s[8][4];
        #pragma unroll
        for (int nt = 0; nt < 8; nt++)
            #pragma unroll
            for (int j = 0; j < 4; j++) s[nt][j] = 0.f;
        #pragma unroll
        for (int kc = 0; kc < 8; kc++) {
            #pragma unroll
            for (int nt = 0; nt < 8; nt++) {
                uint32_t b0 = __float_as_uint(Ks[c][nt*8 + g][kc*8 + t    ]);
                uint32_t b1 = __float_as_uint(Ks[c][nt*8 + g][kc*8 + t + 4]);
                mma_tf32(s[nt][0], s[nt][1], s[nt][2], s[nt][3],
                         qf[kc][0], qf[kc][1], qf[kc][2], qf[kc][3], b0, b1);
            }
        }

        if (kt == qt) {
            #pragma unroll
            for (int nt = 0; nt < 8; nt++) {
                int c0 = nt * 8 + 2 * t;
                if (c0     > rA) s[nt][0] = -1e30f;
                if (c0 + 1 > rA) s[nt][1] = -1e30f;
                if (c0     > rB) s[nt][2] = -1e30f;
                if (c0 + 1 > rB) s[nt][3] = -1e30f;
            }
        }

        float mxA = -1e30f, mxB = -1e30f;
        #pragma unroll
        for (int nt = 0; nt < 8; nt++) {
            mxA = fmaxf(mxA, fmaxf(s[nt][0], s[nt][1]));
            mxB = fmaxf(mxB, fmaxf(s[nt][2], s[nt][3]));
        }
        mxA = fmaxf(mxA, __shfl_xor_sync(0xffffffffu, mxA, 1));
        mxA = fmaxf(mxA, __shfl_xor_sync(0xffffffffu, mxA, 2));
        mxB = fmaxf(mxB, __shfl_xor_sync(0xffffffffu, mxB, 1));
        mxB = fmaxf(mxB, __shfl_xor_sync(0xffffffffu, mxB, 2));
        float mnA = fmaxf(mA, mxA);
        float mnB = fmaxf(mB, mxB);
        float corrA = __expf(mA - mnA);
        float corrB = __expf(mB - mnB);

        float sumA = 0.f, sumB = 0.f;
        #pragma unroll
        for (int nt = 0; nt < 8; nt++) {
            s[nt][0] = __expf(s[nt][0] - mnA); sumA += s[nt][0];
            s[nt][1] = __expf(s[nt][1] - mnA); sumA += s[nt][1];
            s[nt][2] = __expf(s[nt][2] - mnB); sumB += s[nt][2];
            s[nt][3] = __expf(s[nt][3] - mnB); sumB += s[nt][3];
        }
        sumA += __shfl_xor_sync(0xffffffffu, sumA, 1);
        sumA += __shfl_xor_sync(0xffffffffu, sumA, 2);
        sumB += __shfl_xor_sync(0xffffffffu, sumB, 1);
        sumB += __shfl_xor_sync(0xffffffffu, sumB, 2);
        lA = lA * corrA + sumA;
        lB = lB * corrB + sumB;
        mA = mnA; mB = mnB;

        #pragma unroll
        for (int nt = 0; nt < 8; nt++) {
            o[nt][0] *= corrA; o[nt][1] *= corrA;
            o[nt][2] *= corrB; o[nt][3] *= corrB;
        }

        __syncthreads();
        #pragma unroll
        for (int nt = 0; nt < 8; nt++) {
            int c0 = nt * 8 + 2 * t;
            Ks[c][rA][c0    ] = cvt_tf32(s[nt][0]);
            Ks[c][rA][c0 + 1] = cvt_tf32(s[nt][1]);
            Ks[c][rB][c0    ] = cvt_tf32(s[nt][2]);
            Ks[c][rB][c0 + 1] = cvt_tf32(s[nt][3]);
        }
        __syncwarp();

        #pragma unroll
        for (int kc = 0; kc < 8; kc++) {
            uint32_t a0 = __float_as_uint(Ks[c][rA][kc*8 + t    ]);
            uint32_t a1 = __float_as_uint(Ks[c][rB][kc*8 + t    ]);
            uint32_t a2 = __float_as_uint(Ks[c][rA][kc*8 + t + 4]);
            uint32_t a3 = __float_as_uint(Ks[c][rB][kc*8 + t + 4]);
            #pragma unroll
            for (int nt = 0; nt < 8; nt++) {
                uint32_t b0 = __float_as_uint(Vs[c][kc*8 + t    ][nt*8 + g]);
                uint32_t b1 = __float_as_uint(Vs[c][kc*8 + t + 4][nt*8 + g]);
                mma_tf32(o[nt][0], o[nt][1], o[nt][2], o[nt][3],
                         a0, a1, a2, a3, b0, b1);
            }
        }
    }

    // epilogue: y in fp16 (feeds proj GEMM)
    float invA = 1.0f / lA, invB = 1.0f / lB;
    int rowA = qbase + rA;
    __half* yA = Y + (size_t)(b * TT + rowA) * CC + hoff;
    __half* yB = Y + (size_t)(b * TT + rowA + 8) * CC + hoff;
    #pragma unroll
    for (int nt = 0; nt < 8; nt++) {
        int c0 = nt * 8 + 2 * t;
        *(__half2*)(yA + c0) = __floats2half2_rn(o[nt][0] * invA, o[nt][1] * invA);
        *(__half2*)(yB + c0) = __floats2half2_rn(o[nt][2] * invB, o[nt][3] * invB);
    }
}

// ---------------- launcher ----------------
extern "C" void kernel_launch(void* const* d_in, const int* in_sizes, int n_in,
                              void* d_out, int out_size) {
    const float* x     = (const float*)d_in[0];
    const float* ln1_g = (const float*)d_in[1];
    const float* ln1_b = (const float*)d_in[2];
    const float* Wq    = (const float*)d_in[3];
    const float* bq    = (const float*)d_in[4];
    const float* Wk    = (const float*)d_in[5];
    const float* bk    = (const float*)d_in[6];
    const float* Wv    = (const float*)d_in[7];
    const float* bv    = (const float*)d_in[8];
    const float* Wo    = (const float*)d_in[9];
    const float* bo    = (const float*)d_in[10];
    const float* ln2_g = (const float*)d_in[11];
    const float* ln2_b = (const float*)d_in[12];
    const float* W1    = (const float*)d_in[13];
    const float* b1    = (const float*)d_in[14];
    const float* W2    = (const float*)d_in[15];
    const float* b2    = (const float*)d_in[16];
    float* out = (float*)d_out;

    __half *h16, *y16, *m16, *wqkvt, *wot, *w1t, *w2t;
    float *q, *k, *v, *x1, *bqkv;
    cudaGetSymbolAddress((void**)&h16,   g_h16);
    cudaGetSymbolAddress((void**)&q,     g_q);
    cudaGetSymbolAddress((void**)&k,     g_k);
    cudaGetSymbolAddress((void**)&v,     g_v);
    cudaGetSymbolAddress((void**)&y16,   g_y16);
    cudaGetSymbolAddress((void**)&x1,    g_x1);
    cudaGetSymbolAddress((void**)&m16,   g_m16);
    cudaGetSymbolAddress((void**)&wqkvt, g_wqkvt);
    cudaGetSymbolAddress((void**)&bqkv,  g_bqkv);
    cudaGetSymbolAddress((void**)&wot,   g_wot);
    cudaGetSymbolAddress((void**)&w1t,   g_w1t);
    cudaGetSymbolAddress((void**)&w2t,   g_w2t);

    cudaFuncSetAttribute(gemm_fp16<0>, cudaFuncAttributeMaxDynamicSharedMemorySize, GEMM_SMEM);
    cudaFuncSetAttribute(gemm_fp16<1>, cudaFuncAttributeMaxDynamicSharedMemorySize, GEMM_SMEM);
    cudaFuncSetAttribute(gemm_fp16<2>, cudaFuncAttributeMaxDynamicSharedMemorySize, GEMM_SMEM);
    cudaFuncSetAttribute(attn_tc_kernel, cudaFuncAttributeMaxDynamicSharedMemorySize, ATT_SMEM);

    // 0) weight prep: transpose + fp16
    prep_t<<<dim3(CC/32, CC/32), 256>>>(Wq, wqkvt,                      CC, CC, bq, bqkv);
    prep_t<<<dim3(CC/32, CC/32), 256>>>(Wk, wqkvt + (size_t)CC * CC,    CC, CC, bk, bqkv + CC);
    prep_t<<<dim3(CC/32, CC/32), 256>>>(Wv, wqkvt + (size_t)2 * CC * CC,CC, CC, bv, bqkv + 2 * CC);
    prep_t<<<dim3(CC/32, CC/32), 256>>>(Wo, wot, CC, CC, nullptr, nullptr);
    prep_t<<<dim3(FF/32, CC/32), 256>>>(W1, w1t, CC, FF, nullptr, nullptr);
    prep_t<<<dim3(CC/32, FF/32), 256>>>(W2, w2t, FF, CC, nullptr, nullptr);

    dim3 gQKV(3*CC / 128, ROWS / 128);
    dim3 gC(CC / 128, ROWS / 128);
    dim3 gF(FF / 128, ROWS / 128);

    // 1) LN1 -> h (fp16)
    ln_kernel<<<ROWS, 256>>>(x, ln1_g, ln1_b, h16);
    // 2) fused QKV (fp16 mma) -> q,k,v fp32 (tf32-rounded)
    gemm_fp16<0><<<gQKV, 256, GEMM_SMEM>>>(h16, wqkvt, bqkv, nullptr, q, k, v,
                                           ROWS, 3*CC, CC, CC);
    // 3) attention -> y (fp16)
    attn_tc_kernel<<<dim3(TT / 64, NH, BB), 128, ATT_SMEM>>>(q, k, v, y16);
    // 4) proj + residual -> x1 (fp32)
    gemm_fp16<1><<<gC, 256, GEMM_SMEM>>>(y16, wot, bo, x, x1, nullptr, nullptr,
                                         ROWS, CC, CC, CC);
    // 5) LN2 -> h (fp16)
    ln_kernel<<<ROWS, 256>>>(x1, ln2_g, ln2_b, h16);
    // 6) MLP
    gemm_fp16<2><<<gF, 256, GEMM_SMEM>>>(h16, w1t, b1, nullptr, m16, nullptr, nullptr,
                                         ROWS, FF, CC, FF);
    gemm_fp16<1><<<gC, 256, GEMM_SMEM>>>(m16, w2t, b2, x1, out, nullptr, nullptr,
                                         ROWS, CC, FF, CC);
}